// round 1
// baseline (speedup 1.0000x reference)
#include <cuda_runtime.h>
#include <cstdint>
#include <cstddef>

// ---------------- problem constants ----------------
#define BB   16
#define DIN  1024
#define TT   1024
#define KK   8192
#define DCB  256
#define NTOK (BB * TT)          // 16384

// ---------------- output layout (tuple flattened, f32) ----------------
// (z_q_out, indices, commit_loss, codebook_loss, dist, perplexity, active_num)
static constexpr size_t OFF_ZQ     = 0;
static constexpr size_t SZ_ZQ      = (size_t)BB * DIN * TT;        // 16777216
static constexpr size_t OFF_IDX    = OFF_ZQ + SZ_ZQ;               // 16777216
static constexpr size_t OFF_COMMIT = OFF_IDX + NTOK;               // 16793600
static constexpr size_t OFF_CBL    = OFF_COMMIT + BB;              // 16793616
static constexpr size_t OFF_DIST   = OFF_CBL + BB;                 // 16793632
static constexpr size_t SZ_DIST    = (size_t)NTOK * KK;            // 134217728
static constexpr size_t OFF_PERP   = OFF_DIST + SZ_DIST;           // 151011360
static constexpr size_t OFF_ACT    = OFF_PERP + 1;                 // 151011361

// ---------------- scratch (device globals: allocation-free) ----------------
__device__ float g_w_inT [DIN * DCB];      // [i][o]  (k-major for GEMM A)
__device__ float g_w_outT[DCB * DIN];      // [c][o]
__device__ float g_cbT   [DCB * KK];       // [c][k]  raw codebook, transposed
__device__ float g_cbnT  [DCB * KK];       // [c][k]  l2-normalized codebook, transposed
__device__ float g_colsq [KK];             // sum(cb_n^2) per code
__device__ float g_ze    [BB * DCB * TT];  // z_e  [b][c][t]
__device__ float g_inv   [NTOK];           // 1/max(||enc||,eps) per token
__device__ float g_rowsq [NTOK];           // sum(enc_n^2) per token
__device__ unsigned long long g_packed[NTOK]; // argmin (key<<32 | k)
__device__ int   g_idx   [NTOK];
__device__ int   g_counts[KK];
__device__ float g_proj  [KK * DIN];       // proj_cb[k][o] = cb[k]·w_out[o]
__device__ float g_losspart[BB * 4];

// ---------------- init ----------------
__global__ void k_init()
{
    int i = blockIdx.x * blockDim.x + threadIdx.x;   // 64*256 = 16384
    if (i < KK)   g_counts[i] = 0;
    if (i < NTOK) g_packed[i] = 0xFFFFFFFFFFFFFFFFULL;
}

// ---------------- row norms (weight-norm weights + codebook l2norm) ----------------
// which 0: w_in  (256 rows x 1024 cols)  -> g_w_inT  (scale = g/||v||)
// which 1: w_out (1024 rows x 256 cols)  -> g_w_outT (scale = g/||v||)
// which 2: codebook (8192 x 256)         -> g_cbT, g_cbnT, g_colsq (clamped)
__global__ void k_rownorm(int which, const float* __restrict__ src,
                          const float* __restrict__ gvec)
{
    int r   = blockIdx.x;
    int tid = threadIdx.x;
    int cols = (which == 0) ? DIN : DCB;
    const float* row = src + (size_t)r * cols;
    float s = 0.f;
    for (int c = tid; c < cols; c += 256) { float v = row[c]; s += v * v; }
    __shared__ float sm[256];
    sm[tid] = s; __syncthreads();
    #pragma unroll
    for (int off = 128; off; off >>= 1) {
        if (tid < off) sm[tid] += sm[tid + off];
        __syncthreads();
    }
    float sumsq = sm[0];
    if (which == 2) {
        float inv = 1.f / fmaxf(sqrtf(sumsq), 1e-12f);
        if (tid == 0) g_colsq[r] = sumsq * inv * inv;
        for (int c = tid; c < cols; c += 256) {
            float v = row[c];
            g_cbT [(size_t)c * KK + r] = v;
            g_cbnT[(size_t)c * KK + r] = v * inv;
        }
    } else if (which == 0) {
        float scale = gvec[r] / sqrtf(sumsq);
        for (int c = tid; c < cols; c += 256)
            g_w_inT[(size_t)c * DCB + r] = row[c] * scale;
    } else {
        float scale = gvec[r] / sqrtf(sumsq);
        for (int c = tid; c < cols; c += 256)
            g_w_outT[(size_t)c * DIN + r] = row[c] * scale;
    }
}

// ---------------- generic 128x128x8 fp32 GEMM, both operands k-major ----------------
// C[m][n] = sum_k A[k][m] * B[k][n]   (+ per-m bias / dist epilogue)
// MODE 0: z_e   = w_inT x z[b] + in_b      (M=256,  N=1024, K=1024, batched)
// MODE 1: dist  epilogue + argmin          (M=1024, N=8192, K=256,  batched)
// MODE 2: proj  = cbT x w_outT             (M=8192, N=1024, K=256)
template<int MODE>
__global__ __launch_bounds__(256, 2)
void k_gemm(const float* __restrict__ Bext, const float* __restrict__ bias,
            float* __restrict__ Cext)
{
    constexpr int LDA  = (MODE == 0) ? DCB : (MODE == 1) ? TT : KK;
    constexpr int LDB  = (MODE == 0) ? TT  : (MODE == 1) ? KK : DIN;
    constexpr int LDC  = (MODE == 0) ? TT  : (MODE == 1) ? KK : DIN;
    constexpr int KDIM = (MODE == 0) ? DIN : DCB;

    const float* A = (MODE == 0) ? g_w_inT
                   : (MODE == 1) ? (g_ze + (size_t)blockIdx.z * DCB * TT)
                                 : g_cbT;
    const float* Bm = (MODE == 0) ? (Bext + (size_t)blockIdx.z * DIN * TT)
                    : (MODE == 1) ? g_cbnT
                                  : g_w_outT;
    float* C = (MODE == 0) ? (g_ze + (size_t)blockIdx.z * DCB * TT)
             : (MODE == 1) ? (Cext + (size_t)blockIdx.z * (size_t)TT * KK)
                           : g_proj;

    __shared__ float As[8][128];
    __shared__ float Bs[8][128];

    int tid = threadIdx.x;
    int m0  = blockIdx.y * 128;
    int n0  = blockIdx.x * 128;

    int kr = tid >> 5;               // 0..7
    int c4 = (tid & 31) << 2;        // 0..124
    const float* Ag = A  + (size_t)kr * LDA + m0 + c4;
    const float* Bg = Bm + (size_t)kr * LDB + n0 + c4;

    float4 ar = *(const float4*)Ag;
    float4 br = *(const float4*)Bg;

    float acc[8][8];
    #pragma unroll
    for (int i = 0; i < 8; i++)
        #pragma unroll
        for (int j = 0; j < 8; j++) acc[i][j] = 0.f;

    int tr = (tid >> 4) << 2;        // row frags: tr..tr+3, tr+64..tr+67
    int tc = (tid & 15) << 2;        // col frags: tc..tc+3, tc+64..tc+67

    constexpr int KT = KDIM / 8;
    for (int kt = 0; kt < KT; kt++) {
        *(float4*)&As[kr][c4] = ar;
        *(float4*)&Bs[kr][c4] = br;
        __syncthreads();
        if (kt + 1 < KT) {
            Ag += (size_t)8 * LDA;  Bg += (size_t)8 * LDB;
            ar = *(const float4*)Ag;  br = *(const float4*)Bg;
        }
        #pragma unroll
        for (int c = 0; c < 8; c++) {
            float4 a0 = *(const float4*)&As[c][tr];
            float4 a1 = *(const float4*)&As[c][tr + 64];
            float4 b0 = *(const float4*)&Bs[c][tc];
            float4 b1 = *(const float4*)&Bs[c][tc + 64];
            float av[8] = {a0.x, a0.y, a0.z, a0.w, a1.x, a1.y, a1.z, a1.w};
            float bv[8] = {b0.x, b0.y, b0.z, b0.w, b1.x, b1.y, b1.z, b1.w};
            #pragma unroll
            for (int i = 0; i < 8; i++)
                #pragma unroll
                for (int j = 0; j < 8; j++)
                    acc[i][j] += av[i] * bv[j];
        }
        __syncthreads();
    }

    if (MODE != 1) {
        #pragma unroll
        for (int i = 0; i < 8; i++) {
            int m = m0 + tr + ((i < 4) ? i : 60 + i);
            float bb = (MODE == 0) ? bias[m] : 0.f;
            float* crow = C + (size_t)m * LDC + n0;
            float4 v0 = make_float4(acc[i][0] + bb, acc[i][1] + bb,
                                    acc[i][2] + bb, acc[i][3] + bb);
            float4 v1 = make_float4(acc[i][4] + bb, acc[i][5] + bb,
                                    acc[i][6] + bb, acc[i][7] + bb);
            *(float4*)(crow + tc)      = v0;
            *(float4*)(crow + tc + 64) = v1;
        }
    } else {
        float csq[8];
        #pragma unroll
        for (int j = 0; j < 4; j++) {
            csq[j]     = g_colsq[n0 + tc + j];
            csq[4 + j] = g_colsq[n0 + tc + 64 + j];
        }
        int rowbase = blockIdx.z * TT;
        #pragma unroll
        for (int i = 0; i < 8; i++) {
            int m  = m0 + tr + ((i < 4) ? i : 60 + i);
            int rg = rowbase + m;
            float rs  = g_rowsq[rg];
            float iv2 = 2.0f * g_inv[rg];
            float d[8];
            #pragma unroll
            for (int j = 0; j < 8; j++)
                d[j] = rs + csq[j] - iv2 * acc[i][j];
            float* crow = C + (size_t)m * LDC + n0;
            *(float4*)(crow + tc)      = make_float4(d[0], d[1], d[2], d[3]);
            *(float4*)(crow + tc + 64) = make_float4(d[4], d[5], d[6], d[7]);
            // thread-local argmin (ascending k order -> first-hit ties)
            unsigned bestkey = 0xFFFFFFFFu;
            unsigned bestk   = 0;
            #pragma unroll
            for (int j = 0; j < 8; j++) {
                unsigned fu  = __float_as_uint(d[j]);
                unsigned key = (fu & 0x80000000u) ? ~fu : (fu | 0x80000000u);
                unsigned col = (unsigned)(n0 + tc + ((j < 4) ? j : 60 + j));
                if (key < bestkey) { bestkey = key; bestk = col; }
            }
            unsigned long long p = ((unsigned long long)bestkey << 32) | bestk;
            #pragma unroll
            for (int off = 8; off; off >>= 1) {
                unsigned long long q = __shfl_xor_sync(0xFFFFFFFFu, p, off);
                if (q < p) p = q;
            }
            if ((tid & 15) == 0) atomicMin(&g_packed[rg], p);
        }
    }
}

// ---------------- per-token norms of z_e ----------------
__global__ void k_toknorm()
{
    int n = blockIdx.x * 256 + threadIdx.x;   // 64 blocks
    int b = n >> 10, t = n & 1023;
    const float* base = g_ze + (size_t)b * DCB * TT + t;
    float s = 0.f;
    #pragma unroll 4
    for (int c = 0; c < DCB; c++) {
        float v = base[(size_t)c * TT];
        s += v * v;
    }
    float inv = 1.f / fmaxf(sqrtf(s), 1e-12f);
    g_inv[n]   = inv;
    g_rowsq[n] = s * inv * inv;
}

// ---------------- finalize indices + counts ----------------
__global__ void k_indices(float* __restrict__ dout)
{
    int n = blockIdx.x * 256 + threadIdx.x;   // 64 blocks
    unsigned long long p = g_packed[n];
    int idx = (int)(p & 0xFFFFFFFFULL);
    g_idx[n] = idx;
    dout[OFF_IDX + n] = (float)idx;
    atomicAdd(&g_counts[idx], 1);
}

// ---------------- commit/codebook loss partials (deterministic) ----------------
__global__ void k_loss(const float* __restrict__ cb)
{
    int b   = blockIdx.y;
    int t   = blockIdx.x * 256 + threadIdx.x;   // grid.x = 4
    int n   = b * TT + t;
    int idx = g_idx[n];
    const float* ze = g_ze + (size_t)b * DCB * TT + t;
    const float* cr = cb + (size_t)idx * DCB;
    float s = 0.f;
    #pragma unroll 4
    for (int c = 0; c < DCB; c++) {
        float d = ze[(size_t)c * TT] - cr[c];
        s += d * d;
    }
    __shared__ float sm[256];
    sm[threadIdx.x] = s; __syncthreads();
    #pragma unroll
    for (int off = 128; off; off >>= 1) {
        if (threadIdx.x < off) sm[threadIdx.x] += sm[threadIdx.x + off];
        __syncthreads();
    }
    if (threadIdx.x == 0) g_losspart[b * 4 + blockIdx.x] = sm[0];
}

// ---------------- z_q_out gather: proj_cb[idx] + out_b ----------------
__global__ void k_gather(const float* __restrict__ outb, float* __restrict__ dout)
{
    int t  = blockIdx.x * 256 + threadIdx.x;   // grid.x = 4
    int o4 = blockIdx.y * 4;                   // grid.y = 256
    int b  = blockIdx.z;                       // grid.z = 16
    int idx = g_idx[b * TT + t];
    float4 v = *(const float4*)(g_proj + (size_t)idx * DIN + o4);
    size_t base = OFF_ZQ + (size_t)b * DIN * TT + (size_t)o4 * TT + t;
    dout[base]            = v.x + outb[o4];
    dout[base + TT]       = v.y + outb[o4 + 1];
    dout[base + 2 * TT]   = v.z + outb[o4 + 2];
    dout[base + 3 * TT]   = v.w + outb[o4 + 3];
}

// ---------------- scalars: losses, perplexity, active_num ----------------
__global__ void k_final(const float* __restrict__ cs, float* __restrict__ dout)
{
    int tid = threadIdx.x;   // single block of 256
    if (tid < BB) {
        float s = g_losspart[tid * 4] + g_losspart[tid * 4 + 1]
                + g_losspart[tid * 4 + 2] + g_losspart[tid * 4 + 3];
        float mean = s / (float)(DCB * TT);
        dout[OFF_COMMIT + tid] = mean * 0.15f;
        dout[OFF_CBL + tid]    = mean;           // CODEBOOK_LOSS_W = 1.0
    }
    float ent = 0.f;
    int   act = 0;
    for (int k = tid; k < KK; k += 256) {
        float cnt = (float)g_counts[k];
        float p   = cnt / (float)NTOK;
        ent += p * logf(p + 1e-10f);
        float ncs = cs[k] * 0.99f + cnt * 0.01f;
        if (ncs > 2.0f) act++;
    }
    __shared__ float se[256];
    __shared__ int   sa[256];
    se[tid] = ent; sa[tid] = act; __syncthreads();
    #pragma unroll
    for (int off = 128; off; off >>= 1) {
        if (tid < off) { se[tid] += se[tid + off]; sa[tid] += sa[tid + off]; }
        __syncthreads();
    }
    if (tid == 0) {
        dout[OFF_PERP] = expf(-se[0]);
        dout[OFF_ACT]  = (float)sa[0];
    }
}

// ---------------- launch ----------------
extern "C" void kernel_launch(void* const* d_in, const int* in_sizes, int n_in,
                              void* d_out, int out_size)
{
    const float* z     = (const float*)d_in[0];
    const float* in_g  = (const float*)d_in[1];
    const float* in_v  = (const float*)d_in[2];
    const float* in_b  = (const float*)d_in[3];
    const float* out_g = (const float*)d_in[4];
    const float* out_v = (const float*)d_in[5];
    const float* out_b = (const float*)d_in[6];
    const float* cb    = (const float*)d_in[7];
    const float* cs    = (const float*)d_in[8];
    float* dout = (float*)d_out;

    k_init<<<64, 256>>>();

    k_rownorm<<<DCB, 256>>>(0, in_v, in_g);
    k_rownorm<<<DIN, 256>>>(1, out_v, out_g);
    k_rownorm<<<KK,  256>>>(2, cb,   nullptr);

    // z_e = w_in @ z + in_b   [b][256][1024]
    {
        dim3 grid(TT / 128, DCB / 128, BB);
        k_gemm<0><<<grid, 256>>>(z, in_b, nullptr);
    }

    k_toknorm<<<NTOK / 256, 256>>>();

    // dist + fused argmin -> d_out[OFF_DIST]
    {
        dim3 grid(KK / 128, TT / 128, BB);
        k_gemm<1><<<grid, 256>>>(nullptr, nullptr, dout + OFF_DIST);
    }

    k_indices<<<NTOK / 256, 256>>>(dout);

    {
        dim3 grid(4, BB);
        k_loss<<<grid, 256>>>(cb);
    }

    // proj_cb = cb @ w_out^T   [8192][1024]
    {
        dim3 grid(DIN / 128, KK / 128, 1);
        k_gemm<2><<<grid, 256>>>(nullptr, nullptr, nullptr);
    }

    {
        dim3 grid(4, 256, BB);
        k_gather<<<grid, 256>>>(out_b, dout);
    }

    k_final<<<1, 256>>>(cs, dout);
}

// round 3
// speedup vs baseline: 1.2963x; 1.2963x over previous
#include <cuda_runtime.h>
#include <cuda_bf16.h>
#include <cstdint>
#include <cstddef>

// ---------------- problem constants ----------------
#define BB   16
#define DIN  1024
#define TT   1024
#define KK   8192
#define DCB  256
#define NTOK (BB * TT)          // 16384

// ---------------- output layout (tuple flattened, f32) ----------------
static constexpr size_t OFF_ZQ     = 0;
static constexpr size_t SZ_ZQ      = (size_t)BB * DIN * TT;
static constexpr size_t OFF_IDX    = OFF_ZQ + SZ_ZQ;
static constexpr size_t OFF_COMMIT = OFF_IDX + NTOK;
static constexpr size_t OFF_CBL    = OFF_COMMIT + BB;
static constexpr size_t OFF_DIST   = OFF_CBL + BB;
static constexpr size_t SZ_DIST    = (size_t)NTOK * KK;
static constexpr size_t OFF_PERP   = OFF_DIST + SZ_DIST;
static constexpr size_t OFF_ACT    = OFF_PERP + 1;

// ---------------- scratch (device globals) ----------------
__device__ float g_w_inT [DIN * DCB];
__device__ float g_w_outT[DCB * DIN];
__device__ float g_cbT   [DCB * KK];
__device__ float g_cbnT  [DCB * KK];
__device__ float g_colsq [KK];
__device__ float g_ze    [BB * DCB * TT];
__device__ float g_inv   [NTOK];
__device__ float g_rowsq [NTOK];
__device__ int   g_idx   [NTOK];
__device__ int   g_counts[KK];
__device__ float g_proj  [KK * DIN];
__device__ float g_losspart[BB * 4];

// split-bf16 operands (16B aligned for cp.async)
__device__ __align__(16) __nv_bfloat16 g_a_hi[(size_t)NTOK * DCB];
__device__ __align__(16) __nv_bfloat16 g_a_lo[(size_t)NTOK * DCB];
__device__ __align__(16) __nv_bfloat16 g_b_hi[(size_t)KK * DCB];
__device__ __align__(16) __nv_bfloat16 g_b_lo[(size_t)KK * DCB];
// per-(token, 64-code tile) packed min (key<<32 | code), tile = k/64
__device__ unsigned long long g_tilemin[(size_t)NTOK * 128];

// ---------------- helpers ----------------
__device__ __forceinline__ uint32_t smem_u32(const void* p) {
    uint32_t a;
    asm("{ .reg .u64 t; cvta.to.shared.u64 t, %1; cvt.u32.u64 %0, t; }" : "=r"(a) : "l"(p));
    return a;
}
__device__ __forceinline__ void ldsm_x4(uint32_t* r, uint32_t a) {
    asm volatile("ldmatrix.sync.aligned.m8n8.x4.shared.b16 {%0,%1,%2,%3}, [%4];"
        : "=r"(r[0]), "=r"(r[1]), "=r"(r[2]), "=r"(r[3]) : "r"(a));
}
__device__ __forceinline__ void mma_bf16(float* d, const uint32_t* a, const uint32_t* b) {
    asm volatile("mma.sync.aligned.m16n8k16.row.col.f32.bf16.bf16.f32 "
        "{%0,%1,%2,%3}, {%4,%5,%6,%7}, {%8,%9}, {%0,%1,%2,%3};"
        : "+f"(d[0]), "+f"(d[1]), "+f"(d[2]), "+f"(d[3])
        : "r"(a[0]), "r"(a[1]), "r"(a[2]), "r"(a[3]), "r"(b[0]), "r"(b[1]));
}
#define CP_ASYNC16(dst, src) \
    asm volatile("cp.async.cg.shared.global [%0], [%1], 16;" :: "r"(dst), "l"(src) : "memory")
#define CP_COMMIT() asm volatile("cp.async.commit_group;" ::: "memory")
#define CP_WAIT1()  asm volatile("cp.async.wait_group 1;" ::: "memory")
#define CP_WAIT0()  asm volatile("cp.async.wait_group 0;" ::: "memory")

__device__ __forceinline__ unsigned fkey(float f) {
    unsigned u = __float_as_uint(f);
    return (u & 0x80000000u) ? ~u : (u | 0x80000000u);
}
__device__ __forceinline__ float funkey(unsigned k) {
    unsigned u = (k & 0x80000000u) ? (k ^ 0x80000000u) : ~k;
    return __uint_as_float(u);
}

// ---------------- init ----------------
__global__ void k_init()
{
    int i = blockIdx.x * blockDim.x + threadIdx.x;
    if (i < KK) g_counts[i] = 0;
}

// ---------------- row norms + codebook split ----------------
__global__ void k_rownorm(int which, const float* __restrict__ src,
                          const float* __restrict__ gvec)
{
    int r   = blockIdx.x;
    int tid = threadIdx.x;
    int cols = (which == 0) ? DIN : DCB;
    const float* row = src + (size_t)r * cols;
    float s = 0.f;
    for (int c = tid; c < cols; c += 256) { float v = row[c]; s += v * v; }
    __shared__ float sm[256];
    sm[tid] = s; __syncthreads();
    #pragma unroll
    for (int off = 128; off; off >>= 1) {
        if (tid < off) sm[tid] += sm[tid + off];
        __syncthreads();
    }
    float sumsq = sm[0];
    if (which == 2) {
        float inv = 1.f / fmaxf(sqrtf(sumsq), 1e-12f);
        if (tid == 0) g_colsq[r] = sumsq * inv * inv;
        int c = tid;                       // cols == 256 == blockDim
        float v  = row[c];
        float vn = v * inv;
        g_cbT [(size_t)c * KK + r] = v;
        g_cbnT[(size_t)c * KK + r] = vn;
        __nv_bfloat16 hi = __float2bfloat16_rn(vn);
        float lo = vn - __bfloat162float(hi);
        g_b_hi[(size_t)r * DCB + c] = hi;
        g_b_lo[(size_t)r * DCB + c] = __float2bfloat16_rn(lo);
    } else if (which == 0) {
        float scale = gvec[r] / sqrtf(sumsq);
        for (int c = tid; c < cols; c += 256)
            g_w_inT[(size_t)c * DCB + r] = row[c] * scale;
    } else {
        float scale = gvec[r] / sqrtf(sumsq);
        for (int c = tid; c < cols; c += 256)
            g_w_outT[(size_t)c * DIN + r] = row[c] * scale;
    }
}

// ---------------- fp32 SIMT GEMM (z_e and proj) ----------------
template<int MODE>
__global__ __launch_bounds__(256, 2)
void k_gemm(const float* __restrict__ Bext, const float* __restrict__ bias)
{
    constexpr int LDA  = (MODE == 0) ? DCB : KK;
    constexpr int LDB  = (MODE == 0) ? TT  : DIN;
    constexpr int LDC  = (MODE == 0) ? TT  : DIN;
    constexpr int KDIM = (MODE == 0) ? DIN : DCB;

    const float* A  = (MODE == 0) ? g_w_inT : g_cbT;
    const float* Bm = (MODE == 0) ? (Bext + (size_t)blockIdx.z * DIN * TT) : g_w_outT;
    float* C        = (MODE == 0) ? (g_ze + (size_t)blockIdx.z * DCB * TT) : g_proj;

    __shared__ float As[8][128];
    __shared__ float Bs[8][128];

    int tid = threadIdx.x;
    int m0  = blockIdx.y * 128;
    int n0  = blockIdx.x * 128;

    int kr = tid >> 5;
    int c4 = (tid & 31) << 2;
    const float* Ag = A  + (size_t)kr * LDA + m0 + c4;
    const float* Bg = Bm + (size_t)kr * LDB + n0 + c4;

    float4 ar = *(const float4*)Ag;
    float4 br = *(const float4*)Bg;

    float acc[8][8];
    #pragma unroll
    for (int i = 0; i < 8; i++)
        #pragma unroll
        for (int j = 0; j < 8; j++) acc[i][j] = 0.f;

    int tr = (tid >> 4) << 2;
    int tc = (tid & 15) << 2;

    constexpr int KT = KDIM / 8;
    for (int kt = 0; kt < KT; kt++) {
        *(float4*)&As[kr][c4] = ar;
        *(float4*)&Bs[kr][c4] = br;
        __syncthreads();
        if (kt + 1 < KT) {
            Ag += (size_t)8 * LDA;  Bg += (size_t)8 * LDB;
            ar = *(const float4*)Ag;  br = *(const float4*)Bg;
        }
        #pragma unroll
        for (int c = 0; c < 8; c++) {
            float4 a0 = *(const float4*)&As[c][tr];
            float4 a1 = *(const float4*)&As[c][tr + 64];
            float4 b0 = *(const float4*)&Bs[c][tc];
            float4 b1 = *(const float4*)&Bs[c][tc + 64];
            float av[8] = {a0.x, a0.y, a0.z, a0.w, a1.x, a1.y, a1.z, a1.w};
            float bv[8] = {b0.x, b0.y, b0.z, b0.w, b1.x, b1.y, b1.z, b1.w};
            #pragma unroll
            for (int i = 0; i < 8; i++)
                #pragma unroll
                for (int j = 0; j < 8; j++)
                    acc[i][j] += av[i] * bv[j];
        }
        __syncthreads();
    }

    #pragma unroll
    for (int i = 0; i < 8; i++) {
        int m = m0 + tr + ((i < 4) ? i : 60 + i);
        float bb = (MODE == 0) ? bias[m] : 0.f;
        float* crow = C + (size_t)m * LDC + n0;
        *(float4*)(crow + tc)      = make_float4(acc[i][0] + bb, acc[i][1] + bb,
                                                 acc[i][2] + bb, acc[i][3] + bb);
        *(float4*)(crow + tc + 64) = make_float4(acc[i][4] + bb, acc[i][5] + bb,
                                                 acc[i][6] + bb, acc[i][7] + bb);
    }
}

// ---------------- per-token norms of z_e + bf16 split ----------------
__global__ void k_toknorm()
{
    int n = blockIdx.x * 256 + threadIdx.x;
    int b = n >> 10, t = n & 1023;
    const float* base = g_ze + (size_t)b * DCB * TT + t;
    float s = 0.f;
    #pragma unroll 4
    for (int c = 0; c < DCB; c++) {
        float v = base[(size_t)c * TT];
        s += v * v;
    }
    float inv = 1.f / fmaxf(sqrtf(s), 1e-12f);
    g_inv[n]   = inv;
    g_rowsq[n] = s * inv * inv;
    __nv_bfloat16* ah = g_a_hi + (size_t)n * DCB;
    __nv_bfloat16* al = g_a_lo + (size_t)n * DCB;
    #pragma unroll 4
    for (int c = 0; c < DCB; c++) {
        float v = base[(size_t)c * TT] * inv;
        __nv_bfloat16 hi = __float2bfloat16_rn(v);
        float lo = v - __bfloat162float(hi);
        ah[c] = hi;
        al[c] = __float2bfloat16_rn(lo);
    }
}

// ---------------- HMMA dist kernel ----------------
// grid (64, 128): x -> 128-code tile, y -> 128-token tile. 256 threads.
// K=256 streamed in 32-ch chunks, double-buffered cp.async.
// SMEM rows padded to 80B for conflict-free ldmatrix.
static constexpr int ROWB      = 80;                 // 64B data + 16B pad
static constexpr int MAT_BYTES = 128 * ROWB;         // 10240
static constexpr int STAGE     = 4 * MAT_BYTES;      // Ahi, Alo, Bhi, Blo
static constexpr int COLSQ_OFF = 2 * STAGE;          // 81920
static constexpr int SMEM_DIST = COLSQ_OFF + 128 * 4;

__device__ __forceinline__ void dist_load_chunk(uint32_t sbase, int stage, int kc,
                                                int m0, int n0, int tid)
{
    uint32_t st = sbase + stage * STAGE;
    #pragma unroll
    for (int i = 0; i < 8; i++) {
        int lin = tid + i * 256;            // 0..2047
        int mat = lin >> 9;                 // 0..3
        int r   = (lin >> 2) & 127;
        int c   = lin & 3;
        uint32_t dst = st + mat * MAT_BYTES + (uint32_t)(r * ROWB + c * 16);
        const char* src;
        size_t off = ((size_t)((mat < 2 ? m0 : n0) + r) * DCB + kc * 32) * 2 + c * 16;
        if      (mat == 0) src = (const char*)g_a_hi + off;
        else if (mat == 1) src = (const char*)g_a_lo + off;
        else if (mat == 2) src = (const char*)g_b_hi + off;
        else               src = (const char*)g_b_lo + off;
        CP_ASYNC16(dst, src);
    }
    CP_COMMIT();
}

__global__ __launch_bounds__(256, 1)
void k_dist(float* __restrict__ dout)
{
    extern __shared__ __align__(16) char smem_raw[];
    uint32_t sbase = smem_u32(smem_raw);
    float* colsq_s = (float*)(smem_raw + COLSQ_OFF);

    int tid  = threadIdx.x;
    int wid  = tid >> 5;
    int lane = tid & 31;
    int wm   = wid >> 1;      // 0..3  (32-row slice)
    int wn   = wid & 1;       // 0..1  (64-col slice)
    int n0   = blockIdx.x * 128;
    int m0   = blockIdx.y * 128;

    if (tid < 128) colsq_s[tid] = g_colsq[n0 + tid];

    float acc[2][8][4];
    #pragma unroll
    for (int mt = 0; mt < 2; mt++)
        #pragma unroll
        for (int nt = 0; nt < 8; nt++)
            #pragma unroll
            for (int j = 0; j < 4; j++) acc[mt][nt][j] = 0.f;

    dist_load_chunk(sbase, 0, 0, m0, n0, tid);

    // fragment addresses (within a stage)
    int arow = wm * 32 + (lane & 15);
    int acolh = (lane >> 4) * 16;
    int brow = wn * 64 + ((lane >> 4) << 3) + (lane & 7);
    int bcolh = ((lane >> 3) & 1) * 16;

    for (int kc = 0; kc < 8; kc++) {
        int st = kc & 1;
        if (kc < 7) dist_load_chunk(sbase, st ^ 1, kc + 1, m0, n0, tid);
        if (kc < 7) { CP_WAIT1(); } else { CP_WAIT0(); }
        __syncthreads();

        uint32_t sa_hi = sbase + st * STAGE;
        uint32_t sa_lo = sa_hi + MAT_BYTES;
        uint32_t sb_hi = sa_hi + 2 * MAT_BYTES;
        uint32_t sb_lo = sa_hi + 3 * MAT_BYTES;

        #pragma unroll
        for (int s = 0; s < 2; s++) {
            int acol = s * 32 + acolh;
            uint32_t Ah[2][4], Al[2][4];
            ldsm_x4(Ah[0], sa_hi + (uint32_t)(arow * ROWB + acol));
            ldsm_x4(Ah[1], sa_hi + (uint32_t)((arow + 16) * ROWB + acol));
            ldsm_x4(Al[0], sa_lo + (uint32_t)(arow * ROWB + acol));
            ldsm_x4(Al[1], sa_lo + (uint32_t)((arow + 16) * ROWB + acol));
            int bcol = s * 32 + bcolh;
            #pragma unroll
            for (int np = 0; np < 4; np++) {
                uint32_t Bh[4], Bl[4];
                uint32_t ba = (uint32_t)((brow + np * 16) * ROWB + bcol);
                ldsm_x4(Bh, sb_hi + ba);
                ldsm_x4(Bl, sb_lo + ba);
                #pragma unroll
                for (int mt = 0; mt < 2; mt++) {
                    mma_bf16(acc[mt][2 * np],     Ah[mt], Bh);
                    mma_bf16(acc[mt][2 * np],     Ah[mt], Bl);
                    mma_bf16(acc[mt][2 * np],     Al[mt], Bh);
                    mma_bf16(acc[mt][2 * np + 1], Ah[mt], Bh + 2);
                    mma_bf16(acc[mt][2 * np + 1], Ah[mt], Bl + 2);
                    mma_bf16(acc[mt][2 * np + 1], Al[mt], Bh + 2);
                }
            }
        }
        __syncthreads();
    }

    // epilogue: dist = rowsq + colsq - 2*dot ; write + per-64-tile argmin
    int q  = lane >> 2;
    int qq = lane & 3;
    int tileg = blockIdx.x * 2 + wn;     // global 64-code tile
    #pragma unroll
    for (int mt = 0; mt < 2; mt++) {
        int RB = m0 + wm * 32 + mt * 16;
        #pragma unroll
        for (int h = 0; h < 2; h++) {
            int row = RB + h * 8 + q;
            float rsq = g_rowsq[row];
            float* dw = dout + OFF_DIST + (size_t)row * KK + n0;
            unsigned bkey = 0xFFFFFFFFu, bcode = 0;
            #pragma unroll
            for (int nt = 0; nt < 8; nt++) {
                int c0 = wn * 64 + nt * 8 + qq * 2;
                float d0 = rsq + colsq_s[c0]     - 2.f * acc[mt][nt][h * 2 + 0];
                float d1 = rsq + colsq_s[c0 + 1] - 2.f * acc[mt][nt][h * 2 + 1];
                *(float2*)(dw + c0) = make_float2(d0, d1);
                unsigned k0 = fkey(d0), k1 = fkey(d1);
                if (k0 < bkey) { bkey = k0; bcode = (unsigned)(n0 + c0); }
                if (k1 < bkey) { bkey = k1; bcode = (unsigned)(n0 + c0 + 1); }
            }
            unsigned long long p = ((unsigned long long)bkey << 32) | bcode;
            unsigned long long o;
            o = __shfl_xor_sync(0xFFFFFFFFu, p, 1); if (o < p) p = o;
            o = __shfl_xor_sync(0xFFFFFFFFu, p, 2); if (o < p) p = o;
            if (qq == 0) g_tilemin[(size_t)row * 128 + tileg] = p;
        }
    }
}

// ---------------- argmin refinement (exact fp32 on candidates) ----------------
__global__ void k_refine(float* __restrict__ dout)
{
    int warp = threadIdx.x >> 5;
    int lane = threadIdx.x & 31;
    int n = blockIdx.x * 8 + warp;

    const unsigned long long* tm = g_tilemin + (size_t)n * 128;
    unsigned long long best = tm[lane];
    {
        unsigned long long v;
        v = tm[lane + 32]; if (v < best) best = v;
        v = tm[lane + 64]; if (v < best) best = v;
        v = tm[lane + 96]; if (v < best) best = v;
        #pragma unroll
        for (int off = 16; off; off >>= 1) {
            unsigned long long o = __shfl_xor_sync(0xFFFFFFFFu, best, off);
            if (o < best) best = o;
        }
    }
    float dmin = funkey((unsigned)(best >> 32));
    float thresh = dmin + 1e-4f;

    int b = n >> 10, t = n & 1023;
    float inv = g_inv[n];
    float rsq = g_rowsq[n];
    float ev[8];
    #pragma unroll
    for (int j = 0; j < 8; j++)
        ev[j] = g_ze[(size_t)b * DCB * TT + (size_t)(lane * 8 + j) * TT + t] * inv;

    const float* distrow = dout + OFF_DIST + (size_t)n * KK;

    float bestd = 3.4e38f;
    int   bestk = KK;

    for (int ti = 0; ti < 128; ti++) {
        float tmin = funkey((unsigned)(tm[ti] >> 32));
        if (tmin > thresh) continue;
        int k0 = ti * 64;
        float d0 = distrow[k0 + lane];
        float d1 = distrow[k0 + 32 + lane];
        #pragma unroll
        for (int half = 0; half < 2; half++) {
            float dv = (half == 0) ? d0 : d1;
            unsigned mask = __ballot_sync(0xFFFFFFFFu, dv <= thresh);
            while (mask) {
                int j = __ffs(mask) - 1;
                mask &= mask - 1;
                int k = k0 + half * 32 + j;
                float part = 0.f;
                #pragma unroll
                for (int qv = 0; qv < 8; qv++)
                    part += ev[qv] * g_cbnT[(size_t)(lane * 8 + qv) * KK + k];
                #pragma unroll
                for (int off = 16; off; off >>= 1)
                    part += __shfl_xor_sync(0xFFFFFFFFu, part, off);
                float de = rsq + g_colsq[k] - 2.f * part;
                if (de < bestd || (de == bestd && k < bestk)) { bestd = de; bestk = k; }
            }
        }
    }

    if (lane == 0) {
        g_idx[n] = bestk;
        dout[OFF_IDX + n] = (float)bestk;
        atomicAdd(&g_counts[bestk], 1);
    }
}

// ---------------- commit/codebook loss partials ----------------
__global__ void k_loss(const float* __restrict__ cb)
{
    int b   = blockIdx.y;
    int t   = blockIdx.x * 256 + threadIdx.x;
    int n   = b * TT + t;
    int idx = g_idx[n];
    const float* ze = g_ze + (size_t)b * DCB * TT + t;
    const float* cr = cb + (size_t)idx * DCB;
    float s = 0.f;
    #pragma unroll 4
    for (int c = 0; c < DCB; c++) {
        float d = ze[(size_t)c * TT] - cr[c];
        s += d * d;
    }
    __shared__ float sm[256];
    sm[threadIdx.x] = s; __syncthreads();
    #pragma unroll
    for (int off = 128; off; off >>= 1) {
        if (threadIdx.x < off) sm[threadIdx.x] += sm[threadIdx.x + off];
        __syncthreads();
    }
    if (threadIdx.x == 0) g_losspart[b * 4 + blockIdx.x] = sm[0];
}

// ---------------- z_q_out gather ----------------
__global__ void k_gather(const float* __restrict__ outb, float* __restrict__ dout)
{
    int t  = blockIdx.x * 256 + threadIdx.x;
    int o4 = blockIdx.y * 4;
    int b  = blockIdx.z;
    int idx = g_idx[b * TT + t];
    float4 v = *(const float4*)(g_proj + (size_t)idx * DIN + o4);
    size_t base = OFF_ZQ + (size_t)b * DIN * TT + (size_t)o4 * TT + t;
    dout[base]          = v.x + outb[o4];
    dout[base + TT]     = v.y + outb[o4 + 1];
    dout[base + 2 * TT] = v.z + outb[o4 + 2];
    dout[base + 3 * TT] = v.w + outb[o4 + 3];
}

// ---------------- scalars ----------------
__global__ void k_final(const float* __restrict__ cs, float* __restrict__ dout)
{
    int tid = threadIdx.x;
    if (tid < BB) {
        float s = g_losspart[tid * 4] + g_losspart[tid * 4 + 1]
                + g_losspart[tid * 4 + 2] + g_losspart[tid * 4 + 3];
        float mean = s / (float)(DCB * TT);
        dout[OFF_COMMIT + tid] = mean * 0.15f;
        dout[OFF_CBL + tid]    = mean;
    }
    float ent = 0.f;
    int   act = 0;
    for (int k = tid; k < KK; k += 256) {
        float cnt = (float)g_counts[k];
        float p   = cnt / (float)NTOK;
        ent += p * logf(p + 1e-10f);
        float ncs = cs[k] * 0.99f + cnt * 0.01f;
        if (ncs > 2.0f) act++;
    }
    __shared__ float se[256];
    __shared__ int   sa[256];
    se[tid] = ent; sa[tid] = act; __syncthreads();
    #pragma unroll
    for (int off = 128; off; off >>= 1) {
        if (tid < off) { se[tid] += se[tid + off]; sa[tid] += sa[tid + off]; }
        __syncthreads();
    }
    if (tid == 0) {
        dout[OFF_PERP] = expf(-se[0]);
        dout[OFF_ACT]  = (float)sa[0];
    }
}

// ---------------- launch ----------------
extern "C" void kernel_launch(void* const* d_in, const int* in_sizes, int n_in,
                              void* d_out, int out_size)
{
    const float* z     = (const float*)d_in[0];
    const float* in_g  = (const float*)d_in[1];
    const float* in_v  = (const float*)d_in[2];
    const float* in_b  = (const float*)d_in[3];
    const float* out_g = (const float*)d_in[4];
    const float* out_v = (const float*)d_in[5];
    const float* out_b = (const float*)d_in[6];
    const float* cb    = (const float*)d_in[7];
    const float* cs    = (const float*)d_in[8];
    float* dout = (float*)d_out;

    cudaFuncSetAttribute(k_dist, cudaFuncAttributeMaxDynamicSharedMemorySize, SMEM_DIST);

    k_init<<<32, 256>>>();

    k_rownorm<<<DCB, 256>>>(0, in_v, in_g);
    k_rownorm<<<DIN, 256>>>(1, out_v, out_g);
    k_rownorm<<<KK,  256>>>(2, cb,   nullptr);

    {   // z_e = w_in @ z + in_b
        dim3 grid(TT / 128, DCB / 128, BB);
        k_gemm<0><<<grid, 256>>>(z, in_b);
    }

    k_toknorm<<<NTOK / 256, 256>>>();

    {   // dist via HMMA split-bf16
        dim3 grid(KK / 128, NTOK / 128, 1);
        k_dist<<<grid, 256, SMEM_DIST>>>(dout);
    }

    k_refine<<<NTOK / 8, 256>>>(dout);

    {
        dim3 grid(4, BB);
        k_loss<<<grid, 256>>>(cb);
    }

    {   // proj = cb @ w_out^T
        dim3 grid(DIN / 128, KK / 128, 1);
        k_gemm<2><<<grid, 256>>>(nullptr, nullptr);
    }

    {
        dim3 grid(4, 256, BB);
        k_gather<<<grid, 256>>>(out_b, dout);
    }

    k_final<<<1, 256>>>(cs, dout);
}

// round 4
// speedup vs baseline: 1.3871x; 1.0700x over previous
#include <cuda_runtime.h>
#include <cuda_bf16.h>
#include <cstdint>
#include <cstddef>

// ---------------- problem constants ----------------
#define BB   16
#define DIN  1024
#define TT   1024
#define KK   8192
#define DCB  256
#define NTOK (BB * TT)          // 16384

// ---------------- output layout (tuple flattened, f32) ----------------
static constexpr size_t OFF_ZQ     = 0;
static constexpr size_t SZ_ZQ      = (size_t)BB * DIN * TT;
static constexpr size_t OFF_IDX    = OFF_ZQ + SZ_ZQ;
static constexpr size_t OFF_COMMIT = OFF_IDX + NTOK;
static constexpr size_t OFF_CBL    = OFF_COMMIT + BB;
static constexpr size_t OFF_DIST   = OFF_CBL + BB;
static constexpr size_t SZ_DIST    = (size_t)NTOK * KK;
static constexpr size_t OFF_PERP   = OFF_DIST + SZ_DIST;
static constexpr size_t OFF_ACT    = OFF_PERP + 1;

// ---------------- scratch (device globals) ----------------
__device__ float g_w_inT [DIN * DCB];
__device__ float g_cbnT  [DCB * KK];        // normalized codebook transposed (refine)
__device__ float g_colsq [KK];
__device__ float g_ze    [BB * DCB * TT];
__device__ float g_inv   [NTOK];
__device__ float g_rowsq [NTOK];
__device__ int   g_idx   [NTOK];
__device__ int   g_counts[KK];
__device__ float g_proj  [KK * DIN];
__device__ float g_losspart[BB * 4];

// split-bf16 operands (16B aligned for cp.async)
__device__ __align__(16) __nv_bfloat16 g_a_hi[(size_t)NTOK * DCB];   // enc_n split
__device__ __align__(16) __nv_bfloat16 g_a_lo[(size_t)NTOK * DCB];
__device__ __align__(16) __nv_bfloat16 g_b_hi[(size_t)KK * DCB];     // cb_n split
__device__ __align__(16) __nv_bfloat16 g_b_lo[(size_t)KK * DCB];
__device__ __align__(16) __nv_bfloat16 g_cb_hi[(size_t)KK * DCB];    // raw cb split
__device__ __align__(16) __nv_bfloat16 g_cb_lo[(size_t)KK * DCB];
__device__ __align__(16) __nv_bfloat16 g_wo_hi[(size_t)DIN * DCB];   // w_out split
__device__ __align__(16) __nv_bfloat16 g_wo_lo[(size_t)DIN * DCB];
// per-(token, 64-code tile) packed min (key<<32 | code), tile = k/64
__device__ unsigned long long g_tilemin[(size_t)NTOK * 128];

// ---------------- helpers ----------------
__device__ __forceinline__ uint32_t smem_u32(const void* p) {
    uint32_t a;
    asm("{ .reg .u64 t; cvta.to.shared.u64 t, %1; cvt.u32.u64 %0, t; }" : "=r"(a) : "l"(p));
    return a;
}
__device__ __forceinline__ void ldsm_x4(uint32_t* r, uint32_t a) {
    asm volatile("ldmatrix.sync.aligned.m8n8.x4.shared.b16 {%0,%1,%2,%3}, [%4];"
        : "=r"(r[0]), "=r"(r[1]), "=r"(r[2]), "=r"(r[3]) : "r"(a));
}
__device__ __forceinline__ void mma_bf16(float* d, const uint32_t* a, const uint32_t* b) {
    asm volatile("mma.sync.aligned.m16n8k16.row.col.f32.bf16.bf16.f32 "
        "{%0,%1,%2,%3}, {%4,%5,%6,%7}, {%8,%9}, {%0,%1,%2,%3};"
        : "+f"(d[0]), "+f"(d[1]), "+f"(d[2]), "+f"(d[3])
        : "r"(a[0]), "r"(a[1]), "r"(a[2]), "r"(a[3]), "r"(b[0]), "r"(b[1]));
}
#define CP_ASYNC16(dst, src) \
    asm volatile("cp.async.cg.shared.global [%0], [%1], 16;" :: "r"(dst), "l"(src) : "memory")
#define CP_COMMIT() asm volatile("cp.async.commit_group;" ::: "memory")
#define CP_WAIT1()  asm volatile("cp.async.wait_group 1;" ::: "memory")
#define CP_WAIT0()  asm volatile("cp.async.wait_group 0;" ::: "memory")

__device__ __forceinline__ unsigned fkey(float f) {
    unsigned u = __float_as_uint(f);
    return (u & 0x80000000u) ? ~u : (u | 0x80000000u);
}
__device__ __forceinline__ float funkey(unsigned k) {
    unsigned u = (k & 0x80000000u) ? (k ^ 0x80000000u) : ~k;
    return __uint_as_float(u);
}

// ---------------- init ----------------
__global__ void k_init()
{
    int i = blockIdx.x * blockDim.x + threadIdx.x;
    if (i < KK) g_counts[i] = 0;
}

// ---------------- row norms + splits ----------------
// which 0: w_in  (256 x 1024) -> g_w_inT (column-major for fp32 GEMM)
// which 1: w_out (1024 x 256) -> g_wo_hi/lo (row-major split)
// which 2: codebook (8192 x 256) -> g_cbnT, g_colsq, g_b_hi/lo (norm), g_cb_hi/lo (raw)
__global__ void k_rownorm(int which, const float* __restrict__ src,
                          const float* __restrict__ gvec)
{
    int r   = blockIdx.x;
    int tid = threadIdx.x;
    int cols = (which == 0) ? DIN : DCB;
    const float* row = src + (size_t)r * cols;
    float s = 0.f;
    for (int c = tid; c < cols; c += 256) { float v = row[c]; s += v * v; }
    __shared__ float sm[256];
    sm[tid] = s; __syncthreads();
    #pragma unroll
    for (int off = 128; off; off >>= 1) {
        if (tid < off) sm[tid] += sm[tid + off];
        __syncthreads();
    }
    float sumsq = sm[0];
    if (which == 2) {
        float inv = 1.f / fmaxf(sqrtf(sumsq), 1e-12f);
        if (tid == 0) g_colsq[r] = sumsq * inv * inv;
        int c = tid;                       // cols == 256 == blockDim
        float v  = row[c];
        float vn = v * inv;
        g_cbnT[(size_t)c * KK + r] = vn;
        __nv_bfloat16 hi = __float2bfloat16_rn(vn);
        g_b_hi[(size_t)r * DCB + c] = hi;
        g_b_lo[(size_t)r * DCB + c] = __float2bfloat16_rn(vn - __bfloat162float(hi));
        __nv_bfloat16 rh = __float2bfloat16_rn(v);
        g_cb_hi[(size_t)r * DCB + c] = rh;
        g_cb_lo[(size_t)r * DCB + c] = __float2bfloat16_rn(v - __bfloat162float(rh));
    } else if (which == 0) {
        float scale = gvec[r] / sqrtf(sumsq);
        for (int c = tid; c < cols; c += 256)
            g_w_inT[(size_t)c * DCB + r] = row[c] * scale;
    } else {
        float scale = gvec[r] / sqrtf(sumsq);
        int c = tid;                       // cols == 256
        float v = row[c] * scale;
        __nv_bfloat16 hi = __float2bfloat16_rn(v);
        g_wo_hi[(size_t)r * DCB + c] = hi;
        g_wo_lo[(size_t)r * DCB + c] = __float2bfloat16_rn(v - __bfloat162float(hi));
    }
}

// ---------------- fp32 SIMT GEMM: z_e = w_inT x z + in_b ----------------
__global__ __launch_bounds__(256, 2)
void k_zein(const float* __restrict__ Bext, const float* __restrict__ bias)
{
    const float* A  = g_w_inT;                                 // [k][m], LDA=DCB
    const float* Bm = Bext + (size_t)blockIdx.z * DIN * TT;    // [k][n], LDB=TT
    float* C        = g_ze + (size_t)blockIdx.z * DCB * TT;    // [m][n], LDC=TT

    __shared__ float As[8][128];
    __shared__ float Bs[8][128];

    int tid = threadIdx.x;
    int m0  = blockIdx.y * 128;
    int n0  = blockIdx.x * 128;

    int kr = tid >> 5;
    int c4 = (tid & 31) << 2;
    const float* Ag = A  + (size_t)kr * DCB + m0 + c4;
    const float* Bg = Bm + (size_t)kr * TT + n0 + c4;

    float4 ar = *(const float4*)Ag;
    float4 br = *(const float4*)Bg;

    float acc[8][8];
    #pragma unroll
    for (int i = 0; i < 8; i++)
        #pragma unroll
        for (int j = 0; j < 8; j++) acc[i][j] = 0.f;

    int tr = (tid >> 4) << 2;
    int tc = (tid & 15) << 2;

    constexpr int KT = DIN / 8;
    for (int kt = 0; kt < KT; kt++) {
        *(float4*)&As[kr][c4] = ar;
        *(float4*)&Bs[kr][c4] = br;
        __syncthreads();
        if (kt + 1 < KT) {
            Ag += (size_t)8 * DCB;  Bg += (size_t)8 * TT;
            ar = *(const float4*)Ag;  br = *(const float4*)Bg;
        }
        #pragma unroll
        for (int c = 0; c < 8; c++) {
            float4 a0 = *(const float4*)&As[c][tr];
            float4 a1 = *(const float4*)&As[c][tr + 64];
            float4 b0 = *(const float4*)&Bs[c][tc];
            float4 b1 = *(const float4*)&Bs[c][tc + 64];
            float av[8] = {a0.x, a0.y, a0.z, a0.w, a1.x, a1.y, a1.z, a1.w};
            float bv[8] = {b0.x, b0.y, b0.z, b0.w, b1.x, b1.y, b1.z, b1.w};
            #pragma unroll
            for (int i = 0; i < 8; i++)
                #pragma unroll
                for (int j = 0; j < 8; j++)
                    acc[i][j] += av[i] * bv[j];
        }
        __syncthreads();
    }

    #pragma unroll
    for (int i = 0; i < 8; i++) {
        int m = m0 + tr + ((i < 4) ? i : 60 + i);
        float bb = bias[m];
        float* crow = C + (size_t)m * TT + n0;
        *(float4*)(crow + tc)      = make_float4(acc[i][0] + bb, acc[i][1] + bb,
                                                 acc[i][2] + bb, acc[i][3] + bb);
        *(float4*)(crow + tc + 64) = make_float4(acc[i][4] + bb, acc[i][5] + bb,
                                                 acc[i][6] + bb, acc[i][7] + bb);
    }
}

// ---------------- per-token norms + bf16 split (coalesced via SMEM transpose) ----
// block = 256 threads handles 32 tokens (one b, t0..t0+31)
__global__ __launch_bounds__(256)
void k_toknorm()
{
    __shared__ float tile[256][33];
    int blk = blockIdx.x;              // 512 blocks
    int b   = blk >> 5;
    int t0  = (blk & 31) << 5;
    int tid = threadIdx.x;

    const float* zb = g_ze + (size_t)b * DCB * TT + t0;
    #pragma unroll
    for (int i = 0; i < 32; i++) {
        int idx = tid + i * 256;       // 0..8191
        int c = idx >> 5, t = idx & 31;
        tile[c][t] = zb[(size_t)c * TT + t];
    }
    __syncthreads();

    int j    = tid >> 3;               // token within block 0..31
    int part = tid & 7;                // channel slice 0..7 (32 ch each)
    float s = 0.f;
    #pragma unroll
    for (int i = 0; i < 32; i++) {
        float v = tile[part * 32 + i][j];
        s += v * v;
    }
    s += __shfl_xor_sync(0xFFFFFFFFu, s, 4);
    s += __shfl_xor_sync(0xFFFFFFFFu, s, 2);
    s += __shfl_xor_sync(0xFFFFFFFFu, s, 1);
    float inv = 1.f / fmaxf(sqrtf(s), 1e-12f);

    int n = b * TT + t0 + j;
    if (part == 0) { g_inv[n] = inv; g_rowsq[n] = s * inv * inv; }

    uint32_t hw[16], lw[16];
    #pragma unroll
    for (int i = 0; i < 16; i++) {
        float v0 = tile[part * 32 + 2 * i][j] * inv;
        float v1 = tile[part * 32 + 2 * i + 1][j] * inv;
        __nv_bfloat162 h2 = __floats2bfloat162_rn(v0, v1);
        float l0 = v0 - __bfloat162float(h2.x);
        float l1 = v1 - __bfloat162float(h2.y);
        __nv_bfloat162 l2 = __floats2bfloat162_rn(l0, l1);
        hw[i] = *(uint32_t*)&h2;
        lw[i] = *(uint32_t*)&l2;
    }
    uint4* ah = (uint4*)(g_a_hi + (size_t)n * DCB + part * 32);
    uint4* al = (uint4*)(g_a_lo + (size_t)n * DCB + part * 32);
    #pragma unroll
    for (int i = 0; i < 4; i++) {
        ah[i] = make_uint4(hw[4*i], hw[4*i+1], hw[4*i+2], hw[4*i+3]);
        al[i] = make_uint4(lw[4*i], lw[4*i+1], lw[4*i+2], lw[4*i+3]);
    }
}

// ---------------- HMMA split-bf16 GEMM core (dist / proj) ----------------
static constexpr int ROWB      = 80;                 // 64B data + 16B pad
static constexpr int MAT_BYTES = 128 * ROWB;         // 10240
static constexpr int STAGE     = 4 * MAT_BYTES;      // Ahi, Alo, Bhi, Blo
static constexpr int COLSQ_OFF = 2 * STAGE;          // 81920
static constexpr int SMEM_DIST = COLSQ_OFF + 128 * 4;
static constexpr int SMEM_PROJ = 2 * STAGE;

__device__ __forceinline__ void load_chunk4(uint32_t sbase, int stage, int kc,
                                            int m0, int n0, int tid,
                                            const __nv_bfloat16* Ah, const __nv_bfloat16* Al,
                                            const __nv_bfloat16* Bh, const __nv_bfloat16* Bl)
{
    uint32_t st = sbase + stage * STAGE;
    #pragma unroll
    for (int i = 0; i < 8; i++) {
        int lin = tid + i * 256;            // 0..2047
        int mat = lin >> 9;                 // 0..3
        int r   = (lin >> 2) & 127;
        int c   = lin & 3;
        uint32_t dst = st + mat * MAT_BYTES + (uint32_t)(r * ROWB + c * 16);
        size_t off = ((size_t)((mat < 2 ? m0 : n0) + r) * DCB + kc * 32) * 2 + c * 16;
        const char* src;
        if      (mat == 0) src = (const char*)Ah + off;
        else if (mat == 1) src = (const char*)Al + off;
        else if (mat == 2) src = (const char*)Bh + off;
        else               src = (const char*)Bl + off;
        CP_ASYNC16(dst, src);
    }
    CP_COMMIT();
}

// mainloop shared by dist & proj: accumulates acc[2][8][4]
__device__ __forceinline__ void hmma_mainloop(uint32_t sbase, int m0, int n0, int tid,
                                              const __nv_bfloat16* Ah, const __nv_bfloat16* Al,
                                              const __nv_bfloat16* Bh, const __nv_bfloat16* Bl,
                                              float acc[2][8][4])
{
    int wid  = tid >> 5;
    int lane = tid & 31;
    int wm   = wid >> 1;
    int wn   = wid & 1;

    load_chunk4(sbase, 0, 0, m0, n0, tid, Ah, Al, Bh, Bl);

    int arow  = wm * 32 + (lane & 15);
    int acolh = (lane >> 4) * 16;
    int brow  = wn * 64 + ((lane >> 4) << 3) + (lane & 7);
    int bcolh = ((lane >> 3) & 1) * 16;

    for (int kc = 0; kc < 8; kc++) {
        int st = kc & 1;
        if (kc < 7) load_chunk4(sbase, st ^ 1, kc + 1, m0, n0, tid, Ah, Al, Bh, Bl);
        if (kc < 7) { CP_WAIT1(); } else { CP_WAIT0(); }
        __syncthreads();

        uint32_t sa_hi = sbase + st * STAGE;
        uint32_t sa_lo = sa_hi + MAT_BYTES;
        uint32_t sb_hi = sa_hi + 2 * MAT_BYTES;
        uint32_t sb_lo = sa_hi + 3 * MAT_BYTES;

        #pragma unroll
        for (int s = 0; s < 2; s++) {
            int acol = s * 32 + acolh;
            uint32_t Ahf[2][4], Alf[2][4];
            ldsm_x4(Ahf[0], sa_hi + (uint32_t)(arow * ROWB + acol));
            ldsm_x4(Ahf[1], sa_hi + (uint32_t)((arow + 16) * ROWB + acol));
            ldsm_x4(Alf[0], sa_lo + (uint32_t)(arow * ROWB + acol));
            ldsm_x4(Alf[1], sa_lo + (uint32_t)((arow + 16) * ROWB + acol));
            int bcol = s * 32 + bcolh;
            #pragma unroll
            for (int np = 0; np < 4; np++) {
                uint32_t Bhf[4], Blf[4];
                uint32_t ba = (uint32_t)((brow + np * 16) * ROWB + bcol);
                ldsm_x4(Bhf, sb_hi + ba);
                ldsm_x4(Blf, sb_lo + ba);
                #pragma unroll
                for (int mt = 0; mt < 2; mt++) {
                    mma_bf16(acc[mt][2 * np],     Ahf[mt], Bhf);
                    mma_bf16(acc[mt][2 * np],     Ahf[mt], Blf);
                    mma_bf16(acc[mt][2 * np],     Alf[mt], Bhf);
                    mma_bf16(acc[mt][2 * np + 1], Ahf[mt], Bhf + 2);
                    mma_bf16(acc[mt][2 * np + 1], Ahf[mt], Blf + 2);
                    mma_bf16(acc[mt][2 * np + 1], Alf[mt], Bhf + 2);
                }
            }
        }
        __syncthreads();
    }
}

__global__ __launch_bounds__(256, 1)
void k_dist(float* __restrict__ dout)
{
    extern __shared__ __align__(16) char smem_raw[];
    uint32_t sbase = smem_u32(smem_raw);
    float* colsq_s = (float*)(smem_raw + COLSQ_OFF);

    int tid  = threadIdx.x;
    int wid  = tid >> 5;
    int lane = tid & 31;
    int wm   = wid >> 1;
    int wn   = wid & 1;
    int n0   = blockIdx.x * 128;
    int m0   = blockIdx.y * 128;

    if (tid < 128) colsq_s[tid] = g_colsq[n0 + tid];

    float acc[2][8][4];
    #pragma unroll
    for (int mt = 0; mt < 2; mt++)
        #pragma unroll
        for (int nt = 0; nt < 8; nt++)
            #pragma unroll
            for (int j = 0; j < 4; j++) acc[mt][nt][j] = 0.f;

    hmma_mainloop(sbase, m0, n0, tid, g_a_hi, g_a_lo, g_b_hi, g_b_lo, acc);

    int q  = lane >> 2;
    int qq = lane & 3;
    int tileg = blockIdx.x * 2 + wn;
    #pragma unroll
    for (int mt = 0; mt < 2; mt++) {
        int RB = m0 + wm * 32 + mt * 16;
        #pragma unroll
        for (int h = 0; h < 2; h++) {
            int row = RB + h * 8 + q;
            float rsq = g_rowsq[row];
            float* dw = dout + OFF_DIST + (size_t)row * KK + n0;
            unsigned bkey = 0xFFFFFFFFu, bcode = 0;
            #pragma unroll
            for (int nt = 0; nt < 8; nt++) {
                int c0 = wn * 64 + nt * 8 + qq * 2;
                float d0 = rsq + colsq_s[c0]     - 2.f * acc[mt][nt][h * 2 + 0];
                float d1 = rsq + colsq_s[c0 + 1] - 2.f * acc[mt][nt][h * 2 + 1];
                *(float2*)(dw + c0) = make_float2(d0, d1);
                unsigned k0 = fkey(d0), k1 = fkey(d1);
                if (k0 < bkey) { bkey = k0; bcode = (unsigned)(n0 + c0); }
                if (k1 < bkey) { bkey = k1; bcode = (unsigned)(n0 + c0 + 1); }
            }
            unsigned long long p = ((unsigned long long)bkey << 32) | bcode;
            unsigned long long o;
            o = __shfl_xor_sync(0xFFFFFFFFu, p, 1); if (o < p) p = o;
            o = __shfl_xor_sync(0xFFFFFFFFu, p, 2); if (o < p) p = o;
            if (qq == 0) g_tilemin[(size_t)row * 128 + tileg] = p;
        }
    }
}

// proj = cb @ w_out^T   (M=8192 codes, N=1024 out-channels, K=256)
__global__ __launch_bounds__(256, 1)
void k_proj()
{
    extern __shared__ __align__(16) char smem_raw[];
    uint32_t sbase = smem_u32(smem_raw);

    int tid  = threadIdx.x;
    int wid  = tid >> 5;
    int lane = tid & 31;
    int wm   = wid >> 1;
    int wn   = wid & 1;
    int n0   = blockIdx.x * 128;
    int m0   = blockIdx.y * 128;

    float acc[2][8][4];
    #pragma unroll
    for (int mt = 0; mt < 2; mt++)
        #pragma unroll
        for (int nt = 0; nt < 8; nt++)
            #pragma unroll
            for (int j = 0; j < 4; j++) acc[mt][nt][j] = 0.f;

    hmma_mainloop(sbase, m0, n0, tid, g_cb_hi, g_cb_lo, g_wo_hi, g_wo_lo, acc);

    int q  = lane >> 2;
    int qq = lane & 3;
    #pragma unroll
    for (int mt = 0; mt < 2; mt++) {
        int RB = m0 + wm * 32 + mt * 16;
        #pragma unroll
        for (int h = 0; h < 2; h++) {
            int row = RB + h * 8 + q;
            float* pw = g_proj + (size_t)row * DIN + n0;
            #pragma unroll
            for (int nt = 0; nt < 8; nt++) {
                int c0 = wn * 64 + nt * 8 + qq * 2;
                *(float2*)(pw + c0) = make_float2(acc[mt][nt][h * 2 + 0],
                                                  acc[mt][nt][h * 2 + 1]);
            }
        }
    }
}

// ---------------- argmin refinement (exact fp32 on candidates) ----------------
__global__ void k_refine(float* __restrict__ dout)
{
    int warp = threadIdx.x >> 5;
    int lane = threadIdx.x & 31;
    int n = blockIdx.x * 8 + warp;

    const unsigned long long* tm = g_tilemin + (size_t)n * 128;
    unsigned long long best = tm[lane];
    {
        unsigned long long v;
        v = tm[lane + 32]; if (v < best) best = v;
        v = tm[lane + 64]; if (v < best) best = v;
        v = tm[lane + 96]; if (v < best) best = v;
        #pragma unroll
        for (int off = 16; off; off >>= 1) {
            unsigned long long o = __shfl_xor_sync(0xFFFFFFFFu, best, off);
            if (o < best) best = o;
        }
    }
    float dmin = funkey((unsigned)(best >> 32));
    float thresh = dmin + 1e-4f;

    int b = n >> 10, t = n & 1023;
    float inv = g_inv[n];
    float rsq = g_rowsq[n];
    float ev[8];
    #pragma unroll
    for (int j = 0; j < 8; j++)
        ev[j] = g_ze[(size_t)b * DCB * TT + (size_t)(lane * 8 + j) * TT + t] * inv;

    const float* distrow = dout + OFF_DIST + (size_t)n * KK;

    float bestd = 3.4e38f;
    int   bestk = KK;

    for (int ti = 0; ti < 128; ti++) {
        float tmin = funkey((unsigned)(tm[ti] >> 32));
        if (tmin > thresh) continue;
        int k0 = ti * 64;
        float d0 = distrow[k0 + lane];
        float d1 = distrow[k0 + 32 + lane];
        #pragma unroll
        for (int half = 0; half < 2; half++) {
            float dv = (half == 0) ? d0 : d1;
            unsigned mask = __ballot_sync(0xFFFFFFFFu, dv <= thresh);
            while (mask) {
                int j = __ffs(mask) - 1;
                mask &= mask - 1;
                int k = k0 + half * 32 + j;
                float part = 0.f;
                #pragma unroll
                for (int qv = 0; qv < 8; qv++)
                    part += ev[qv] * g_cbnT[(size_t)(lane * 8 + qv) * KK + k];
                #pragma unroll
                for (int off = 16; off; off >>= 1)
                    part += __shfl_xor_sync(0xFFFFFFFFu, part, off);
                float de = rsq + g_colsq[k] - 2.f * part;
                if (de < bestd || (de == bestd && k < bestk)) { bestd = de; bestk = k; }
            }
        }
    }

    if (lane == 0) {
        g_idx[n] = bestk;
        dout[OFF_IDX + n] = (float)bestk;
        atomicAdd(&g_counts[bestk], 1);
    }
}

// ---------------- commit/codebook loss partials ----------------
__global__ void k_loss(const float* __restrict__ cb)
{
    int b   = blockIdx.y;
    int t   = blockIdx.x * 256 + threadIdx.x;
    int n   = b * TT + t;
    int idx = g_idx[n];
    const float* ze = g_ze + (size_t)b * DCB * TT + t;
    const float* cr = cb + (size_t)idx * DCB;
    float s = 0.f;
    #pragma unroll 4
    for (int c = 0; c < DCB; c++) {
        float d = ze[(size_t)c * TT] - cr[c];
        s += d * d;
    }
    __shared__ float sm[256];
    sm[threadIdx.x] = s; __syncthreads();
    #pragma unroll
    for (int off = 128; off; off >>= 1) {
        if (threadIdx.x < off) sm[threadIdx.x] += sm[threadIdx.x + off];
        __syncthreads();
    }
    if (threadIdx.x == 0) g_losspart[b * 4 + blockIdx.x] = sm[0];
}

// ---------------- z_q_out gather ----------------
__global__ void k_gather(const float* __restrict__ outb, float* __restrict__ dout)
{
    int t  = blockIdx.x * 256 + threadIdx.x;
    int o4 = blockIdx.y * 4;
    int b  = blockIdx.z;
    int idx = g_idx[b * TT + t];
    float4 v = *(const float4*)(g_proj + (size_t)idx * DIN + o4);
    size_t base = OFF_ZQ + (size_t)b * DIN * TT + (size_t)o4 * TT + t;
    dout[base]          = v.x + outb[o4];
    dout[base + TT]     = v.y + outb[o4 + 1];
    dout[base + 2 * TT] = v.z + outb[o4 + 2];
    dout[base + 3 * TT] = v.w + outb[o4 + 3];
}

// ---------------- scalars ----------------
__global__ void k_final(const float* __restrict__ cs, float* __restrict__ dout)
{
    int tid = threadIdx.x;
    if (tid < BB) {
        float s = g_losspart[tid * 4] + g_losspart[tid * 4 + 1]
                + g_losspart[tid * 4 + 2] + g_losspart[tid * 4 + 3];
        float mean = s / (float)(DCB * TT);
        dout[OFF_COMMIT + tid] = mean * 0.15f;
        dout[OFF_CBL + tid]    = mean;
    }
    float ent = 0.f;
    int   act = 0;
    for (int k = tid; k < KK; k += 256) {
        float cnt = (float)g_counts[k];
        float p   = cnt / (float)NTOK;
        ent += p * logf(p + 1e-10f);
        float ncs = cs[k] * 0.99f + cnt * 0.01f;
        if (ncs > 2.0f) act++;
    }
    __shared__ float se[256];
    __shared__ int   sa[256];
    se[tid] = ent; sa[tid] = act; __syncthreads();
    #pragma unroll
    for (int off = 128; off; off >>= 1) {
        if (tid < off) { se[tid] += se[tid + off]; sa[tid] += sa[tid + off]; }
        __syncthreads();
    }
    if (tid == 0) {
        dout[OFF_PERP] = expf(-se[0]);
        dout[OFF_ACT]  = (float)sa[0];
    }
}

// ---------------- launch ----------------
extern "C" void kernel_launch(void* const* d_in, const int* in_sizes, int n_in,
                              void* d_out, int out_size)
{
    const float* z     = (const float*)d_in[0];
    const float* in_g  = (const float*)d_in[1];
    const float* in_v  = (const float*)d_in[2];
    const float* in_b  = (const float*)d_in[3];
    const float* out_g = (const float*)d_in[4];
    const float* out_v = (const float*)d_in[5];
    const float* out_b = (const float*)d_in[6];
    const float* cb    = (const float*)d_in[7];
    const float* cs    = (const float*)d_in[8];
    float* dout = (float*)d_out;

    cudaFuncSetAttribute(k_dist, cudaFuncAttributeMaxDynamicSharedMemorySize, SMEM_DIST);
    cudaFuncSetAttribute(k_proj, cudaFuncAttributeMaxDynamicSharedMemorySize, SMEM_PROJ);

    k_init<<<32, 256>>>();

    k_rownorm<<<DCB, 256>>>(0, in_v, in_g);
    k_rownorm<<<DIN, 256>>>(1, out_v, out_g);
    k_rownorm<<<KK,  256>>>(2, cb,   nullptr);

    {   // z_e = w_in @ z + in_b
        dim3 grid(TT / 128, DCB / 128, BB);
        k_zein<<<grid, 256>>>(z, in_b);
    }

    k_toknorm<<<NTOK / 32, 256>>>();

    {   // dist via HMMA split-bf16
        dim3 grid(KK / 128, NTOK / 128, 1);
        k_dist<<<grid, 256, SMEM_DIST>>>(dout);
    }

    k_refine<<<NTOK / 8, 256>>>(dout);

    {
        dim3 grid(4, BB);
        k_loss<<<grid, 256>>>(cb);
    }

    {   // proj = cb @ w_out^T via HMMA
        dim3 grid(DIN / 128, KK / 128, 1);
        k_proj<<<grid, 256, SMEM_PROJ>>>();
    }

    {
        dim3 grid(4, 256, BB);
        k_gather<<<grid, 256>>>(out_b, dout);
    }

    k_final<<<1, 256>>>(cs, dout);
}

// round 5
// speedup vs baseline: 1.9487x; 1.4049x over previous
#include <cuda_runtime.h>
#include <cuda_bf16.h>
#include <cstdint>
#include <cstddef>

// ---------------- problem constants ----------------
#define BB   16
#define DIN  1024
#define TT   1024
#define KK   8192
#define DCB  256
#define NTOK (BB * TT)          // 16384

// ---------------- output layout (tuple flattened, f32) ----------------
static constexpr size_t OFF_ZQ     = 0;
static constexpr size_t SZ_ZQ      = (size_t)BB * DIN * TT;
static constexpr size_t OFF_IDX    = OFF_ZQ + SZ_ZQ;
static constexpr size_t OFF_COMMIT = OFF_IDX + NTOK;
static constexpr size_t OFF_CBL    = OFF_COMMIT + BB;
static constexpr size_t OFF_DIST   = OFF_CBL + BB;
static constexpr size_t SZ_DIST    = (size_t)NTOK * KK;
static constexpr size_t OFF_PERP   = OFF_DIST + SZ_DIST;
static constexpr size_t OFF_ACT    = OFF_PERP + 1;

// ---------------- scratch (device globals) ----------------
__device__ float g_w_inT [DIN * DCB];
__device__ float g_cbnT  [DCB * KK];        // normalized codebook transposed (refine)
__device__ float g_colsq [KK];              // ||cb_n||^2
__device__ float g_cbsq  [KK];              // ||cb||^2 raw
__device__ float g_cbinv [KK];              // 1/max(||cb||,eps)
__device__ float g_ze    [BB * DCB * TT];
__device__ float g_inv   [NTOK];
__device__ float g_rowsq [NTOK];            // ||enc_n||^2
__device__ float g_rowsq_raw[NTOK];         // ||z_e||^2 raw
__device__ float g_lossn [NTOK];
__device__ int   g_idx   [NTOK];
__device__ int   g_counts[KK];
__device__ float g_proj  [KK * DIN];

// split-bf16 operands (16B aligned for cp.async)
__device__ __align__(16) __nv_bfloat16 g_a_hi[(size_t)NTOK * DCB];   // enc_n split hi
__device__ __align__(16) __nv_bfloat16 g_a_lo[(size_t)NTOK * DCB];   // enc_n split lo
__device__ __align__(16) __nv_bfloat16 g_b_hi[(size_t)KK * DCB];     // cb_n rounded
__device__ __align__(16) __nv_bfloat16 g_cb_hi[(size_t)KK * DCB];    // raw cb split
__device__ __align__(16) __nv_bfloat16 g_cb_lo[(size_t)KK * DCB];
__device__ __align__(16) __nv_bfloat16 g_wo_hi[(size_t)DIN * DCB];   // w_out split
__device__ __align__(16) __nv_bfloat16 g_wo_lo[(size_t)DIN * DCB];
// per-(token, 64-code tile) packed min (key<<32 | code), tile = k/64
__device__ unsigned long long g_tilemin[(size_t)NTOK * 128];

// ---------------- helpers ----------------
__device__ __forceinline__ uint32_t smem_u32(const void* p) {
    uint32_t a;
    asm("{ .reg .u64 t; cvta.to.shared.u64 t, %1; cvt.u32.u64 %0, t; }" : "=r"(a) : "l"(p));
    return a;
}
__device__ __forceinline__ void ldsm_x4(uint32_t* r, uint32_t a) {
    asm volatile("ldmatrix.sync.aligned.m8n8.x4.shared.b16 {%0,%1,%2,%3}, [%4];"
        : "=r"(r[0]), "=r"(r[1]), "=r"(r[2]), "=r"(r[3]) : "r"(a));
}
__device__ __forceinline__ void mma_bf16(float* d, const uint32_t* a, const uint32_t* b) {
    asm volatile("mma.sync.aligned.m16n8k16.row.col.f32.bf16.bf16.f32 "
        "{%0,%1,%2,%3}, {%4,%5,%6,%7}, {%8,%9}, {%0,%1,%2,%3};"
        : "+f"(d[0]), "+f"(d[1]), "+f"(d[2]), "+f"(d[3])
        : "r"(a[0]), "r"(a[1]), "r"(a[2]), "r"(a[3]), "r"(b[0]), "r"(b[1]));
}
#define CP_ASYNC16(dst, src) \
    asm volatile("cp.async.cg.shared.global [%0], [%1], 16;" :: "r"(dst), "l"(src) : "memory")
#define CP_COMMIT() asm volatile("cp.async.commit_group;" ::: "memory")
#define CP_WAIT1()  asm volatile("cp.async.wait_group 1;" ::: "memory")
#define CP_WAIT0()  asm volatile("cp.async.wait_group 0;" ::: "memory")

__device__ __forceinline__ unsigned fkey(float f) {
    unsigned u = __float_as_uint(f);
    return (u & 0x80000000u) ? ~u : (u | 0x80000000u);
}
__device__ __forceinline__ float funkey(unsigned k) {
    unsigned u = (k & 0x80000000u) ? (k ^ 0x80000000u) : ~k;
    return __uint_as_float(u);
}

// ---------------- prep: init + all weight norms + splits (one launch) --------
// blocks [0,256)            : w_in rows
// blocks [256,1280)         : w_out rows
// blocks [1280,9472)        : codebook rows (+ counts zero)
__global__ void k_prep(const float* __restrict__ in_v, const float* __restrict__ in_g,
                       const float* __restrict__ out_v, const float* __restrict__ out_g,
                       const float* __restrict__ cb)
{
    int blk = blockIdx.x;
    int tid = threadIdx.x;
    __shared__ float sm[256];

    if (blk < 256) {                                    // w_in: 256 rows x 1024
        int r = blk;
        const float* row = in_v + (size_t)r * DIN;
        float s = 0.f;
        for (int c = tid; c < DIN; c += 256) { float v = row[c]; s += v * v; }
        sm[tid] = s; __syncthreads();
        #pragma unroll
        for (int off = 128; off; off >>= 1) {
            if (tid < off) sm[tid] += sm[tid + off];
            __syncthreads();
        }
        float scale = in_g[r] / sqrtf(sm[0]);
        for (int c = tid; c < DIN; c += 256)
            g_w_inT[(size_t)c * DCB + r] = row[c] * scale;
    } else if (blk < 1280) {                            // w_out: 1024 rows x 256
        int r = blk - 256;
        const float* row = out_v + (size_t)r * DCB;
        float v = row[tid];
        sm[tid] = v * v; __syncthreads();
        #pragma unroll
        for (int off = 128; off; off >>= 1) {
            if (tid < off) sm[tid] += sm[tid + off];
            __syncthreads();
        }
        float scale = out_g[r] / sqrtf(sm[0]);
        float w = v * scale;
        __nv_bfloat16 hi = __float2bfloat16_rn(w);
        g_wo_hi[(size_t)r * DCB + tid] = hi;
        g_wo_lo[(size_t)r * DCB + tid] = __float2bfloat16_rn(w - __bfloat162float(hi));
    } else {                                            // codebook: 8192 rows x 256
        int r = blk - 1280;
        const float* row = cb + (size_t)r * DCB;
        float v = row[tid];
        sm[tid] = v * v; __syncthreads();
        #pragma unroll
        for (int off = 128; off; off >>= 1) {
            if (tid < off) sm[tid] += sm[tid + off];
            __syncthreads();
        }
        float sumsq = sm[0];
        float inv = 1.f / fmaxf(sqrtf(sumsq), 1e-12f);
        if (tid == 0) {
            g_colsq[r] = sumsq * inv * inv;
            g_cbsq[r]  = sumsq;
            g_cbinv[r] = inv;
            g_counts[r] = 0;
        }
        float vn = v * inv;
        g_cbnT[(size_t)tid * KK + r] = vn;
        g_b_hi[(size_t)r * DCB + tid] = __float2bfloat16_rn(vn);
        __nv_bfloat16 rh = __float2bfloat16_rn(v);
        g_cb_hi[(size_t)r * DCB + tid] = rh;
        g_cb_lo[(size_t)r * DCB + tid] = __float2bfloat16_rn(v - __bfloat162float(rh));
    }
}

// ---------------- fp32 SIMT GEMM: z_e = w_inT x z + in_b ----------------
__global__ __launch_bounds__(256, 2)
void k_zein(const float* __restrict__ Bext, const float* __restrict__ bias)
{
    const float* A  = g_w_inT;
    const float* Bm = Bext + (size_t)blockIdx.z * DIN * TT;
    float* C        = g_ze + (size_t)blockIdx.z * DCB * TT;

    __shared__ float As[8][128];
    __shared__ float Bs[8][128];

    int tid = threadIdx.x;
    int m0  = blockIdx.y * 128;
    int n0  = blockIdx.x * 128;

    int kr = tid >> 5;
    int c4 = (tid & 31) << 2;
    const float* Ag = A  + (size_t)kr * DCB + m0 + c4;
    const float* Bg = Bm + (size_t)kr * TT + n0 + c4;

    float4 ar = *(const float4*)Ag;
    float4 br = *(const float4*)Bg;

    float acc[8][8];
    #pragma unroll
    for (int i = 0; i < 8; i++)
        #pragma unroll
        for (int j = 0; j < 8; j++) acc[i][j] = 0.f;

    int tr = (tid >> 4) << 2;
    int tc = (tid & 15) << 2;

    constexpr int KT = DIN / 8;
    for (int kt = 0; kt < KT; kt++) {
        *(float4*)&As[kr][c4] = ar;
        *(float4*)&Bs[kr][c4] = br;
        __syncthreads();
        if (kt + 1 < KT) {
            Ag += (size_t)8 * DCB;  Bg += (size_t)8 * TT;
            ar = *(const float4*)Ag;  br = *(const float4*)Bg;
        }
        #pragma unroll
        for (int c = 0; c < 8; c++) {
            float4 a0 = *(const float4*)&As[c][tr];
            float4 a1 = *(const float4*)&As[c][tr + 64];
            float4 b0 = *(const float4*)&Bs[c][tc];
            float4 b1 = *(const float4*)&Bs[c][tc + 64];
            float av[8] = {a0.x, a0.y, a0.z, a0.w, a1.x, a1.y, a1.z, a1.w};
            float bv[8] = {b0.x, b0.y, b0.z, b0.w, b1.x, b1.y, b1.z, b1.w};
            #pragma unroll
            for (int i = 0; i < 8; i++)
                #pragma unroll
                for (int j = 0; j < 8; j++)
                    acc[i][j] += av[i] * bv[j];
        }
        __syncthreads();
    }

    #pragma unroll
    for (int i = 0; i < 8; i++) {
        int m = m0 + tr + ((i < 4) ? i : 60 + i);
        float bb = bias[m];
        float* crow = C + (size_t)m * TT + n0;
        *(float4*)(crow + tc)      = make_float4(acc[i][0] + bb, acc[i][1] + bb,
                                                 acc[i][2] + bb, acc[i][3] + bb);
        *(float4*)(crow + tc + 64) = make_float4(acc[i][4] + bb, acc[i][5] + bb,
                                                 acc[i][6] + bb, acc[i][7] + bb);
    }
}

// ---------------- per-token norms + bf16 split (coalesced) ----------------
__global__ __launch_bounds__(256)
void k_toknorm()
{
    __shared__ float tile[256][33];
    int blk = blockIdx.x;
    int b   = blk >> 5;
    int t0  = (blk & 31) << 5;
    int tid = threadIdx.x;

    const float* zb = g_ze + (size_t)b * DCB * TT + t0;
    #pragma unroll
    for (int i = 0; i < 32; i++) {
        int idx = tid + i * 256;
        int c = idx >> 5, t = idx & 31;
        tile[c][t] = zb[(size_t)c * TT + t];
    }
    __syncthreads();

    int j    = tid >> 3;
    int part = tid & 7;
    float s = 0.f;
    #pragma unroll
    for (int i = 0; i < 32; i++) {
        float v = tile[part * 32 + i][j];
        s += v * v;
    }
    s += __shfl_xor_sync(0xFFFFFFFFu, s, 4);
    s += __shfl_xor_sync(0xFFFFFFFFu, s, 2);
    s += __shfl_xor_sync(0xFFFFFFFFu, s, 1);
    float inv = 1.f / fmaxf(sqrtf(s), 1e-12f);

    int n = b * TT + t0 + j;
    if (part == 0) {
        g_inv[n] = inv;
        g_rowsq[n] = s * inv * inv;
        g_rowsq_raw[n] = s;
    }

    uint32_t hw[16], lw[16];
    #pragma unroll
    for (int i = 0; i < 16; i++) {
        float v0 = tile[part * 32 + 2 * i][j] * inv;
        float v1 = tile[part * 32 + 2 * i + 1][j] * inv;
        __nv_bfloat162 h2 = __floats2bfloat162_rn(v0, v1);
        float l0 = v0 - __bfloat162float(h2.x);
        float l1 = v1 - __bfloat162float(h2.y);
        __nv_bfloat162 l2 = __floats2bfloat162_rn(l0, l1);
        hw[i] = *(uint32_t*)&h2;
        lw[i] = *(uint32_t*)&l2;
    }
    uint4* ah = (uint4*)(g_a_hi + (size_t)n * DCB + part * 32);
    uint4* al = (uint4*)(g_a_lo + (size_t)n * DCB + part * 32);
    #pragma unroll
    for (int i = 0; i < 4; i++) {
        ah[i] = make_uint4(hw[4*i], hw[4*i+1], hw[4*i+2], hw[4*i+3]);
        al[i] = make_uint4(lw[4*i], lw[4*i+1], lw[4*i+2], lw[4*i+3]);
    }
}

// ---------------- HMMA GEMM tiles ----------------
static constexpr int ROWB      = 80;
static constexpr int MAT_BYTES = 128 * ROWB;          // 10240
static constexpr int STAGE3    = 3 * MAT_BYTES;       // dist: Ahi, Alo, Bhi
static constexpr int STAGE4    = 4 * MAT_BYTES;       // proj: Ahi, Alo, Bhi, Blo
static constexpr int COLSQ_OFF = 2 * STAGE3;          // 61440
static constexpr int SMEM_DIST = COLSQ_OFF + 128 * 4; // 61952
static constexpr int SMEM_PROJ = 2 * STAGE4;          // 81920

// dist loader: 3 matrices (Ahi, Alo, Bhi), 1536 x 16B
__device__ __forceinline__ void load_chunk3(uint32_t sbase, int stage, int kc,
                                            int m0, int n0, int tid)
{
    uint32_t st = sbase + stage * STAGE3;
    #pragma unroll
    for (int i = 0; i < 6; i++) {
        int lin = tid + i * 256;            // 0..1535
        int mat = lin >> 9;                 // 0..2
        int r   = (lin >> 2) & 127;
        int c   = lin & 3;
        uint32_t dst = st + mat * MAT_BYTES + (uint32_t)(r * ROWB + c * 16);
        size_t off = ((size_t)((mat < 2 ? m0 : n0) + r) * DCB + kc * 32) * 2 + c * 16;
        const char* src;
        if      (mat == 0) src = (const char*)g_a_hi + off;
        else if (mat == 1) src = (const char*)g_a_lo + off;
        else               src = (const char*)g_b_hi + off;
        CP_ASYNC16(dst, src);
    }
    CP_COMMIT();
}

__global__ __launch_bounds__(256, 2)
void k_dist(float* __restrict__ dout)
{
    extern __shared__ __align__(16) char smem_raw[];
    uint32_t sbase = smem_u32(smem_raw);
    float* colsq_s = (float*)(smem_raw + COLSQ_OFF);

    int tid  = threadIdx.x;
    int wid  = tid >> 5;
    int lane = tid & 31;
    int wm   = wid >> 1;
    int wn   = wid & 1;
    int n0   = blockIdx.x * 128;
    int m0   = blockIdx.y * 128;

    if (tid < 128) colsq_s[tid] = g_colsq[n0 + tid];

    float acc[2][8][4];
    #pragma unroll
    for (int mt = 0; mt < 2; mt++)
        #pragma unroll
        for (int nt = 0; nt < 8; nt++)
            #pragma unroll
            for (int j = 0; j < 4; j++) acc[mt][nt][j] = 0.f;

    load_chunk3(sbase, 0, 0, m0, n0, tid);

    int arow  = wm * 32 + (lane & 15);
    int acolh = (lane >> 4) * 16;
    int brow  = wn * 64 + ((lane >> 4) << 3) + (lane & 7);
    int bcolh = ((lane >> 3) & 1) * 16;

    for (int kc = 0; kc < 8; kc++) {
        int st = kc & 1;
        if (kc < 7) load_chunk3(sbase, st ^ 1, kc + 1, m0, n0, tid);
        if (kc < 7) { CP_WAIT1(); } else { CP_WAIT0(); }
        __syncthreads();

        uint32_t sa_hi = sbase + st * STAGE3;
        uint32_t sa_lo = sa_hi + MAT_BYTES;
        uint32_t sb_hi = sa_hi + 2 * MAT_BYTES;

        #pragma unroll
        for (int s = 0; s < 2; s++) {
            int acol = s * 32 + acolh;
            uint32_t Ahf[2][4], Alf[2][4];
            ldsm_x4(Ahf[0], sa_hi + (uint32_t)(arow * ROWB + acol));
            ldsm_x4(Ahf[1], sa_hi + (uint32_t)((arow + 16) * ROWB + acol));
            ldsm_x4(Alf[0], sa_lo + (uint32_t)(arow * ROWB + acol));
            ldsm_x4(Alf[1], sa_lo + (uint32_t)((arow + 16) * ROWB + acol));
            int bcol = s * 32 + bcolh;
            #pragma unroll
            for (int np = 0; np < 4; np++) {
                uint32_t Bhf[4];
                uint32_t ba = (uint32_t)((brow + np * 16) * ROWB + bcol);
                ldsm_x4(Bhf, sb_hi + ba);
                #pragma unroll
                for (int mt = 0; mt < 2; mt++) {
                    mma_bf16(acc[mt][2 * np],     Ahf[mt], Bhf);
                    mma_bf16(acc[mt][2 * np],     Alf[mt], Bhf);
                    mma_bf16(acc[mt][2 * np + 1], Ahf[mt], Bhf + 2);
                    mma_bf16(acc[mt][2 * np + 1], Alf[mt], Bhf + 2);
                }
            }
        }
        __syncthreads();
    }

    int q  = lane >> 2;
    int qq = lane & 3;
    int tileg = blockIdx.x * 2 + wn;
    #pragma unroll
    for (int mt = 0; mt < 2; mt++) {
        int RB = m0 + wm * 32 + mt * 16;
        #pragma unroll
        for (int h = 0; h < 2; h++) {
            int row = RB + h * 8 + q;
            float rsq = g_rowsq[row];
            float* dw = dout + OFF_DIST + (size_t)row * KK + n0;
            unsigned bkey = 0xFFFFFFFFu, bcode = 0;
            #pragma unroll
            for (int nt = 0; nt < 8; nt++) {
                int c0 = wn * 64 + nt * 8 + qq * 2;
                float d0 = rsq + colsq_s[c0]     - 2.f * acc[mt][nt][h * 2 + 0];
                float d1 = rsq + colsq_s[c0 + 1] - 2.f * acc[mt][nt][h * 2 + 1];
                *(float2*)(dw + c0) = make_float2(d0, d1);
                unsigned k0 = fkey(d0), k1 = fkey(d1);
                if (k0 < bkey) { bkey = k0; bcode = (unsigned)(n0 + c0); }
                if (k1 < bkey) { bkey = k1; bcode = (unsigned)(n0 + c0 + 1); }
            }
            unsigned long long p = ((unsigned long long)bkey << 32) | bcode;
            unsigned long long o;
            o = __shfl_xor_sync(0xFFFFFFFFu, p, 1); if (o < p) p = o;
            o = __shfl_xor_sync(0xFFFFFFFFu, p, 2); if (o < p) p = o;
            if (qq == 0) g_tilemin[(size_t)row * 128 + tileg] = p;
        }
    }
}

// proj loader: 4 matrices (cb hi/lo, wo hi/lo)
__device__ __forceinline__ void load_chunk4(uint32_t sbase, int stage, int kc,
                                            int m0, int n0, int tid)
{
    uint32_t st = sbase + stage * STAGE4;
    #pragma unroll
    for (int i = 0; i < 8; i++) {
        int lin = tid + i * 256;
        int mat = lin >> 9;
        int r   = (lin >> 2) & 127;
        int c   = lin & 3;
        uint32_t dst = st + mat * MAT_BYTES + (uint32_t)(r * ROWB + c * 16);
        size_t off = ((size_t)((mat < 2 ? m0 : n0) + r) * DCB + kc * 32) * 2 + c * 16;
        const char* src;
        if      (mat == 0) src = (const char*)g_cb_hi + off;
        else if (mat == 1) src = (const char*)g_cb_lo + off;
        else if (mat == 2) src = (const char*)g_wo_hi + off;
        else               src = (const char*)g_wo_lo + off;
        CP_ASYNC16(dst, src);
    }
    CP_COMMIT();
}

__global__ __launch_bounds__(256, 1)
void k_proj()
{
    extern __shared__ __align__(16) char smem_raw[];
    uint32_t sbase = smem_u32(smem_raw);

    int tid  = threadIdx.x;
    int wid  = tid >> 5;
    int lane = tid & 31;
    int wm   = wid >> 1;
    int wn   = wid & 1;
    int n0   = blockIdx.x * 128;
    int m0   = blockIdx.y * 128;

    float acc[2][8][4];
    #pragma unroll
    for (int mt = 0; mt < 2; mt++)
        #pragma unroll
        for (int nt = 0; nt < 8; nt++)
            #pragma unroll
            for (int j = 0; j < 4; j++) acc[mt][nt][j] = 0.f;

    load_chunk4(sbase, 0, 0, m0, n0, tid);

    int arow  = wm * 32 + (lane & 15);
    int acolh = (lane >> 4) * 16;
    int brow  = wn * 64 + ((lane >> 4) << 3) + (lane & 7);
    int bcolh = ((lane >> 3) & 1) * 16;

    for (int kc = 0; kc < 8; kc++) {
        int st = kc & 1;
        if (kc < 7) load_chunk4(sbase, st ^ 1, kc + 1, m0, n0, tid);
        if (kc < 7) { CP_WAIT1(); } else { CP_WAIT0(); }
        __syncthreads();

        uint32_t sa_hi = sbase + st * STAGE4;
        uint32_t sa_lo = sa_hi + MAT_BYTES;
        uint32_t sb_hi = sa_hi + 2 * MAT_BYTES;
        uint32_t sb_lo = sa_hi + 3 * MAT_BYTES;

        #pragma unroll
        for (int s = 0; s < 2; s++) {
            int acol = s * 32 + acolh;
            uint32_t Ahf[2][4], Alf[2][4];
            ldsm_x4(Ahf[0], sa_hi + (uint32_t)(arow * ROWB + acol));
            ldsm_x4(Ahf[1], sa_hi + (uint32_t)((arow + 16) * ROWB + acol));
            ldsm_x4(Alf[0], sa_lo + (uint32_t)(arow * ROWB + acol));
            ldsm_x4(Alf[1], sa_lo + (uint32_t)((arow + 16) * ROWB + acol));
            int bcol = s * 32 + bcolh;
            #pragma unroll
            for (int np = 0; np < 4; np++) {
                uint32_t Bhf[4], Blf[4];
                uint32_t ba = (uint32_t)((brow + np * 16) * ROWB + bcol);
                ldsm_x4(Bhf, sb_hi + ba);
                ldsm_x4(Blf, sb_lo + ba);
                #pragma unroll
                for (int mt = 0; mt < 2; mt++) {
                    mma_bf16(acc[mt][2 * np],     Ahf[mt], Bhf);
                    mma_bf16(acc[mt][2 * np],     Ahf[mt], Blf);
                    mma_bf16(acc[mt][2 * np],     Alf[mt], Bhf);
                    mma_bf16(acc[mt][2 * np + 1], Ahf[mt], Bhf + 2);
                    mma_bf16(acc[mt][2 * np + 1], Ahf[mt], Blf + 2);
                    mma_bf16(acc[mt][2 * np + 1], Alf[mt], Bhf + 2);
                }
            }
        }
        __syncthreads();
    }

    int q  = lane >> 2;
    int qq = lane & 3;
    #pragma unroll
    for (int mt = 0; mt < 2; mt++) {
        int RB = m0 + wm * 32 + mt * 16;
        #pragma unroll
        for (int h = 0; h < 2; h++) {
            int row = RB + h * 8 + q;
            float* pw = g_proj + (size_t)row * DIN + n0;
            #pragma unroll
            for (int nt = 0; nt < 8; nt++) {
                int c0 = wn * 64 + nt * 8 + qq * 2;
                *(float2*)(pw + c0) = make_float2(acc[mt][nt][h * 2 + 0],
                                                  acc[mt][nt][h * 2 + 1]);
            }
        }
    }
}

// ---------------- argmin refinement (exact fp32) + fused loss ----------------
__global__ void k_refine(float* __restrict__ dout)
{
    int warp = threadIdx.x >> 5;
    int lane = threadIdx.x & 31;
    int n = blockIdx.x * 8 + warp;

    const unsigned long long* tm = g_tilemin + (size_t)n * 128;
    unsigned long long best = tm[lane];
    {
        unsigned long long v;
        v = tm[lane + 32]; if (v < best) best = v;
        v = tm[lane + 64]; if (v < best) best = v;
        v = tm[lane + 96]; if (v < best) best = v;
        #pragma unroll
        for (int off = 16; off; off >>= 1) {
            unsigned long long o = __shfl_xor_sync(0xFFFFFFFFu, best, off);
            if (o < best) best = o;
        }
    }
    float dmin = funkey((unsigned)(best >> 32));
    float thresh = dmin + 3e-3f;

    int b = n >> 10, t = n & 1023;
    float inv = g_inv[n];
    float rsq = g_rowsq[n];
    float ev[8];
    #pragma unroll
    for (int j = 0; j < 8; j++)
        ev[j] = g_ze[(size_t)b * DCB * TT + (size_t)(lane * 8 + j) * TT + t] * inv;

    const float* distrow = dout + OFF_DIST + (size_t)n * KK;

    float bestd = 3.4e38f;
    int   bestk = KK;
    float bestpart = 0.f;

    for (int ti = 0; ti < 128; ti++) {
        float tmin = funkey((unsigned)(tm[ti] >> 32));
        if (tmin > thresh) continue;
        int k0 = ti * 64;
        float d0 = distrow[k0 + lane];
        float d1 = distrow[k0 + 32 + lane];
        #pragma unroll
        for (int half = 0; half < 2; half++) {
            float dv = (half == 0) ? d0 : d1;
            unsigned mask = __ballot_sync(0xFFFFFFFFu, dv <= thresh);
            while (mask) {
                int j = __ffs(mask) - 1;
                mask &= mask - 1;
                int k = k0 + half * 32 + j;
                float part = 0.f;
                #pragma unroll
                for (int qv = 0; qv < 8; qv++)
                    part += ev[qv] * g_cbnT[(size_t)(lane * 8 + qv) * KK + k];
                #pragma unroll
                for (int off = 16; off; off >>= 1)
                    part += __shfl_xor_sync(0xFFFFFFFFu, part, off);
                float de = rsq + g_colsq[k] - 2.f * part;
                if (de < bestd || (de == bestd && k < bestk)) {
                    bestd = de; bestk = k; bestpart = part;
                }
            }
        }
    }

    if (lane == 0) {
        g_idx[n] = bestk;
        dout[OFF_IDX + n] = (float)bestk;
        atomicAdd(&g_counts[bestk], 1);
        // loss: ||ze - cb_k||^2 = ||ze||^2 + ||cb_k||^2 - 2 * (enc_n . cb_n) * ||ze|| * ||cb_k||
        float dot_raw = bestpart / (inv * g_cbinv[bestk]);
        g_lossn[n] = g_rowsq_raw[n] + g_cbsq[bestk] - 2.f * dot_raw;
    }
}

// ---------------- z_q_out gather ----------------
__global__ void k_gather(const float* __restrict__ outb, float* __restrict__ dout)
{
    int t  = blockIdx.x * 256 + threadIdx.x;
    int o4 = blockIdx.y * 4;
    int b  = blockIdx.z;
    int idx = g_idx[b * TT + t];
    float4 v = *(const float4*)(g_proj + (size_t)idx * DIN + o4);
    size_t base = OFF_ZQ + (size_t)b * DIN * TT + (size_t)o4 * TT + t;
    dout[base]          = v.x + outb[o4];
    dout[base + TT]     = v.y + outb[o4 + 1];
    dout[base + 2 * TT] = v.z + outb[o4 + 2];
    dout[base + 3 * TT] = v.w + outb[o4 + 3];
}

// ---------------- scalars: losses, perplexity, active ----------------
__global__ void k_final(const float* __restrict__ cs, float* __restrict__ dout)
{
    int tid = threadIdx.x;
    // deterministic per-batch loss reduction: 16 threads per batch, fixed order
    __shared__ float lsum[256];
    {
        int bb = tid >> 4;          // batch
        int sl = tid & 15;          // slot
        float s = 0.f;
        #pragma unroll 4
        for (int i = 0; i < 64; i++)
            s += g_lossn[bb * TT + sl + i * 16];
        lsum[tid] = s;
    }
    __syncthreads();
    if (tid < BB) {
        float s = 0.f;
        #pragma unroll
        for (int i = 0; i < 16; i++) s += lsum[tid * 16 + i];
        float mean = s / (float)(DCB * TT);
        dout[OFF_COMMIT + tid] = mean * 0.15f;
        dout[OFF_CBL + tid]    = mean;
    }

    float ent = 0.f;
    int   act = 0;
    for (int k = tid; k < KK; k += 256) {
        float cnt = (float)g_counts[k];
        float p   = cnt / (float)NTOK;
        ent += p * logf(p + 1e-10f);
        float ncs = cs[k] * 0.99f + cnt * 0.01f;
        if (ncs > 2.0f) act++;
    }
    __shared__ float se[256];
    __shared__ int   sa[256];
    se[tid] = ent; sa[tid] = act; __syncthreads();
    #pragma unroll
    for (int off = 128; off; off >>= 1) {
        if (tid < off) { se[tid] += se[tid + off]; sa[tid] += sa[tid + off]; }
        __syncthreads();
    }
    if (tid == 0) {
        dout[OFF_PERP] = expf(-se[0]);
        dout[OFF_ACT]  = (float)sa[0];
    }
}

// ---------------- launch ----------------
extern "C" void kernel_launch(void* const* d_in, const int* in_sizes, int n_in,
                              void* d_out, int out_size)
{
    const float* z     = (const float*)d_in[0];
    const float* in_g  = (const float*)d_in[1];
    const float* in_v  = (const float*)d_in[2];
    const float* in_b  = (const float*)d_in[3];
    const float* out_g = (const float*)d_in[4];
    const float* out_v = (const float*)d_in[5];
    const float* out_b = (const float*)d_in[6];
    const float* cb    = (const float*)d_in[7];
    const float* cs    = (const float*)d_in[8];
    float* dout = (float*)d_out;

    cudaFuncSetAttribute(k_dist, cudaFuncAttributeMaxDynamicSharedMemorySize, SMEM_DIST);
    cudaFuncSetAttribute(k_proj, cudaFuncAttributeMaxDynamicSharedMemorySize, SMEM_PROJ);

    k_prep<<<1280 + KK, 256>>>(in_v, in_g, out_v, out_g, cb);      // #1

    {   // #2: z_e = w_in @ z + in_b
        dim3 grid(TT / 128, DCB / 128, BB);
        k_zein<<<grid, 256>>>(z, in_b);
    }

    k_toknorm<<<NTOK / 32, 256>>>();                               // #3

    {   // #4: dist via HMMA 2-pass split-bf16
        dim3 grid(KK / 128, NTOK / 128, 1);
        k_dist<<<grid, 256, SMEM_DIST>>>(dout);
    }

    k_refine<<<NTOK / 8, 256>>>(dout);                             // #5

    {   // #6: proj = cb @ w_out^T via HMMA 3-pass
        dim3 grid(DIN / 128, KK / 128, 1);
        k_proj<<<grid, 256, SMEM_PROJ>>>();
    }

    {   // #7
        dim3 grid(4, 256, BB);
        k_gather<<<grid, 256>>>(out_b, dout);
    }

    k_final<<<1, 256>>>(cs, dout);                                 // #8
}

// round 6
// speedup vs baseline: 2.1524x; 1.1045x over previous
#include <cuda_runtime.h>
#include <cuda_bf16.h>
#include <cstdint>
#include <cstddef>

// ---------------- problem constants ----------------
#define BB   16
#define DIN  1024
#define TT   1024
#define KK   8192
#define DCB  256
#define NTOK (BB * TT)          // 16384

// ---------------- output layout (tuple flattened, f32) ----------------
static constexpr size_t OFF_ZQ     = 0;
static constexpr size_t SZ_ZQ      = (size_t)BB * DIN * TT;
static constexpr size_t OFF_IDX    = OFF_ZQ + SZ_ZQ;
static constexpr size_t OFF_COMMIT = OFF_IDX + NTOK;
static constexpr size_t OFF_CBL    = OFF_COMMIT + BB;
static constexpr size_t OFF_DIST   = OFF_CBL + BB;
static constexpr size_t SZ_DIST    = (size_t)NTOK * KK;
static constexpr size_t OFF_PERP   = OFF_DIST + SZ_DIST;
static constexpr size_t OFF_ACT    = OFF_PERP + 1;

// ---------------- scratch (device globals) ----------------
__device__ float g_w_inT [DIN * DCB];
__device__ float g_cbn   [KK * DCB];        // normalized codebook, ROW-major (refine)
__device__ float g_colsq [KK];              // ||cb_n||^2
__device__ float g_cbsq  [KK];              // ||cb||^2 raw
__device__ float g_cbinv [KK];              // 1/max(||cb||,eps)
__device__ float g_ze    [BB * DCB * TT];
__device__ float g_inv   [NTOK];
__device__ float g_rowsq [NTOK];            // ||enc_n||^2
__device__ float g_rowsq_raw[NTOK];         // ||z_e||^2 raw
__device__ float g_lossn [NTOK];
__device__ int   g_idx   [NTOK];
__device__ int   g_counts[KK];
__device__ float g_proj  [KK * DIN];

// split-bf16 operands (16B aligned for cp.async)
__device__ __align__(16) __nv_bfloat16 g_a_hi[(size_t)NTOK * DCB];   // enc_n split hi
__device__ __align__(16) __nv_bfloat16 g_a_lo[(size_t)NTOK * DCB];   // enc_n split lo
__device__ __align__(16) __nv_bfloat16 g_b_hi[(size_t)KK * DCB];     // cb_n rounded
__device__ __align__(16) __nv_bfloat16 g_cb_hi[(size_t)KK * DCB];    // raw cb split
__device__ __align__(16) __nv_bfloat16 g_cb_lo[(size_t)KK * DCB];
__device__ __align__(16) __nv_bfloat16 g_wo_hi[(size_t)DIN * DCB];   // w_out split
__device__ __align__(16) __nv_bfloat16 g_wo_lo[(size_t)DIN * DCB];
// per-(token, 64-code tile) packed min (key<<32 | code), tile = k/64
__device__ unsigned long long g_tilemin[(size_t)NTOK * 128];

// ---------------- helpers ----------------
__device__ __forceinline__ uint32_t smem_u32(const void* p) {
    uint32_t a;
    asm("{ .reg .u64 t; cvta.to.shared.u64 t, %1; cvt.u32.u64 %0, t; }" : "=r"(a) : "l"(p));
    return a;
}
__device__ __forceinline__ void ldsm_x4(uint32_t* r, uint32_t a) {
    asm volatile("ldmatrix.sync.aligned.m8n8.x4.shared.b16 {%0,%1,%2,%3}, [%4];"
        : "=r"(r[0]), "=r"(r[1]), "=r"(r[2]), "=r"(r[3]) : "r"(a));
}
__device__ __forceinline__ void mma_bf16(float* d, const uint32_t* a, const uint32_t* b) {
    asm volatile("mma.sync.aligned.m16n8k16.row.col.f32.bf16.bf16.f32 "
        "{%0,%1,%2,%3}, {%4,%5,%6,%7}, {%8,%9}, {%0,%1,%2,%3};"
        : "+f"(d[0]), "+f"(d[1]), "+f"(d[2]), "+f"(d[3])
        : "r"(a[0]), "r"(a[1]), "r"(a[2]), "r"(a[3]), "r"(b[0]), "r"(b[1]));
}
#define CP_ASYNC16(dst, src) \
    asm volatile("cp.async.cg.shared.global [%0], [%1], 16;" :: "r"(dst), "l"(src) : "memory")
#define CP_COMMIT() asm volatile("cp.async.commit_group;" ::: "memory")
#define CP_WAIT1()  asm volatile("cp.async.wait_group 1;" ::: "memory")
#define CP_WAIT0()  asm volatile("cp.async.wait_group 0;" ::: "memory")

__device__ __forceinline__ unsigned fkey(float f) {
    unsigned u = __float_as_uint(f);
    return (u & 0x80000000u) ? ~u : (u | 0x80000000u);
}
__device__ __forceinline__ float funkey(unsigned k) {
    unsigned u = (k & 0x80000000u) ? (k ^ 0x80000000u) : ~k;
    return __uint_as_float(u);
}

// ---------------- prep A: w_in weight-norm (main stream) ----------------
__global__ void k_prep_win(const float* __restrict__ in_v, const float* __restrict__ in_g)
{
    int r   = blockIdx.x;                // 256 blocks
    int tid = threadIdx.x;
    const float* row = in_v + (size_t)r * DIN;
    float s = 0.f;
    for (int c = tid; c < DIN; c += 256) { float v = row[c]; s += v * v; }
    __shared__ float sm[256];
    sm[tid] = s; __syncthreads();
    #pragma unroll
    for (int off = 128; off; off >>= 1) {
        if (tid < off) sm[tid] += sm[tid + off];
        __syncthreads();
    }
    float scale = in_g[r] / sqrtf(sm[0]);
    for (int c = tid; c < DIN; c += 256)
        g_w_inT[(size_t)c * DCB + r] = row[c] * scale;
}

// ---------------- prep B: w_out + codebook norms & splits (stream 2) --------
// blocks [0,1024): w_out rows; blocks [1024,9216): codebook rows
__global__ void k_prep_cbwo(const float* __restrict__ out_v, const float* __restrict__ out_g,
                            const float* __restrict__ cb)
{
    int blk = blockIdx.x;
    int tid = threadIdx.x;
    __shared__ float sm[256];

    if (blk < 1024) {                                   // w_out: 1024 rows x 256
        int r = blk;
        const float* row = out_v + (size_t)r * DCB;
        float v = row[tid];
        sm[tid] = v * v; __syncthreads();
        #pragma unroll
        for (int off = 128; off; off >>= 1) {
            if (tid < off) sm[tid] += sm[tid + off];
            __syncthreads();
        }
        float scale = out_g[r] / sqrtf(sm[0]);
        float w = v * scale;
        __nv_bfloat16 hi = __float2bfloat16_rn(w);
        g_wo_hi[(size_t)r * DCB + tid] = hi;
        g_wo_lo[(size_t)r * DCB + tid] = __float2bfloat16_rn(w - __bfloat162float(hi));
    } else {                                            // codebook: 8192 rows x 256
        int r = blk - 1024;
        const float* row = cb + (size_t)r * DCB;
        float v = row[tid];
        sm[tid] = v * v; __syncthreads();
        #pragma unroll
        for (int off = 128; off; off >>= 1) {
            if (tid < off) sm[tid] += sm[tid + off];
            __syncthreads();
        }
        float sumsq = sm[0];
        float inv = 1.f / fmaxf(sqrtf(sumsq), 1e-12f);
        if (tid == 0) {
            g_colsq[r] = sumsq * inv * inv;
            g_cbsq[r]  = sumsq;
            g_cbinv[r] = inv;
            g_counts[r] = 0;
        }
        float vn = v * inv;
        g_cbn[(size_t)r * DCB + tid] = vn;              // row-major, coalesced
        g_b_hi[(size_t)r * DCB + tid] = __float2bfloat16_rn(vn);
        __nv_bfloat16 rh = __float2bfloat16_rn(v);
        g_cb_hi[(size_t)r * DCB + tid] = rh;
        g_cb_lo[(size_t)r * DCB + tid] = __float2bfloat16_rn(v - __bfloat162float(rh));
    }
}

// ---------------- fp32 SIMT GEMM: z_e = w_inT x z + in_b ----------------
__global__ __launch_bounds__(256, 2)
void k_zein(const float* __restrict__ Bext, const float* __restrict__ bias)
{
    const float* A  = g_w_inT;
    const float* Bm = Bext + (size_t)blockIdx.z * DIN * TT;
    float* C        = g_ze + (size_t)blockIdx.z * DCB * TT;

    __shared__ float As[8][128];
    __shared__ float Bs[8][128];

    int tid = threadIdx.x;
    int m0  = blockIdx.y * 128;
    int n0  = blockIdx.x * 128;

    int kr = tid >> 5;
    int c4 = (tid & 31) << 2;
    const float* Ag = A  + (size_t)kr * DCB + m0 + c4;
    const float* Bg = Bm + (size_t)kr * TT + n0 + c4;

    float4 ar = *(const float4*)Ag;
    float4 br = *(const float4*)Bg;

    float acc[8][8];
    #pragma unroll
    for (int i = 0; i < 8; i++)
        #pragma unroll
        for (int j = 0; j < 8; j++) acc[i][j] = 0.f;

    int tr = (tid >> 4) << 2;
    int tc = (tid & 15) << 2;

    constexpr int KT = DIN / 8;
    for (int kt = 0; kt < KT; kt++) {
        *(float4*)&As[kr][c4] = ar;
        *(float4*)&Bs[kr][c4] = br;
        __syncthreads();
        if (kt + 1 < KT) {
            Ag += (size_t)8 * DCB;  Bg += (size_t)8 * TT;
            ar = *(const float4*)Ag;  br = *(const float4*)Bg;
        }
        #pragma unroll
        for (int c = 0; c < 8; c++) {
            float4 a0 = *(const float4*)&As[c][tr];
            float4 a1 = *(const float4*)&As[c][tr + 64];
            float4 b0 = *(const float4*)&Bs[c][tc];
            float4 b1 = *(const float4*)&Bs[c][tc + 64];
            float av[8] = {a0.x, a0.y, a0.z, a0.w, a1.x, a1.y, a1.z, a1.w};
            float bv[8] = {b0.x, b0.y, b0.z, b0.w, b1.x, b1.y, b1.z, b1.w};
            #pragma unroll
            for (int i = 0; i < 8; i++)
                #pragma unroll
                for (int j = 0; j < 8; j++)
                    acc[i][j] += av[i] * bv[j];
        }
        __syncthreads();
    }

    #pragma unroll
    for (int i = 0; i < 8; i++) {
        int m = m0 + tr + ((i < 4) ? i : 60 + i);
        float bb = bias[m];
        float* crow = C + (size_t)m * TT + n0;
        *(float4*)(crow + tc)      = make_float4(acc[i][0] + bb, acc[i][1] + bb,
                                                 acc[i][2] + bb, acc[i][3] + bb);
        *(float4*)(crow + tc + 64) = make_float4(acc[i][4] + bb, acc[i][5] + bb,
                                                 acc[i][6] + bb, acc[i][7] + bb);
    }
}

// ---------------- per-token norms + bf16 split (coalesced) ----------------
__global__ __launch_bounds__(256)
void k_toknorm()
{
    __shared__ float tile[256][33];
    int blk = blockIdx.x;
    int b   = blk >> 5;
    int t0  = (blk & 31) << 5;
    int tid = threadIdx.x;

    const float* zb = g_ze + (size_t)b * DCB * TT + t0;
    #pragma unroll
    for (int i = 0; i < 32; i++) {
        int idx = tid + i * 256;
        int c = idx >> 5, t = idx & 31;
        tile[c][t] = zb[(size_t)c * TT + t];
    }
    __syncthreads();

    int j    = tid >> 3;
    int part = tid & 7;
    float s = 0.f;
    #pragma unroll
    for (int i = 0; i < 32; i++) {
        float v = tile[part * 32 + i][j];
        s += v * v;
    }
    s += __shfl_xor_sync(0xFFFFFFFFu, s, 4);
    s += __shfl_xor_sync(0xFFFFFFFFu, s, 2);
    s += __shfl_xor_sync(0xFFFFFFFFu, s, 1);
    float inv = 1.f / fmaxf(sqrtf(s), 1e-12f);

    int n = b * TT + t0 + j;
    if (part == 0) {
        g_inv[n] = inv;
        g_rowsq[n] = s * inv * inv;
        g_rowsq_raw[n] = s;
    }

    uint32_t hw[16], lw[16];
    #pragma unroll
    for (int i = 0; i < 16; i++) {
        float v0 = tile[part * 32 + 2 * i][j] * inv;
        float v1 = tile[part * 32 + 2 * i + 1][j] * inv;
        __nv_bfloat162 h2 = __floats2bfloat162_rn(v0, v1);
        float l0 = v0 - __bfloat162float(h2.x);
        float l1 = v1 - __bfloat162float(h2.y);
        __nv_bfloat162 l2 = __floats2bfloat162_rn(l0, l1);
        hw[i] = *(uint32_t*)&h2;
        lw[i] = *(uint32_t*)&l2;
    }
    uint4* ah = (uint4*)(g_a_hi + (size_t)n * DCB + part * 32);
    uint4* al = (uint4*)(g_a_lo + (size_t)n * DCB + part * 32);
    #pragma unroll
    for (int i = 0; i < 4; i++) {
        ah[i] = make_uint4(hw[4*i], hw[4*i+1], hw[4*i+2], hw[4*i+3]);
        al[i] = make_uint4(lw[4*i], lw[4*i+1], lw[4*i+2], lw[4*i+3]);
    }
}

// ---------------- HMMA GEMM tiles ----------------
static constexpr int ROWB      = 80;
static constexpr int MAT_BYTES = 128 * ROWB;          // 10240
static constexpr int STAGE3    = 3 * MAT_BYTES;       // dist: Ahi, Alo, Bhi
static constexpr int STAGE4    = 4 * MAT_BYTES;       // proj: Ahi, Alo, Bhi, Blo
static constexpr int COLSQ_OFF = 3 * STAGE3;          // 92160 (after 3-stage ring)
static constexpr int SMEM_DIST = COLSQ_OFF + 128 * 4; // 92672
static constexpr int SMEM_PROJ = 2 * STAGE4;          // 81920

// dist loader: 3 matrices (Ahi, Alo, Bhi), 1536 x 16B
__device__ __forceinline__ void load_chunk3(uint32_t sbase, int stage, int kc,
                                            int m0, int n0, int tid)
{
    uint32_t st = sbase + stage * STAGE3;
    #pragma unroll
    for (int i = 0; i < 6; i++) {
        int lin = tid + i * 256;            // 0..1535
        int mat = lin >> 9;                 // 0..2
        int r   = (lin >> 2) & 127;
        int c   = lin & 3;
        uint32_t dst = st + mat * MAT_BYTES + (uint32_t)(r * ROWB + c * 16);
        size_t off = ((size_t)((mat < 2 ? m0 : n0) + r) * DCB + kc * 32) * 2 + c * 16;
        const char* src;
        if      (mat == 0) src = (const char*)g_a_hi + off;
        else if (mat == 1) src = (const char*)g_a_lo + off;
        else               src = (const char*)g_b_hi + off;
        CP_ASYNC16(dst, src);
    }
    CP_COMMIT();
}

__global__ __launch_bounds__(256, 2)
void k_dist(float* __restrict__ dout)
{
    extern __shared__ __align__(16) char smem_raw[];
    uint32_t sbase = smem_u32(smem_raw);
    float* colsq_s = (float*)(smem_raw + COLSQ_OFF);

    int tid  = threadIdx.x;
    int wid  = tid >> 5;
    int lane = tid & 31;
    int wm   = wid >> 1;
    int wn   = wid & 1;
    int n0   = blockIdx.x * 128;
    int m0   = blockIdx.y * 128;

    if (tid < 128) colsq_s[tid] = g_colsq[n0 + tid];

    float acc[2][8][4];
    #pragma unroll
    for (int mt = 0; mt < 2; mt++)
        #pragma unroll
        for (int nt = 0; nt < 8; nt++)
            #pragma unroll
            for (int j = 0; j < 4; j++) acc[mt][nt][j] = 0.f;

    // 3-stage ring prologue
    load_chunk3(sbase, 0, 0, m0, n0, tid);
    load_chunk3(sbase, 1, 1, m0, n0, tid);

    int arow  = wm * 32 + (lane & 15);
    int acolh = (lane >> 4) * 16;
    int brow  = wn * 64 + ((lane >> 4) << 3) + (lane & 7);
    int bcolh = ((lane >> 3) & 1) * 16;

    int stage = 0;
    for (int kc = 0; kc < 8; kc++) {
        if (kc < 7) { CP_WAIT1(); } else { CP_WAIT0(); }
        __syncthreads();     // all warps done with the stage we are about to refill
        if (kc + 2 < 8) {
            int nstage = stage + 2; if (nstage >= 3) nstage -= 3;
            load_chunk3(sbase, nstage, kc + 2, m0, n0, tid);
        }

        uint32_t sa_hi = sbase + stage * STAGE3;
        uint32_t sa_lo = sa_hi + MAT_BYTES;
        uint32_t sb_hi = sa_hi + 2 * MAT_BYTES;

        #pragma unroll
        for (int s = 0; s < 2; s++) {
            int acol = s * 32 + acolh;
            uint32_t Ahf[2][4], Alf[2][4];
            ldsm_x4(Ahf[0], sa_hi + (uint32_t)(arow * ROWB + acol));
            ldsm_x4(Ahf[1], sa_hi + (uint32_t)((arow + 16) * ROWB + acol));
            ldsm_x4(Alf[0], sa_lo + (uint32_t)(arow * ROWB + acol));
            ldsm_x4(Alf[1], sa_lo + (uint32_t)((arow + 16) * ROWB + acol));
            int bcol = s * 32 + bcolh;
            #pragma unroll
            for (int np = 0; np < 4; np++) {
                uint32_t Bhf[4];
                uint32_t ba = (uint32_t)((brow + np * 16) * ROWB + bcol);
                ldsm_x4(Bhf, sb_hi + ba);
                #pragma unroll
                for (int mt = 0; mt < 2; mt++) {
                    mma_bf16(acc[mt][2 * np],     Ahf[mt], Bhf);
                    mma_bf16(acc[mt][2 * np],     Alf[mt], Bhf);
                    mma_bf16(acc[mt][2 * np + 1], Ahf[mt], Bhf + 2);
                    mma_bf16(acc[mt][2 * np + 1], Alf[mt], Bhf + 2);
                }
            }
        }
        stage = (stage + 1 == 3) ? 0 : stage + 1;
    }

    int q  = lane >> 2;
    int qq = lane & 3;
    int tileg = blockIdx.x * 2 + wn;
    #pragma unroll
    for (int mt = 0; mt < 2; mt++) {
        int RB = m0 + wm * 32 + mt * 16;
        #pragma unroll
        for (int h = 0; h < 2; h++) {
            int row = RB + h * 8 + q;
            float rsq = g_rowsq[row];
            float* dw = dout + OFF_DIST + (size_t)row * KK + n0;
            unsigned bkey = 0xFFFFFFFFu, bcode = 0;
            #pragma unroll
            for (int nt = 0; nt < 8; nt++) {
                int c0 = wn * 64 + nt * 8 + qq * 2;
                float d0 = rsq + colsq_s[c0]     - 2.f * acc[mt][nt][h * 2 + 0];
                float d1 = rsq + colsq_s[c0 + 1] - 2.f * acc[mt][nt][h * 2 + 1];
                *(float2*)(dw + c0) = make_float2(d0, d1);
                unsigned k0 = fkey(d0), k1 = fkey(d1);
                if (k0 < bkey) { bkey = k0; bcode = (unsigned)(n0 + c0); }
                if (k1 < bkey) { bkey = k1; bcode = (unsigned)(n0 + c0 + 1); }
            }
            unsigned long long p = ((unsigned long long)bkey << 32) | bcode;
            unsigned long long o;
            o = __shfl_xor_sync(0xFFFFFFFFu, p, 1); if (o < p) p = o;
            o = __shfl_xor_sync(0xFFFFFFFFu, p, 2); if (o < p) p = o;
            if (qq == 0) g_tilemin[(size_t)row * 128 + tileg] = p;
        }
    }
}

// proj loader: 4 matrices (cb hi/lo, wo hi/lo)
__device__ __forceinline__ void load_chunk4(uint32_t sbase, int stage, int kc,
                                            int m0, int n0, int tid)
{
    uint32_t st = sbase + stage * STAGE4;
    #pragma unroll
    for (int i = 0; i < 8; i++) {
        int lin = tid + i * 256;
        int mat = lin >> 9;
        int r   = (lin >> 2) & 127;
        int c   = lin & 3;
        uint32_t dst = st + mat * MAT_BYTES + (uint32_t)(r * ROWB + c * 16);
        size_t off = ((size_t)((mat < 2 ? m0 : n0) + r) * DCB + kc * 32) * 2 + c * 16;
        const char* src;
        if      (mat == 0) src = (const char*)g_cb_hi + off;
        else if (mat == 1) src = (const char*)g_cb_lo + off;
        else if (mat == 2) src = (const char*)g_wo_hi + off;
        else               src = (const char*)g_wo_lo + off;
        CP_ASYNC16(dst, src);
    }
    CP_COMMIT();
}

__global__ __launch_bounds__(256, 2)
void k_proj()
{
    extern __shared__ __align__(16) char smem_raw[];
    uint32_t sbase = smem_u32(smem_raw);

    int tid  = threadIdx.x;
    int wid  = tid >> 5;
    int lane = tid & 31;
    int wm   = wid >> 1;
    int wn   = wid & 1;
    int n0   = blockIdx.x * 128;
    int m0   = blockIdx.y * 128;

    float acc[2][8][4];
    #pragma unroll
    for (int mt = 0; mt < 2; mt++)
        #pragma unroll
        for (int nt = 0; nt < 8; nt++)
            #pragma unroll
            for (int j = 0; j < 4; j++) acc[mt][nt][j] = 0.f;

    load_chunk4(sbase, 0, 0, m0, n0, tid);

    int arow  = wm * 32 + (lane & 15);
    int acolh = (lane >> 4) * 16;
    int brow  = wn * 64 + ((lane >> 4) << 3) + (lane & 7);
    int bcolh = ((lane >> 3) & 1) * 16;

    for (int kc = 0; kc < 8; kc++) {
        int st = kc & 1;
        if (kc < 7) load_chunk4(sbase, st ^ 1, kc + 1, m0, n0, tid);
        if (kc < 7) { CP_WAIT1(); } else { CP_WAIT0(); }
        __syncthreads();

        uint32_t sa_hi = sbase + st * STAGE4;
        uint32_t sa_lo = sa_hi + MAT_BYTES;
        uint32_t sb_hi = sa_hi + 2 * MAT_BYTES;
        uint32_t sb_lo = sa_hi + 3 * MAT_BYTES;

        #pragma unroll
        for (int s = 0; s < 2; s++) {
            int acol = s * 32 + acolh;
            uint32_t Ahf[2][4], Alf[2][4];
            ldsm_x4(Ahf[0], sa_hi + (uint32_t)(arow * ROWB + acol));
            ldsm_x4(Ahf[1], sa_hi + (uint32_t)((arow + 16) * ROWB + acol));
            ldsm_x4(Alf[0], sa_lo + (uint32_t)(arow * ROWB + acol));
            ldsm_x4(Alf[1], sa_lo + (uint32_t)((arow + 16) * ROWB + acol));
            int bcol = s * 32 + bcolh;
            #pragma unroll
            for (int np = 0; np < 4; np++) {
                uint32_t Bhf[4], Blf[4];
                uint32_t ba = (uint32_t)((brow + np * 16) * ROWB + bcol);
                ldsm_x4(Bhf, sb_hi + ba);
                ldsm_x4(Blf, sb_lo + ba);
                #pragma unroll
                for (int mt = 0; mt < 2; mt++) {
                    mma_bf16(acc[mt][2 * np],     Ahf[mt], Bhf);
                    mma_bf16(acc[mt][2 * np],     Ahf[mt], Blf);
                    mma_bf16(acc[mt][2 * np],     Alf[mt], Bhf);
                    mma_bf16(acc[mt][2 * np + 1], Ahf[mt], Bhf + 2);
                    mma_bf16(acc[mt][2 * np + 1], Ahf[mt], Blf + 2);
                    mma_bf16(acc[mt][2 * np + 1], Alf[mt], Bhf + 2);
                }
            }
        }
        __syncthreads();
    }

    int q  = lane >> 2;
    int qq = lane & 3;
    #pragma unroll
    for (int mt = 0; mt < 2; mt++) {
        int RB = m0 + wm * 32 + mt * 16;
        #pragma unroll
        for (int h = 0; h < 2; h++) {
            int row = RB + h * 8 + q;
            float* pw = g_proj + (size_t)row * DIN + n0;
            #pragma unroll
            for (int nt = 0; nt < 8; nt++) {
                int c0 = wn * 64 + nt * 8 + qq * 2;
                *(float2*)(pw + c0) = make_float2(acc[mt][nt][h * 2 + 0],
                                                  acc[mt][nt][h * 2 + 1]);
            }
        }
    }
}

// ---------------- argmin refinement (near-exact fp32) + fused loss ----------
__global__ void k_refine(float* __restrict__ dout)
{
    int warp = threadIdx.x >> 5;
    int lane = threadIdx.x & 31;
    int n = blockIdx.x * 8 + warp;

    const unsigned long long* tm = g_tilemin + (size_t)n * 128;
    unsigned long long best = tm[lane];
    {
        unsigned long long v;
        v = tm[lane + 32]; if (v < best) best = v;
        v = tm[lane + 64]; if (v < best) best = v;
        v = tm[lane + 96]; if (v < best) best = v;
        #pragma unroll
        for (int off = 16; off; off >>= 1) {
            unsigned long long o = __shfl_xor_sync(0xFFFFFFFFu, best, off);
            if (o < best) best = o;
        }
    }
    float dmin = funkey((unsigned)(best >> 32));
    float thresh = dmin + 4e-3f;

    float inv = g_inv[n];
    float rsq = g_rowsq[n];
    // enc_n reconstructed from split (residual ~2^-16 relative: dist error ~1e-7)
    float ev[8];
    {
        const __nv_bfloat16* ah = g_a_hi + (size_t)n * DCB + lane * 8;
        const __nv_bfloat16* al = g_a_lo + (size_t)n * DCB + lane * 8;
        #pragma unroll
        for (int j = 0; j < 8; j++)
            ev[j] = __bfloat162float(ah[j]) + __bfloat162float(al[j]);
    }

    const float* distrow = dout + OFF_DIST + (size_t)n * KK;

    float bestd = 3.4e38f;
    int   bestk = KK;
    float bestpart = 0.f;

    for (int ti = 0; ti < 128; ti++) {
        float tmin = funkey((unsigned)(tm[ti] >> 32));
        if (tmin > thresh) continue;
        int k0 = ti * 64;
        float d0 = distrow[k0 + lane];
        float d1 = distrow[k0 + 32 + lane];
        #pragma unroll
        for (int half = 0; half < 2; half++) {
            float dv = (half == 0) ? d0 : d1;
            unsigned mask = __ballot_sync(0xFFFFFFFFu, dv <= thresh);
            while (mask) {
                int j = __ffs(mask) - 1;
                mask &= mask - 1;
                int k = k0 + half * 32 + j;
                const float* cr = g_cbn + (size_t)k * DCB + lane * 8;
                float part = 0.f;
                #pragma unroll
                for (int qv = 0; qv < 8; qv++)
                    part += ev[qv] * cr[qv];
                #pragma unroll
                for (int off = 16; off; off >>= 1)
                    part += __shfl_xor_sync(0xFFFFFFFFu, part, off);
                float de = rsq + g_colsq[k] - 2.f * part;
                if (de < bestd || (de == bestd && k < bestk)) {
                    bestd = de; bestk = k; bestpart = part;
                }
            }
        }
    }

    if (lane == 0) {
        g_idx[n] = bestk;
        dout[OFF_IDX + n] = (float)bestk;
        atomicAdd(&g_counts[bestk], 1);
        float dot_raw = bestpart / (inv * g_cbinv[bestk]);
        g_lossn[n] = g_rowsq_raw[n] + g_cbsq[bestk] - 2.f * dot_raw;
    }
}

// ---------------- z_q_out gather ----------------
__global__ void k_gather(const float* __restrict__ outb, float* __restrict__ dout)
{
    int t  = blockIdx.x * 256 + threadIdx.x;
    int o4 = blockIdx.y * 4;
    int b  = blockIdx.z;
    int idx = g_idx[b * TT + t];
    float4 v = *(const float4*)(g_proj + (size_t)idx * DIN + o4);
    size_t base = OFF_ZQ + (size_t)b * DIN * TT + (size_t)o4 * TT + t;
    dout[base]          = v.x + outb[o4];
    dout[base + TT]     = v.y + outb[o4 + 1];
    dout[base + 2 * TT] = v.z + outb[o4 + 2];
    dout[base + 3 * TT] = v.w + outb[o4 + 3];
}

// ---------------- scalars: losses, perplexity, active ----------------
__global__ void k_final(const float* __restrict__ cs, float* __restrict__ dout)
{
    int tid = threadIdx.x;
    __shared__ float lsum[256];
    {
        int bb = tid >> 4;
        int sl = tid & 15;
        float s = 0.f;
        #pragma unroll 4
        for (int i = 0; i < 64; i++)
            s += g_lossn[bb * TT + sl + i * 16];
        lsum[tid] = s;
    }
    __syncthreads();
    if (tid < BB) {
        float s = 0.f;
        #pragma unroll
        for (int i = 0; i < 16; i++) s += lsum[tid * 16 + i];
        float mean = s / (float)(DCB * TT);
        dout[OFF_COMMIT + tid] = mean * 0.15f;
        dout[OFF_CBL + tid]    = mean;
    }

    float ent = 0.f;
    int   act = 0;
    for (int k = tid; k < KK; k += 256) {
        float cnt = (float)g_counts[k];
        float p   = cnt / (float)NTOK;
        ent += p * logf(p + 1e-10f);
        float ncs = cs[k] * 0.99f + cnt * 0.01f;
        if (ncs > 2.0f) act++;
    }
    __shared__ float se[256];
    __shared__ int   sa[256];
    se[tid] = ent; sa[tid] = act; __syncthreads();
    #pragma unroll
    for (int off = 128; off; off >>= 1) {
        if (tid < off) { se[tid] += se[tid + off]; sa[tid] += sa[tid + off]; }
        __syncthreads();
    }
    if (tid == 0) {
        dout[OFF_PERP] = expf(-se[0]);
        dout[OFF_ACT]  = (float)sa[0];
    }
}

// ---------------- launch (fork-join: prep_cbwo + proj overlap zein chain) ----
extern "C" void kernel_launch(void* const* d_in, const int* in_sizes, int n_in,
                              void* d_out, int out_size)
{
    const float* z     = (const float*)d_in[0];
    const float* in_g  = (const float*)d_in[1];
    const float* in_v  = (const float*)d_in[2];
    const float* in_b  = (const float*)d_in[3];
    const float* out_g = (const float*)d_in[4];
    const float* out_v = (const float*)d_in[5];
    const float* out_b = (const float*)d_in[6];
    const float* cb    = (const float*)d_in[7];
    const float* cs    = (const float*)d_in[8];
    float* dout = (float*)d_out;

    static cudaStream_t s2 = nullptr;
    static cudaEvent_t  evF = nullptr, evJ = nullptr;
    if (!s2) {
        cudaStreamCreateWithFlags(&s2, cudaStreamNonBlocking);
        cudaEventCreateWithFlags(&evF, cudaEventDisableTiming);
        cudaEventCreateWithFlags(&evJ, cudaEventDisableTiming);
        cudaFuncSetAttribute(k_dist, cudaFuncAttributeMaxDynamicSharedMemorySize, SMEM_DIST);
        cudaFuncSetAttribute(k_proj, cudaFuncAttributeMaxDynamicSharedMemorySize, SMEM_PROJ);
    }

    // fork: stream2 does codebook/w_out prep + proj GEMM
    cudaEventRecord(evF, 0);
    cudaStreamWaitEvent(s2, evF, 0);
    k_prep_cbwo<<<1024 + KK, 256, 0, s2>>>(out_v, out_g, cb);
    {
        dim3 grid(DIN / 128, KK / 128, 1);
        k_proj<<<grid, 256, SMEM_PROJ, s2>>>();
    }
    cudaEventRecord(evJ, s2);

    // main chain
    k_prep_win<<<256, 256>>>(in_v, in_g);
    {
        dim3 grid(TT / 128, DCB / 128, BB);
        k_zein<<<grid, 256>>>(z, in_b);
    }
    k_toknorm<<<NTOK / 32, 256>>>();

    // join: dist needs g_b_hi/g_colsq; refine needs g_cbn; gather needs g_proj
    cudaStreamWaitEvent(0, evJ, 0);

    {
        dim3 grid(KK / 128, NTOK / 128, 1);
        k_dist<<<grid, 256, SMEM_DIST>>>(dout);
    }
    k_refine<<<NTOK / 8, 256>>>(dout);
    {
        dim3 grid(4, 256, BB);
        k_gather<<<grid, 256>>>(out_b, dout);
    }
    k_final<<<1, 256>>>(cs, dout);
}

// round 8
// speedup vs baseline: 2.3097x; 1.0731x over previous
#include <cuda_runtime.h>
#include <cuda_bf16.h>
#include <cuda_fp16.h>
#include <cstdint>
#include <cstddef>

// ---------------- problem constants ----------------
#define BB   16
#define DIN  1024
#define TT   1024
#define KK   8192
#define DCB  256
#define NTOK (BB * TT)          // 16384

// ---------------- output layout (tuple flattened, f32) ----------------
static constexpr size_t OFF_ZQ     = 0;
static constexpr size_t SZ_ZQ      = (size_t)BB * DIN * TT;
static constexpr size_t OFF_IDX    = OFF_ZQ + SZ_ZQ;
static constexpr size_t OFF_COMMIT = OFF_IDX + NTOK;
static constexpr size_t OFF_CBL    = OFF_COMMIT + BB;
static constexpr size_t OFF_DIST   = OFF_CBL + BB;
static constexpr size_t SZ_DIST    = (size_t)NTOK * KK;
static constexpr size_t OFF_PERP   = OFF_DIST + SZ_DIST;
static constexpr size_t OFF_ACT    = OFF_PERP + 1;

// ---------------- scratch (device globals) ----------------
__device__ float g_cbn   [KK * DCB];        // normalized codebook, row-major (refine)
__device__ float g_colsq [KK];              // ||cb_n||^2
__device__ float g_cbsq  [KK];              // ||cb||^2 raw
__device__ float g_cbinv [KK];              // 1/max(||cb||,eps)
__device__ float g_ze    [BB * DCB * TT];
__device__ float g_inv   [NTOK];
__device__ float g_rowsq [NTOK];            // ||enc_n||^2
__device__ float g_rowsq_raw[NTOK];         // ||z_e||^2 raw
__device__ float g_lossn [NTOK];
__device__ int   g_idx   [NTOK];
__device__ int   g_counts[KK];
__device__ float g_proj  [KK * DIN];

// split operands (16B aligned for cp.async)
__device__ __align__(16) __nv_bfloat16 g_a_hi[(size_t)NTOK * DCB];   // enc_n split hi (bf16)
__device__ __align__(16) __nv_bfloat16 g_a_lo[(size_t)NTOK * DCB];   // enc_n split lo (bf16)
__device__ __align__(16) __nv_bfloat16 g_b_hi[(size_t)KK * DCB];     // cb_n rounded (bf16)
__device__ __align__(16) __nv_bfloat16 g_cb_hi[(size_t)KK * DCB];    // raw cb split (bf16)
__device__ __align__(16) __nv_bfloat16 g_cb_lo[(size_t)KK * DCB];
__device__ __align__(16) __nv_bfloat16 g_wo_hi[(size_t)DIN * DCB];   // w_out split (bf16)
__device__ __align__(16) __nv_bfloat16 g_wo_lo[(size_t)DIN * DCB];
// fp16 split operands for z_e GEMM
__device__ __align__(16) __half g_wi_hi[(size_t)DCB * DIN];          // w_in split [c][k]
__device__ __align__(16) __half g_wi_lo[(size_t)DCB * DIN];
__device__ __align__(16) __half g_z_hi[(size_t)NTOK * DIN];          // z transposed [b][t][k]
__device__ __align__(16) __half g_z_lo[(size_t)NTOK * DIN];
// per-(token, 64-code tile) packed min (key<<32 | code), tile = k/64
__device__ unsigned long long g_tilemin[(size_t)NTOK * 128];

// ---------------- helpers ----------------
__device__ __forceinline__ uint32_t smem_u32(const void* p) {
    uint32_t a;
    asm("{ .reg .u64 t; cvta.to.shared.u64 t, %1; cvt.u32.u64 %0, t; }" : "=r"(a) : "l"(p));
    return a;
}
__device__ __forceinline__ void ldsm_x4(uint32_t* r, uint32_t a) {
    asm volatile("ldmatrix.sync.aligned.m8n8.x4.shared.b16 {%0,%1,%2,%3}, [%4];"
        : "=r"(r[0]), "=r"(r[1]), "=r"(r[2]), "=r"(r[3]) : "r"(a));
}
__device__ __forceinline__ void mma_bf16(float* d, const uint32_t* a, const uint32_t* b) {
    asm volatile("mma.sync.aligned.m16n8k16.row.col.f32.bf16.bf16.f32 "
        "{%0,%1,%2,%3}, {%4,%5,%6,%7}, {%8,%9}, {%0,%1,%2,%3};"
        : "+f"(d[0]), "+f"(d[1]), "+f"(d[2]), "+f"(d[3])
        : "r"(a[0]), "r"(a[1]), "r"(a[2]), "r"(a[3]), "r"(b[0]), "r"(b[1]));
}
__device__ __forceinline__ void mma_f16(float* d, const uint32_t* a, const uint32_t* b) {
    asm volatile("mma.sync.aligned.m16n8k16.row.col.f32.f16.f16.f32 "
        "{%0,%1,%2,%3}, {%4,%5,%6,%7}, {%8,%9}, {%0,%1,%2,%3};"
        : "+f"(d[0]), "+f"(d[1]), "+f"(d[2]), "+f"(d[3])
        : "r"(a[0]), "r"(a[1]), "r"(a[2]), "r"(a[3]), "r"(b[0]), "r"(b[1]));
}
#define CP_ASYNC16(dst, src) \
    asm volatile("cp.async.cg.shared.global [%0], [%1], 16;" :: "r"(dst), "l"(src) : "memory")
#define CP_COMMIT() asm volatile("cp.async.commit_group;" ::: "memory")
#define CP_WAIT1()  asm volatile("cp.async.wait_group 1;" ::: "memory")
#define CP_WAIT0()  asm volatile("cp.async.wait_group 0;" ::: "memory")

__device__ __forceinline__ unsigned fkey(float f) {
    unsigned u = __float_as_uint(f);
    return (u & 0x80000000u) ? ~u : (u | 0x80000000u);
}
__device__ __forceinline__ float funkey(unsigned k) {
    unsigned u = (k & 0x80000000u) ? (k ^ 0x80000000u) : ~k;
    return __uint_as_float(u);
}

// ---------------- prep A: w_in weight-norm -> fp16 split, row-major -------
__global__ void k_prep_win(const float* __restrict__ in_v, const float* __restrict__ in_g)
{
    int r   = blockIdx.x;                // 256 blocks
    int tid = threadIdx.x;
    const float* row = in_v + (size_t)r * DIN;
    float v4[4];
    float s = 0.f;
    #pragma unroll
    for (int i = 0; i < 4; i++) { v4[i] = row[tid * 4 + i]; s += v4[i] * v4[i]; }
    __shared__ float sm[256];
    sm[tid] = s; __syncthreads();
    #pragma unroll
    for (int off = 128; off; off >>= 1) {
        if (tid < off) sm[tid] += sm[tid + off];
        __syncthreads();
    }
    float scale = in_g[r] / sqrtf(sm[0]);
    __half2 h2a, h2b, l2a, l2b;
    float w0 = v4[0] * scale, w1 = v4[1] * scale, w2 = v4[2] * scale, w3 = v4[3] * scale;
    h2a = __floats2half2_rn(w0, w1);
    h2b = __floats2half2_rn(w2, w3);
    l2a = __floats2half2_rn(w0 - __half2float(h2a.x), w1 - __half2float(h2a.y));
    l2b = __floats2half2_rn(w2 - __half2float(h2b.x), w3 - __half2float(h2b.y));
    *(uint2*)(g_wi_hi + (size_t)r * DIN + tid * 4) =
        make_uint2(*(uint32_t*)&h2a, *(uint32_t*)&h2b);
    *(uint2*)(g_wi_lo + (size_t)r * DIN + tid * 4) =
        make_uint2(*(uint32_t*)&l2a, *(uint32_t*)&l2b);
}

// ---------------- z transpose + fp16 split:  [b][k][t] -> [b][t][k] -------
// grid (4, 32, 16): k0 = x*256, t0 = y*32, b = z
__global__ __launch_bounds__(256)
void k_zsplit(const float* __restrict__ z)
{
    __shared__ float tile[256][33];
    int k0 = blockIdx.x * 256;
    int t0 = blockIdx.y * 32;
    int b  = blockIdx.z;
    int tid = threadIdx.x;

    const float* zb = z + (size_t)b * DIN * TT + (size_t)k0 * TT + t0;
    #pragma unroll
    for (int i = 0; i < 32; i++) {
        int idx = tid + i * 256;
        int c = idx >> 5, t = idx & 31;
        tile[c][t] = zb[(size_t)c * TT + t];
    }
    __syncthreads();

    int j    = tid >> 3;               // token 0..31
    int part = tid & 7;                // 32-k slice
    uint32_t hw[16], lw[16];
    #pragma unroll
    for (int i = 0; i < 16; i++) {
        float v0 = tile[part * 32 + 2 * i][j];
        float v1 = tile[part * 32 + 2 * i + 1][j];
        __half2 h2 = __floats2half2_rn(v0, v1);
        __half2 l2 = __floats2half2_rn(v0 - __half2float(h2.x), v1 - __half2float(h2.y));
        hw[i] = *(uint32_t*)&h2;
        lw[i] = *(uint32_t*)&l2;
    }
    size_t base = ((size_t)b * TT + t0 + j) * DIN + k0 + part * 32;
    uint4* zh = (uint4*)(g_z_hi + base);
    uint4* zl = (uint4*)(g_z_lo + base);
    #pragma unroll
    for (int i = 0; i < 4; i++) {
        zh[i] = make_uint4(hw[4*i], hw[4*i+1], hw[4*i+2], hw[4*i+3]);
        zl[i] = make_uint4(lw[4*i], lw[4*i+1], lw[4*i+2], lw[4*i+3]);
    }
}

// ---------------- prep B: w_out + codebook norms & splits (stream 2) --------
__global__ void k_prep_cbwo(const float* __restrict__ out_v, const float* __restrict__ out_g,
                            const float* __restrict__ cb)
{
    int blk = blockIdx.x;
    int tid = threadIdx.x;
    __shared__ float sm[256];

    if (blk < 1024) {                                   // w_out: 1024 rows x 256
        int r = blk;
        const float* row = out_v + (size_t)r * DCB;
        float v = row[tid];
        sm[tid] = v * v; __syncthreads();
        #pragma unroll
        for (int off = 128; off; off >>= 1) {
            if (tid < off) sm[tid] += sm[tid + off];
            __syncthreads();
        }
        float scale = out_g[r] / sqrtf(sm[0]);
        float w = v * scale;
        __nv_bfloat16 hi = __float2bfloat16_rn(w);
        g_wo_hi[(size_t)r * DCB + tid] = hi;
        g_wo_lo[(size_t)r * DCB + tid] = __float2bfloat16_rn(w - __bfloat162float(hi));
    } else {                                            // codebook: 8192 rows x 256
        int r = blk - 1024;
        const float* row = cb + (size_t)r * DCB;
        float v = row[tid];
        sm[tid] = v * v; __syncthreads();
        #pragma unroll
        for (int off = 128; off; off >>= 1) {
            if (tid < off) sm[tid] += sm[tid + off];
            __syncthreads();
        }
        float sumsq = sm[0];
        float inv = 1.f / fmaxf(sqrtf(sumsq), 1e-12f);
        if (tid == 0) {
            g_colsq[r] = sumsq * inv * inv;
            g_cbsq[r]  = sumsq;
            g_cbinv[r] = inv;
            g_counts[r] = 0;
        }
        float vn = v * inv;
        g_cbn[(size_t)r * DCB + tid] = vn;
        g_b_hi[(size_t)r * DCB + tid] = __float2bfloat16_rn(vn);
        __nv_bfloat16 rh = __float2bfloat16_rn(v);
        g_cb_hi[(size_t)r * DCB + tid] = rh;
        g_cb_lo[(size_t)r * DCB + tid] = __float2bfloat16_rn(v - __bfloat162float(rh));
    }
}

// ---------------- per-token norms + bf16 split (coalesced) ----------------
__global__ __launch_bounds__(256)
void k_toknorm()
{
    __shared__ float tile[256][33];
    int blk = blockIdx.x;
    int b   = blk >> 5;
    int t0  = (blk & 31) << 5;
    int tid = threadIdx.x;

    const float* zb = g_ze + (size_t)b * DCB * TT + t0;
    #pragma unroll
    for (int i = 0; i < 32; i++) {
        int idx = tid + i * 256;
        int c = idx >> 5, t = idx & 31;
        tile[c][t] = zb[(size_t)c * TT + t];
    }
    __syncthreads();

    int j    = tid >> 3;
    int part = tid & 7;
    float s = 0.f;
    #pragma unroll
    for (int i = 0; i < 32; i++) {
        float v = tile[part * 32 + i][j];
        s += v * v;
    }
    s += __shfl_xor_sync(0xFFFFFFFFu, s, 4);
    s += __shfl_xor_sync(0xFFFFFFFFu, s, 2);
    s += __shfl_xor_sync(0xFFFFFFFFu, s, 1);
    float inv = 1.f / fmaxf(sqrtf(s), 1e-12f);

    int n = b * TT + t0 + j;
    if (part == 0) {
        g_inv[n] = inv;
        g_rowsq[n] = s * inv * inv;
        g_rowsq_raw[n] = s;
    }

    uint32_t hw[16], lw[16];
    #pragma unroll
    for (int i = 0; i < 16; i++) {
        float v0 = tile[part * 32 + 2 * i][j] * inv;
        float v1 = tile[part * 32 + 2 * i + 1][j] * inv;
        __nv_bfloat162 h2 = __floats2bfloat162_rn(v0, v1);
        float l0 = v0 - __bfloat162float(h2.x);
        float l1 = v1 - __bfloat162float(h2.y);
        __nv_bfloat162 l2 = __floats2bfloat162_rn(l0, l1);
        hw[i] = *(uint32_t*)&h2;
        lw[i] = *(uint32_t*)&l2;
    }
    uint4* ah = (uint4*)(g_a_hi + (size_t)n * DCB + part * 32);
    uint4* al = (uint4*)(g_a_lo + (size_t)n * DCB + part * 32);
    #pragma unroll
    for (int i = 0; i < 4; i++) {
        ah[i] = make_uint4(hw[4*i], hw[4*i+1], hw[4*i+2], hw[4*i+3]);
        al[i] = make_uint4(lw[4*i], lw[4*i+1], lw[4*i+2], lw[4*i+3]);
    }
}

// ---------------- HMMA GEMM tiles ----------------
static constexpr int ROWB      = 80;
static constexpr int MAT_BYTES = 128 * ROWB;          // 10240
static constexpr int STAGE3    = 3 * MAT_BYTES;       // dist: Ahi, Alo, Bhi
static constexpr int STAGE4    = 4 * MAT_BYTES;       // 3-pass: Ahi, Alo, Bhi, Blo
static constexpr int COLSQ_OFF = 3 * STAGE3;          // 92160
static constexpr int SMEM_DIST = COLSQ_OFF + 128 * 4; // 92672
static constexpr int SMEM_P4   = 2 * STAGE4;          // 81920

// dist loader: 3 matrices (Ahi, Alo, Bhi), K stride 256
__device__ __forceinline__ void load_chunk3(uint32_t sbase, int stage, int kc,
                                            int m0, int n0, int tid)
{
    uint32_t st = sbase + stage * STAGE3;
    #pragma unroll
    for (int i = 0; i < 6; i++) {
        int lin = tid + i * 256;            // 0..1535
        int mat = lin >> 9;                 // 0..2
        int r   = (lin >> 2) & 127;
        int c   = lin & 3;
        uint32_t dst = st + mat * MAT_BYTES + (uint32_t)(r * ROWB + c * 16);
        size_t off = ((size_t)((mat < 2 ? m0 : n0) + r) * DCB + kc * 32) * 2 + c * 16;
        const char* src;
        if      (mat == 0) src = (const char*)g_a_hi + off;
        else if (mat == 1) src = (const char*)g_a_lo + off;
        else               src = (const char*)g_b_hi + off;
        CP_ASYNC16(dst, src);
    }
    CP_COMMIT();
}

__global__ __launch_bounds__(256, 2)
void k_dist(float* __restrict__ dout)
{
    extern __shared__ __align__(16) char smem_raw[];
    uint32_t sbase = smem_u32(smem_raw);
    float* colsq_s = (float*)(smem_raw + COLSQ_OFF);

    int tid  = threadIdx.x;
    int wid  = tid >> 5;
    int lane = tid & 31;
    int wm   = wid >> 1;
    int wn   = wid & 1;
    int n0   = blockIdx.x * 128;
    int m0   = blockIdx.y * 128;

    if (tid < 128) colsq_s[tid] = g_colsq[n0 + tid];

    float acc[2][8][4];
    #pragma unroll
    for (int mt = 0; mt < 2; mt++)
        #pragma unroll
        for (int nt = 0; nt < 8; nt++)
            #pragma unroll
            for (int j = 0; j < 4; j++) acc[mt][nt][j] = 0.f;

    load_chunk3(sbase, 0, 0, m0, n0, tid);
    load_chunk3(sbase, 1, 1, m0, n0, tid);

    int arow  = wm * 32 + (lane & 15);
    int acolh = (lane >> 4) * 16;
    int brow  = wn * 64 + ((lane >> 4) << 3) + (lane & 7);
    int bcolh = ((lane >> 3) & 1) * 16;

    int stage = 0;
    for (int kc = 0; kc < 8; kc++) {
        if (kc < 7) { CP_WAIT1(); } else { CP_WAIT0(); }
        __syncthreads();
        if (kc + 2 < 8) {
            int nstage = stage + 2; if (nstage >= 3) nstage -= 3;
            load_chunk3(sbase, nstage, kc + 2, m0, n0, tid);
        }

        uint32_t sa_hi = sbase + stage * STAGE3;
        uint32_t sa_lo = sa_hi + MAT_BYTES;
        uint32_t sb_hi = sa_hi + 2 * MAT_BYTES;

        #pragma unroll
        for (int s = 0; s < 2; s++) {
            int acol = s * 32 + acolh;
            uint32_t Ahf[2][4], Alf[2][4];
            ldsm_x4(Ahf[0], sa_hi + (uint32_t)(arow * ROWB + acol));
            ldsm_x4(Ahf[1], sa_hi + (uint32_t)((arow + 16) * ROWB + acol));
            ldsm_x4(Alf[0], sa_lo + (uint32_t)(arow * ROWB + acol));
            ldsm_x4(Alf[1], sa_lo + (uint32_t)((arow + 16) * ROWB + acol));
            int bcol = s * 32 + bcolh;
            #pragma unroll
            for (int np = 0; np < 4; np++) {
                uint32_t Bhf[4];
                uint32_t ba = (uint32_t)((brow + np * 16) * ROWB + bcol);
                ldsm_x4(Bhf, sb_hi + ba);
                #pragma unroll
                for (int mt = 0; mt < 2; mt++) {
                    mma_bf16(acc[mt][2 * np],     Ahf[mt], Bhf);
                    mma_bf16(acc[mt][2 * np],     Alf[mt], Bhf);
                    mma_bf16(acc[mt][2 * np + 1], Ahf[mt], Bhf + 2);
                    mma_bf16(acc[mt][2 * np + 1], Alf[mt], Bhf + 2);
                }
            }
        }
        stage = (stage + 1 == 3) ? 0 : stage + 1;
    }

    int q  = lane >> 2;
    int qq = lane & 3;
    int tileg = blockIdx.x * 2 + wn;
    #pragma unroll
    for (int mt = 0; mt < 2; mt++) {
        int RB = m0 + wm * 32 + mt * 16;
        #pragma unroll
        for (int h = 0; h < 2; h++) {
            int row = RB + h * 8 + q;
            float rsq = g_rowsq[row];
            float* dw = dout + OFF_DIST + (size_t)row * KK + n0;
            unsigned bkey = 0xFFFFFFFFu, bcode = 0;
            #pragma unroll
            for (int nt = 0; nt < 8; nt++) {
                int c0 = wn * 64 + nt * 8 + qq * 2;
                float d0 = rsq + colsq_s[c0]     - 2.f * acc[mt][nt][h * 2 + 0];
                float d1 = rsq + colsq_s[c0 + 1] - 2.f * acc[mt][nt][h * 2 + 1];
                *(float2*)(dw + c0) = make_float2(d0, d1);
                unsigned k0 = fkey(d0), k1 = fkey(d1);
                if (k0 < bkey) { bkey = k0; bcode = (unsigned)(n0 + c0); }
                if (k1 < bkey) { bkey = k1; bcode = (unsigned)(n0 + c0 + 1); }
            }
            unsigned long long p = ((unsigned long long)bkey << 32) | bcode;
            unsigned long long o;
            o = __shfl_xor_sync(0xFFFFFFFFu, p, 1); if (o < p) p = o;
            o = __shfl_xor_sync(0xFFFFFFFFu, p, 2); if (o < p) p = o;
            if (qq == 0) g_tilemin[(size_t)row * 128 + tileg] = p;
        }
    }
}

// ---------------- generic 4-matrix 3-pass HMMA mainloop ----------------
template<int KDIM>
__device__ __forceinline__ void load_chunk4T(uint32_t sbase, int stage, int kc,
                                             int m0, int n0, int tid,
                                             const void* Ah, const void* Al,
                                             const void* Bh, const void* Bl)
{
    uint32_t st = sbase + stage * STAGE4;
    #pragma unroll
    for (int i = 0; i < 8; i++) {
        int lin = tid + i * 256;
        int mat = lin >> 9;
        int r   = (lin >> 2) & 127;
        int c   = lin & 3;
        uint32_t dst = st + mat * MAT_BYTES + (uint32_t)(r * ROWB + c * 16);
        size_t off = ((size_t)((mat < 2 ? m0 : n0) + r) * KDIM + kc * 32) * 2 + c * 16;
        const char* src;
        if      (mat == 0) src = (const char*)Ah + off;
        else if (mat == 1) src = (const char*)Al + off;
        else if (mat == 2) src = (const char*)Bh + off;
        else               src = (const char*)Bl + off;
        CP_ASYNC16(dst, src);
    }
    CP_COMMIT();
}

template<int KDIM, bool HALF>
__device__ __forceinline__ void hmma4_loop(uint32_t sbase, int m0, int n0, int tid,
                                           const void* Ah, const void* Al,
                                           const void* Bh, const void* Bl,
                                           float acc[2][8][4])
{
    int wid  = tid >> 5;
    int lane = tid & 31;
    int wm   = wid >> 1;
    int wn   = wid & 1;

    load_chunk4T<KDIM>(sbase, 0, 0, m0, n0, tid, Ah, Al, Bh, Bl);

    int arow  = wm * 32 + (lane & 15);
    int acolh = (lane >> 4) * 16;
    int brow  = wn * 64 + ((lane >> 4) << 3) + (lane & 7);
    int bcolh = ((lane >> 3) & 1) * 16;

    constexpr int NCH = KDIM / 32;
    for (int kc = 0; kc < NCH; kc++) {
        int st = kc & 1;
        if (kc < NCH - 1) load_chunk4T<KDIM>(sbase, st ^ 1, kc + 1, m0, n0, tid, Ah, Al, Bh, Bl);
        if (kc < NCH - 1) { CP_WAIT1(); } else { CP_WAIT0(); }
        __syncthreads();

        uint32_t sa_hi = sbase + st * STAGE4;
        uint32_t sa_lo = sa_hi + MAT_BYTES;
        uint32_t sb_hi = sa_hi + 2 * MAT_BYTES;
        uint32_t sb_lo = sa_hi + 3 * MAT_BYTES;

        #pragma unroll
        for (int s = 0; s < 2; s++) {
            int acol = s * 32 + acolh;
            uint32_t Ahf[2][4], Alf[2][4];
            ldsm_x4(Ahf[0], sa_hi + (uint32_t)(arow * ROWB + acol));
            ldsm_x4(Ahf[1], sa_hi + (uint32_t)((arow + 16) * ROWB + acol));
            ldsm_x4(Alf[0], sa_lo + (uint32_t)(arow * ROWB + acol));
            ldsm_x4(Alf[1], sa_lo + (uint32_t)((arow + 16) * ROWB + acol));
            int bcol = s * 32 + bcolh;
            #pragma unroll
            for (int np = 0; np < 4; np++) {
                uint32_t Bhf[4], Blf[4];
                uint32_t ba = (uint32_t)((brow + np * 16) * ROWB + bcol);
                ldsm_x4(Bhf, sb_hi + ba);
                ldsm_x4(Blf, sb_lo + ba);
                #pragma unroll
                for (int mt = 0; mt < 2; mt++) {
                    if (HALF) {
                        mma_f16(acc[mt][2 * np],     Ahf[mt], Bhf);
                        mma_f16(acc[mt][2 * np],     Ahf[mt], Blf);
                        mma_f16(acc[mt][2 * np],     Alf[mt], Bhf);
                        mma_f16(acc[mt][2 * np + 1], Ahf[mt], Bhf + 2);
                        mma_f16(acc[mt][2 * np + 1], Ahf[mt], Blf + 2);
                        mma_f16(acc[mt][2 * np + 1], Alf[mt], Bhf + 2);
                    } else {
                        mma_bf16(acc[mt][2 * np],     Ahf[mt], Bhf);
                        mma_bf16(acc[mt][2 * np],     Ahf[mt], Blf);
                        mma_bf16(acc[mt][2 * np],     Alf[mt], Bhf);
                        mma_bf16(acc[mt][2 * np + 1], Ahf[mt], Bhf + 2);
                        mma_bf16(acc[mt][2 * np + 1], Ahf[mt], Blf + 2);
                        mma_bf16(acc[mt][2 * np + 1], Alf[mt], Bhf + 2);
                    }
                }
            }
        }
        __syncthreads();
    }
}

// proj = cb @ w_out^T   (M=8192, N=1024, K=256, bf16 3-pass)
__global__ __launch_bounds__(256, 2)
void k_proj()
{
    extern __shared__ __align__(16) char smem_raw[];
    uint32_t sbase = smem_u32(smem_raw);

    int tid  = threadIdx.x;
    int wid  = tid >> 5;
    int lane = tid & 31;
    int wm   = wid >> 1;
    int wn   = wid & 1;
    int n0   = blockIdx.x * 128;
    int m0   = blockIdx.y * 128;

    float acc[2][8][4];
    #pragma unroll
    for (int mt = 0; mt < 2; mt++)
        #pragma unroll
        for (int nt = 0; nt < 8; nt++)
            #pragma unroll
            for (int j = 0; j < 4; j++) acc[mt][nt][j] = 0.f;

    hmma4_loop<DCB, false>(sbase, m0, n0, tid, g_cb_hi, g_cb_lo, g_wo_hi, g_wo_lo, acc);

    int q  = lane >> 2;
    int qq = lane & 3;
    #pragma unroll
    for (int mt = 0; mt < 2; mt++) {
        int RB = m0 + wm * 32 + mt * 16;
        #pragma unroll
        for (int h = 0; h < 2; h++) {
            int row = RB + h * 8 + q;
            float* pw = g_proj + (size_t)row * DIN + n0;
            #pragma unroll
            for (int nt = 0; nt < 8; nt++) {
                int c0 = wn * 64 + nt * 8 + qq * 2;
                *(float2*)(pw + c0) = make_float2(acc[mt][nt][h * 2 + 0],
                                                  acc[mt][nt][h * 2 + 1]);
            }
        }
    }
}

// z_e = w_in @ z + in_b  (M=256 ch, N=1024 tok/batch, K=1024, fp16 3-pass)
__global__ __launch_bounds__(256, 2)
void k_zein(const float* __restrict__ bias)
{
    extern __shared__ __align__(16) char smem_raw[];
    uint32_t sbase = smem_u32(smem_raw);

    int tid  = threadIdx.x;
    int wid  = tid >> 5;
    int lane = tid & 31;
    int wm   = wid >> 1;
    int wn   = wid & 1;
    int n0   = blockIdx.x * 128;     // token within batch
    int m0   = blockIdx.y * 128;     // channel
    int b    = blockIdx.z;

    const __half* zh = g_z_hi + (size_t)b * TT * DIN;
    const __half* zl = g_z_lo + (size_t)b * TT * DIN;

    float acc[2][8][4];
    #pragma unroll
    for (int mt = 0; mt < 2; mt++)
        #pragma unroll
        for (int nt = 0; nt < 8; nt++)
            #pragma unroll
            for (int j = 0; j < 4; j++) acc[mt][nt][j] = 0.f;

    hmma4_loop<DIN, true>(sbase, m0, n0, tid, g_wi_hi, g_wi_lo, zh, zl, acc);

    int q  = lane >> 2;
    int qq = lane & 3;
    float* C = g_ze + (size_t)b * DCB * TT;
    #pragma unroll
    for (int mt = 0; mt < 2; mt++) {
        int RB = m0 + wm * 32 + mt * 16;
        #pragma unroll
        for (int h = 0; h < 2; h++) {
            int row = RB + h * 8 + q;
            float bb = bias[row];
            float* cw = C + (size_t)row * TT + n0;
            #pragma unroll
            for (int nt = 0; nt < 8; nt++) {
                int c0 = wn * 64 + nt * 8 + qq * 2;
                *(float2*)(cw + c0) = make_float2(acc[mt][nt][h * 2 + 0] + bb,
                                                  acc[mt][nt][h * 2 + 1] + bb);
            }
        }
    }
}

// ---------------- argmin refinement (near-exact fp32) + fused loss ----------
__global__ void k_refine(float* __restrict__ dout)
{
    int warp = threadIdx.x >> 5;
    int lane = threadIdx.x & 31;
    int n = blockIdx.x * 8 + warp;

    const unsigned long long* tm = g_tilemin + (size_t)n * 128;
    unsigned long long best = tm[lane];
    {
        unsigned long long v;
        v = tm[lane + 32]; if (v < best) best = v;
        v = tm[lane + 64]; if (v < best) best = v;
        v = tm[lane + 96]; if (v < best) best = v;
        #pragma unroll
        for (int off = 16; off; off >>= 1) {
            unsigned long long o = __shfl_xor_sync(0xFFFFFFFFu, best, off);
            if (o < best) best = o;
        }
    }
    float dmin = funkey((unsigned)(best >> 32));
    float thresh = dmin + 4e-3f;

    float inv = g_inv[n];
    float rsq = g_rowsq[n];
    float ev[8];
    {
        const __nv_bfloat16* ah = g_a_hi + (size_t)n * DCB + lane * 8;
        const __nv_bfloat16* al = g_a_lo + (size_t)n * DCB + lane * 8;
        #pragma unroll
        for (int j = 0; j < 8; j++)
            ev[j] = __bfloat162float(ah[j]) + __bfloat162float(al[j]);
    }

    const float* distrow = dout + OFF_DIST + (size_t)n * KK;

    float bestd = 3.4e38f;
    int   bestk = KK;
    float bestpart = 0.f;

    for (int ti = 0; ti < 128; ti++) {
        float tmin = funkey((unsigned)(tm[ti] >> 32));
        if (tmin > thresh) continue;
        int k0 = ti * 64;
        float d0 = distrow[k0 + lane];
        float d1 = distrow[k0 + 32 + lane];
        #pragma unroll
        for (int half = 0; half < 2; half++) {
            float dv = (half == 0) ? d0 : d1;
            unsigned mask = __ballot_sync(0xFFFFFFFFu, dv <= thresh);
            while (mask) {
                int j = __ffs(mask) - 1;
                mask &= mask - 1;
                int k = k0 + half * 32 + j;
                const float* cr = g_cbn + (size_t)k * DCB + lane * 8;
                float part = 0.f;
                #pragma unroll
                for (int qv = 0; qv < 8; qv++)
                    part += ev[qv] * cr[qv];
                #pragma unroll
                for (int off = 16; off; off >>= 1)
                    part += __shfl_xor_sync(0xFFFFFFFFu, part, off);
                float de = rsq + g_colsq[k] - 2.f * part;
                if (de < bestd || (de == bestd && k < bestk)) {
                    bestd = de; bestk = k; bestpart = part;
                }
            }
        }
    }

    if (lane == 0) {
        g_idx[n] = bestk;
        dout[OFF_IDX + n] = (float)bestk;
        atomicAdd(&g_counts[bestk], 1);
        float dot_raw = bestpart / (inv * g_cbinv[bestk]);
        g_lossn[n] = g_rowsq_raw[n] + g_cbsq[bestk] - 2.f * dot_raw;
    }
}

// ---------------- z_q_out gather ----------------
__global__ void k_gather(const float* __restrict__ outb, float* __restrict__ dout)
{
    int t  = blockIdx.x * 256 + threadIdx.x;
    int o4 = blockIdx.y * 4;
    int b  = blockIdx.z;
    int idx = g_idx[b * TT + t];
    float4 v = *(const float4*)(g_proj + (size_t)idx * DIN + o4);
    size_t base = OFF_ZQ + (size_t)b * DIN * TT + (size_t)o4 * TT + t;
    dout[base]          = v.x + outb[o4];
    dout[base + TT]     = v.y + outb[o4 + 1];
    dout[base + 2 * TT] = v.z + outb[o4 + 2];
    dout[base + 3 * TT] = v.w + outb[o4 + 3];
}

// ---------------- scalars: losses, perplexity, active ----------------
__global__ void k_final(const float* __restrict__ cs, float* __restrict__ dout)
{
    int tid = threadIdx.x;
    __shared__ float lsum[256];
    {
        int bb = tid >> 4;
        int sl = tid & 15;
        float s = 0.f;
        #pragma unroll 4
        for (int i = 0; i < 64; i++)
            s += g_lossn[bb * TT + sl + i * 16];
        lsum[tid] = s;
    }
    __syncthreads();
    if (tid < BB) {
        float s = 0.f;
        #pragma unroll
        for (int i = 0; i < 16; i++) s += lsum[tid * 16 + i];
        float mean = s / (float)(DCB * TT);
        dout[OFF_COMMIT + tid] = mean * 0.15f;
        dout[OFF_CBL + tid]    = mean;
    }

    float ent = 0.f;
    int   act = 0;
    for (int k = tid; k < KK; k += 256) {
        float cnt = (float)g_counts[k];
        float p   = cnt / (float)NTOK;
        ent += p * logf(p + 1e-10f);
        float ncs = cs[k] * 0.99f + cnt * 0.01f;
        if (ncs > 2.0f) act++;
    }
    __shared__ float se[256];
    __shared__ int   sa[256];
    se[tid] = ent; sa[tid] = act; __syncthreads();
    #pragma unroll
    for (int off = 128; off; off >>= 1) {
        if (tid < off) { se[tid] += se[tid + off]; sa[tid] += sa[tid + off]; }
        __syncthreads();
    }
    if (tid == 0) {
        dout[OFF_PERP] = expf(-se[0]);
        dout[OFF_ACT]  = (float)sa[0];
    }
}

// ---------------- launch (fork-join) ----------------
extern "C" void kernel_launch(void* const* d_in, const int* in_sizes, int n_in,
                              void* d_out, int out_size)
{
    const float* z     = (const float*)d_in[0];
    const float* in_g  = (const float*)d_in[1];
    const float* in_v  = (const float*)d_in[2];
    const float* in_b  = (const float*)d_in[3];
    const float* out_g = (const float*)d_in[4];
    const float* out_v = (const float*)d_in[5];
    const float* out_b = (const float*)d_in[6];
    const float* cb    = (const float*)d_in[7];
    const float* cs    = (const float*)d_in[8];
    float* dout = (float*)d_out;

    static cudaStream_t s2 = nullptr;
    static cudaEvent_t  evF = nullptr, evJ = nullptr;
    if (!s2) {
        cudaStreamCreateWithFlags(&s2, cudaStreamNonBlocking);
        cudaEventCreateWithFlags(&evF, cudaEventDisableTiming);
        cudaEventCreateWithFlags(&evJ, cudaEventDisableTiming);
        cudaFuncSetAttribute(k_dist, cudaFuncAttributeMaxDynamicSharedMemorySize, SMEM_DIST);
        cudaFuncSetAttribute(k_proj, cudaFuncAttributeMaxDynamicSharedMemorySize, SMEM_P4);
        cudaFuncSetAttribute(k_zein, cudaFuncAttributeMaxDynamicSharedMemorySize, SMEM_P4);
    }

    // fork: stream2 does codebook/w_out prep + proj GEMM
    cudaEventRecord(evF, 0);
    cudaStreamWaitEvent(s2, evF, 0);
    k_prep_cbwo<<<1024 + KK, 256, 0, s2>>>(out_v, out_g, cb);
    {
        dim3 grid(DIN / 128, KK / 128, 1);
        k_proj<<<grid, 256, SMEM_P4, s2>>>();
    }
    cudaEventRecord(evJ, s2);

    // main chain
    k_prep_win<<<256, 256>>>(in_v, in_g);
    {
        dim3 grid(4, 32, BB);
        k_zsplit<<<grid, 256>>>(z);
    }
    {
        dim3 grid(TT / 128, DCB / 128, BB);
        k_zein<<<grid, 256, SMEM_P4>>>(in_b);
    }
    k_toknorm<<<NTOK / 32, 256>>>();

    // join
    cudaStreamWaitEvent(0, evJ, 0);

    {
        dim3 grid(KK / 128, NTOK / 128, 1);
        k_dist<<<grid, 256, SMEM_DIST>>>(dout);
    }
    k_refine<<<NTOK / 8, 256>>>(dout);
    {
        dim3 grid(4, 256, BB);
        k_gather<<<grid, 256>>>(out_b, dout);
    }
    k_final<<<1, 256>>>(cs, dout);
}

// round 13
// speedup vs baseline: 3.0180x; 1.3067x over previous
#include <cuda_runtime.h>
#include <cuda_bf16.h>
#include <cuda_fp16.h>
#include <cstdint>
#include <cstddef>

// ---------------- problem constants ----------------
#define BB   16
#define DIN  1024
#define TT   1024
#define KK   8192
#define DCB  256
#define NTOK (BB * TT)          // 16384

// ---------------- output layout (tuple flattened, f32) ----------------
static constexpr size_t OFF_ZQ     = 0;
static constexpr size_t SZ_ZQ      = (size_t)BB * DIN * TT;
static constexpr size_t OFF_IDX    = OFF_ZQ + SZ_ZQ;
static constexpr size_t OFF_COMMIT = OFF_IDX + NTOK;
static constexpr size_t OFF_CBL    = OFF_COMMIT + BB;
static constexpr size_t OFF_DIST   = OFF_CBL + BB;
static constexpr size_t SZ_DIST    = (size_t)NTOK * KK;
static constexpr size_t OFF_PERP   = OFF_DIST + SZ_DIST;
static constexpr size_t OFF_ACT    = OFF_PERP + 1;

// ---------------- scratch (device globals) ----------------
__device__ float g_cbn   [KK * DCB];        // normalized codebook, row-major (refine)
__device__ float g_colsq [KK];              // ||cb_n||^2
__device__ float g_cbsq  [KK];              // ||cb||^2 raw
__device__ float g_cbinv [KK];              // 1/max(||cb||,eps)
__device__ float g_ze    [BB * DCB * TT];
__device__ float g_inv   [NTOK];
__device__ float g_rowsq [NTOK];            // ||enc_n||^2
__device__ float g_rowsq_raw[NTOK];         // ||z_e||^2 raw
__device__ float g_lossn [NTOK];
__device__ int   g_idx   [NTOK];
__device__ int   g_counts[KK];
__device__ float g_proj  [KK * DIN];

// split operands (16B aligned for cp.async)
__device__ __align__(16) __nv_bfloat16 g_a_hi[(size_t)NTOK * DCB];   // enc_n rounded (bf16)
__device__ __align__(16) __nv_bfloat16 g_a_lo[(size_t)NTOK * DCB];   // enc_n residual (refine reconstruct)
__device__ __align__(16) __nv_bfloat16 g_b_hi[(size_t)KK * DCB];     // cb_n rounded (bf16)
__device__ __align__(16) __nv_bfloat16 g_cb_hi[(size_t)KK * DCB];    // raw cb split (bf16)
__device__ __align__(16) __nv_bfloat16 g_cb_lo[(size_t)KK * DCB];
__device__ __align__(16) __nv_bfloat16 g_wo_hi[(size_t)DIN * DCB];   // w_out split (bf16)
__device__ __align__(16) __nv_bfloat16 g_wo_lo[(size_t)DIN * DCB];
// fp16 split operands for z_e GEMM
__device__ __align__(16) __half g_wi_hi[(size_t)DCB * DIN];          // w_in split [c][k]
__device__ __align__(16) __half g_wi_lo[(size_t)DCB * DIN];
__device__ __align__(16) __half g_z_hi[(size_t)NTOK * DIN];          // z transposed [b][t][k]
__device__ __align__(16) __half g_z_lo[(size_t)NTOK * DIN];
// per-(token, 64-code tile) packed min (key<<32 | code), tile = k/64
__device__ unsigned long long g_tilemin[(size_t)NTOK * 128];

// ---------------- helpers ----------------
__device__ __forceinline__ uint32_t smem_u32(const void* p) {
    uint32_t a;
    asm("{ .reg .u64 t; cvta.to.shared.u64 t, %1; cvt.u32.u64 %0, t; }" : "=r"(a) : "l"(p));
    return a;
}
__device__ __forceinline__ void ldsm_x4(uint32_t* r, uint32_t a) {
    asm volatile("ldmatrix.sync.aligned.m8n8.x4.shared.b16 {%0,%1,%2,%3}, [%4];"
        : "=r"(r[0]), "=r"(r[1]), "=r"(r[2]), "=r"(r[3]) : "r"(a));
}
__device__ __forceinline__ void mma_bf16(float* d, const uint32_t* a, const uint32_t* b) {
    asm volatile("mma.sync.aligned.m16n8k16.row.col.f32.bf16.bf16.f32 "
        "{%0,%1,%2,%3}, {%4,%5,%6,%7}, {%8,%9}, {%0,%1,%2,%3};"
        : "+f"(d[0]), "+f"(d[1]), "+f"(d[2]), "+f"(d[3])
        : "r"(a[0]), "r"(a[1]), "r"(a[2]), "r"(a[3]), "r"(b[0]), "r"(b[1]));
}
__device__ __forceinline__ void mma_f16(float* d, const uint32_t* a, const uint32_t* b) {
    asm volatile("mma.sync.aligned.m16n8k16.row.col.f32.f16.f16.f32 "
        "{%0,%1,%2,%3}, {%4,%5,%6,%7}, {%8,%9}, {%0,%1,%2,%3};"
        : "+f"(d[0]), "+f"(d[1]), "+f"(d[2]), "+f"(d[3])
        : "r"(a[0]), "r"(a[1]), "r"(a[2]), "r"(a[3]), "r"(b[0]), "r"(b[1]));
}
#define CP_ASYNC16(dst, src) \
    asm volatile("cp.async.cg.shared.global [%0], [%1], 16;" :: "r"(dst), "l"(src) : "memory")
#define CP_COMMIT() asm volatile("cp.async.commit_group;" ::: "memory")
#define CP_WAIT1()  asm volatile("cp.async.wait_group 1;" ::: "memory")
#define CP_WAIT0()  asm volatile("cp.async.wait_group 0;" ::: "memory")

__device__ __forceinline__ unsigned fkey(float f) {
    unsigned u = __float_as_uint(f);
    return (u & 0x80000000u) ? ~u : (u | 0x80000000u);
}
__device__ __forceinline__ float funkey(unsigned k) {
    unsigned u = (k & 0x80000000u) ? (k ^ 0x80000000u) : ~k;
    return __uint_as_float(u);
}

// ---------------- prep A: w_in weight-norm -> fp16 split, row-major -------
__global__ void k_prep_win(const float* __restrict__ in_v, const float* __restrict__ in_g)
{
    int r   = blockIdx.x;                // 256 blocks
    int tid = threadIdx.x;
    const float* row = in_v + (size_t)r * DIN;
    float v4[4];
    float s = 0.f;
    #pragma unroll
    for (int i = 0; i < 4; i++) { v4[i] = row[tid * 4 + i]; s += v4[i] * v4[i]; }
    __shared__ float sm[256];
    sm[tid] = s; __syncthreads();
    #pragma unroll
    for (int off = 128; off; off >>= 1) {
        if (tid < off) sm[tid] += sm[tid + off];
        __syncthreads();
    }
    float scale = in_g[r] / sqrtf(sm[0]);
    __half2 h2a, h2b, l2a, l2b;
    float w0 = v4[0] * scale, w1 = v4[1] * scale, w2 = v4[2] * scale, w3 = v4[3] * scale;
    h2a = __floats2half2_rn(w0, w1);
    h2b = __floats2half2_rn(w2, w3);
    l2a = __floats2half2_rn(w0 - __half2float(h2a.x), w1 - __half2float(h2a.y));
    l2b = __floats2half2_rn(w2 - __half2float(h2b.x), w3 - __half2float(h2b.y));
    *(uint2*)(g_wi_hi + (size_t)r * DIN + tid * 4) =
        make_uint2(*(uint32_t*)&h2a, *(uint32_t*)&h2b);
    *(uint2*)(g_wi_lo + (size_t)r * DIN + tid * 4) =
        make_uint2(*(uint32_t*)&l2a, *(uint32_t*)&l2b);
}

// ---------------- z transpose + fp16 split:  [b][k][t] -> [b][t][k] -------
__global__ __launch_bounds__(256)
void k_zsplit(const float* __restrict__ z)
{
    __shared__ float tile[256][33];
    int k0 = blockIdx.x * 256;
    int t0 = blockIdx.y * 32;
    int b  = blockIdx.z;
    int tid = threadIdx.x;

    const float* zb = z + (size_t)b * DIN * TT + (size_t)k0 * TT + t0;
    #pragma unroll
    for (int i = 0; i < 32; i++) {
        int idx = tid + i * 256;
        int c = idx >> 5, t = idx & 31;
        tile[c][t] = zb[(size_t)c * TT + t];
    }
    __syncthreads();

    int j    = tid >> 3;               // token 0..31
    int part = tid & 7;                // 32-k slice
    uint32_t hw[16], lw[16];
    #pragma unroll
    for (int i = 0; i < 16; i++) {
        float v0 = tile[part * 32 + 2 * i][j];
        float v1 = tile[part * 32 + 2 * i + 1][j];
        __half2 h2 = __floats2half2_rn(v0, v1);
        __half2 l2 = __floats2half2_rn(v0 - __half2float(h2.x), v1 - __half2float(h2.y));
        hw[i] = *(uint32_t*)&h2;
        lw[i] = *(uint32_t*)&l2;
    }
    size_t base = ((size_t)b * TT + t0 + j) * DIN + k0 + part * 32;
    uint4* zh = (uint4*)(g_z_hi + base);
    uint4* zl = (uint4*)(g_z_lo + base);
    #pragma unroll
    for (int i = 0; i < 4; i++) {
        zh[i] = make_uint4(hw[4*i], hw[4*i+1], hw[4*i+2], hw[4*i+3]);
        zl[i] = make_uint4(lw[4*i], lw[4*i+1], lw[4*i+2], lw[4*i+3]);
    }
}

// ---------------- prep B: w_out + codebook norms & splits (stream 2) --------
__global__ void k_prep_cbwo(const float* __restrict__ out_v, const float* __restrict__ out_g,
                            const float* __restrict__ cb)
{
    int blk = blockIdx.x;
    int tid = threadIdx.x;
    __shared__ float sm[256];

    if (blk < 1024) {                                   // w_out: 1024 rows x 256
        int r = blk;
        const float* row = out_v + (size_t)r * DCB;
        float v = row[tid];
        sm[tid] = v * v; __syncthreads();
        #pragma unroll
        for (int off = 128; off; off >>= 1) {
            if (tid < off) sm[tid] += sm[tid + off];
            __syncthreads();
        }
        float scale = out_g[r] / sqrtf(sm[0]);
        float w = v * scale;
        __nv_bfloat16 hi = __float2bfloat16_rn(w);
        g_wo_hi[(size_t)r * DCB + tid] = hi;
        g_wo_lo[(size_t)r * DCB + tid] = __float2bfloat16_rn(w - __bfloat162float(hi));
    } else {                                            // codebook: 8192 rows x 256
        int r = blk - 1024;
        const float* row = cb + (size_t)r * DCB;
        float v = row[tid];
        sm[tid] = v * v; __syncthreads();
        #pragma unroll
        for (int off = 128; off; off >>= 1) {
            if (tid < off) sm[tid] += sm[tid + off];
            __syncthreads();
        }
        float sumsq = sm[0];
        float inv = 1.f / fmaxf(sqrtf(sumsq), 1e-12f);
        if (tid == 0) {
            g_colsq[r] = sumsq * inv * inv;
            g_cbsq[r]  = sumsq;
            g_cbinv[r] = inv;
            g_counts[r] = 0;
        }
        float vn = v * inv;
        g_cbn[(size_t)r * DCB + tid] = vn;
        g_b_hi[(size_t)r * DCB + tid] = __float2bfloat16_rn(vn);
        __nv_bfloat16 rh = __float2bfloat16_rn(v);
        g_cb_hi[(size_t)r * DCB + tid] = rh;
        g_cb_lo[(size_t)r * DCB + tid] = __float2bfloat16_rn(v - __bfloat162float(rh));
    }
}

// ---------------- per-token norms + bf16 split (coalesced) ----------------
__global__ __launch_bounds__(256)
void k_toknorm()
{
    __shared__ float tile[256][33];
    int blk = blockIdx.x;
    int b   = blk >> 5;
    int t0  = (blk & 31) << 5;
    int tid = threadIdx.x;

    const float* zb = g_ze + (size_t)b * DCB * TT + t0;
    #pragma unroll
    for (int i = 0; i < 32; i++) {
        int idx = tid + i * 256;
        int c = idx >> 5, t = idx & 31;
        tile[c][t] = zb[(size_t)c * TT + t];
    }
    __syncthreads();

    int j    = tid >> 3;
    int part = tid & 7;
    float s = 0.f;
    #pragma unroll
    for (int i = 0; i < 32; i++) {
        float v = tile[part * 32 + i][j];
        s += v * v;
    }
    s += __shfl_xor_sync(0xFFFFFFFFu, s, 4);
    s += __shfl_xor_sync(0xFFFFFFFFu, s, 2);
    s += __shfl_xor_sync(0xFFFFFFFFu, s, 1);
    float inv = 1.f / fmaxf(sqrtf(s), 1e-12f);

    int n = b * TT + t0 + j;
    if (part == 0) {
        g_inv[n] = inv;
        g_rowsq[n] = s * inv * inv;
        g_rowsq_raw[n] = s;
    }

    uint32_t hw[16], lw[16];
    #pragma unroll
    for (int i = 0; i < 16; i++) {
        float v0 = tile[part * 32 + 2 * i][j] * inv;
        float v1 = tile[part * 32 + 2 * i + 1][j] * inv;
        __nv_bfloat162 h2 = __floats2bfloat162_rn(v0, v1);
        float l0 = v0 - __bfloat162float(h2.x);
        float l1 = v1 - __bfloat162float(h2.y);
        __nv_bfloat162 l2 = __floats2bfloat162_rn(l0, l1);
        hw[i] = *(uint32_t*)&h2;
        lw[i] = *(uint32_t*)&l2;
    }
    uint4* ah = (uint4*)(g_a_hi + (size_t)n * DCB + part * 32);
    uint4* al = (uint4*)(g_a_lo + (size_t)n * DCB + part * 32);
    #pragma unroll
    for (int i = 0; i < 4; i++) {
        ah[i] = make_uint4(hw[4*i], hw[4*i+1], hw[4*i+2], hw[4*i+3]);
        al[i] = make_uint4(lw[4*i], lw[4*i+1], lw[4*i+2], lw[4*i+3]);
    }
}

// ---------------- HMMA GEMM tiles ----------------
static constexpr int ROWB      = 80;
static constexpr int MAT_BYTES = 128 * ROWB;          // 10240
static constexpr int STAGE2    = 2 * MAT_BYTES;       // dist: Ahi, Bhi (single pass)
static constexpr int STAGE4    = 4 * MAT_BYTES;       // 3-pass: Ahi, Alo, Bhi, Blo
static constexpr int COLSQ_OFF = 3 * STAGE2;          // 61440
static constexpr int SMEM_DIST = COLSQ_OFF + 128 * 4; // 61952
static constexpr int SMEM_P4   = 2 * STAGE4;          // 81920

// dist loader: 2 matrices (Ahi, Bhi), K stride 256
__device__ __forceinline__ void load_chunk2(uint32_t sbase, int stage, int kc,
                                            int m0, int n0, int tid)
{
    uint32_t st = sbase + stage * STAGE2;
    #pragma unroll
    for (int i = 0; i < 4; i++) {
        int lin = tid + i * 256;            // 0..1023
        int mat = lin >> 9;                 // 0..1
        int r   = (lin >> 2) & 127;
        int c   = lin & 3;
        uint32_t dst = st + mat * MAT_BYTES + (uint32_t)(r * ROWB + c * 16);
        size_t off = ((size_t)((mat == 0 ? m0 : n0) + r) * DCB + kc * 32) * 2 + c * 16;
        const char* src = (mat == 0) ? ((const char*)g_a_hi + off)
                                     : ((const char*)g_b_hi + off);
        CP_ASYNC16(dst, src);
    }
    CP_COMMIT();
}

__global__ __launch_bounds__(256, 2)
void k_dist(float* __restrict__ dout)
{
    extern __shared__ __align__(16) char smem_raw[];
    uint32_t sbase = smem_u32(smem_raw);
    float* colsq_s = (float*)(smem_raw + COLSQ_OFF);

    int tid  = threadIdx.x;
    int wid  = tid >> 5;
    int lane = tid & 31;
    int wm   = wid >> 1;
    int wn   = wid & 1;
    int n0   = blockIdx.x * 128;
    int m0   = blockIdx.y * 128;

    if (tid < 128) colsq_s[tid] = g_colsq[n0 + tid];

    float acc[2][8][4];
    #pragma unroll
    for (int mt = 0; mt < 2; mt++)
        #pragma unroll
        for (int nt = 0; nt < 8; nt++)
            #pragma unroll
            for (int j = 0; j < 4; j++) acc[mt][nt][j] = 0.f;

    load_chunk2(sbase, 0, 0, m0, n0, tid);
    load_chunk2(sbase, 1, 1, m0, n0, tid);

    int arow  = wm * 32 + (lane & 15);
    int acolh = (lane >> 4) * 16;
    int brow  = wn * 64 + ((lane >> 4) << 3) + (lane & 7);
    int bcolh = ((lane >> 3) & 1) * 16;

    int stage = 0;
    for (int kc = 0; kc < 8; kc++) {
        if (kc < 7) { CP_WAIT1(); } else { CP_WAIT0(); }
        __syncthreads();
        if (kc + 2 < 8) {
            int nstage = stage + 2; if (nstage >= 3) nstage -= 3;
            load_chunk2(sbase, nstage, kc + 2, m0, n0, tid);
        }

        uint32_t sa_hi = sbase + stage * STAGE2;
        uint32_t sb_hi = sa_hi + MAT_BYTES;

        #pragma unroll
        for (int s = 0; s < 2; s++) {
            int acol = s * 32 + acolh;
            uint32_t Ahf[2][4];
            ldsm_x4(Ahf[0], sa_hi + (uint32_t)(arow * ROWB + acol));
            ldsm_x4(Ahf[1], sa_hi + (uint32_t)((arow + 16) * ROWB + acol));
            int bcol = s * 32 + bcolh;
            #pragma unroll
            for (int np = 0; np < 4; np++) {
                uint32_t Bhf[4];
                uint32_t ba = (uint32_t)((brow + np * 16) * ROWB + bcol);
                ldsm_x4(Bhf, sb_hi + ba);
                #pragma unroll
                for (int mt = 0; mt < 2; mt++) {
                    mma_bf16(acc[mt][2 * np],     Ahf[mt], Bhf);
                    mma_bf16(acc[mt][2 * np + 1], Ahf[mt], Bhf + 2);
                }
            }
        }
        stage = (stage + 1 == 3) ? 0 : stage + 1;
    }

    int q  = lane >> 2;
    int qq = lane & 3;
    int tileg = blockIdx.x * 2 + wn;
    #pragma unroll
    for (int mt = 0; mt < 2; mt++) {
        int RB = m0 + wm * 32 + mt * 16;
        #pragma unroll
        for (int h = 0; h < 2; h++) {
            int row = RB + h * 8 + q;
            float rsq = g_rowsq[row];
            float* dw = dout + OFF_DIST + (size_t)row * KK + n0;
            unsigned bkey = 0xFFFFFFFFu, bcode = 0;
            #pragma unroll
            for (int nt = 0; nt < 8; nt++) {
                int c0 = wn * 64 + nt * 8 + qq * 2;
                float d0 = rsq + colsq_s[c0]     - 2.f * acc[mt][nt][h * 2 + 0];
                float d1 = rsq + colsq_s[c0 + 1] - 2.f * acc[mt][nt][h * 2 + 1];
                *(float2*)(dw + c0) = make_float2(d0, d1);
                unsigned k0 = fkey(d0), k1 = fkey(d1);
                if (k0 < bkey) { bkey = k0; bcode = (unsigned)(n0 + c0); }
                if (k1 < bkey) { bkey = k1; bcode = (unsigned)(n0 + c0 + 1); }
            }
            unsigned long long p = ((unsigned long long)bkey << 32) | bcode;
            unsigned long long o;
            o = __shfl_xor_sync(0xFFFFFFFFu, p, 1); if (o < p) p = o;
            o = __shfl_xor_sync(0xFFFFFFFFu, p, 2); if (o < p) p = o;
            if (qq == 0) g_tilemin[(size_t)row * 128 + tileg] = p;
        }
    }
}

// ---------------- generic 4-matrix 3-pass HMMA mainloop ----------------
template<int KDIM>
__device__ __forceinline__ void load_chunk4T(uint32_t sbase, int stage, int kc,
                                             int m0, int n0, int tid,
                                             const void* Ah, const void* Al,
                                             const void* Bh, const void* Bl)
{
    uint32_t st = sbase + stage * STAGE4;
    #pragma unroll
    for (int i = 0; i < 8; i++) {
        int lin = tid + i * 256;
        int mat = lin >> 9;
        int r   = (lin >> 2) & 127;
        int c   = lin & 3;
        uint32_t dst = st + mat * MAT_BYTES + (uint32_t)(r * ROWB + c * 16);
        size_t off = ((size_t)((mat < 2 ? m0 : n0) + r) * KDIM + kc * 32) * 2 + c * 16;
        const char* src;
        if      (mat == 0) src = (const char*)Ah + off;
        else if (mat == 1) src = (const char*)Al + off;
        else if (mat == 2) src = (const char*)Bh + off;
        else               src = (const char*)Bl + off;
        CP_ASYNC16(dst, src);
    }
    CP_COMMIT();
}

template<int KDIM, bool HALF>
__device__ __forceinline__ void hmma4_loop(uint32_t sbase, int m0, int n0, int tid,
                                           const void* Ah, const void* Al,
                                           const void* Bh, const void* Bl,
                                           float acc[2][8][4])
{
    int wid  = tid >> 5;
    int lane = tid & 31;
    int wm   = wid >> 1;
    int wn   = wid & 1;

    load_chunk4T<KDIM>(sbase, 0, 0, m0, n0, tid, Ah, Al, Bh, Bl);

    int arow  = wm * 32 + (lane & 15);
    int acolh = (lane >> 4) * 16;
    int brow  = wn * 64 + ((lane >> 4) << 3) + (lane & 7);
    int bcolh = ((lane >> 3) & 1) * 16;

    constexpr int NCH = KDIM / 32;
    for (int kc = 0; kc < NCH; kc++) {
        int st = kc & 1;
        if (kc < NCH - 1) load_chunk4T<KDIM>(sbase, st ^ 1, kc + 1, m0, n0, tid, Ah, Al, Bh, Bl);
        if (kc < NCH - 1) { CP_WAIT1(); } else { CP_WAIT0(); }
        __syncthreads();

        uint32_t sa_hi = sbase + st * STAGE4;
        uint32_t sa_lo = sa_hi + MAT_BYTES;
        uint32_t sb_hi = sa_hi + 2 * MAT_BYTES;
        uint32_t sb_lo = sa_hi + 3 * MAT_BYTES;

        #pragma unroll
        for (int s = 0; s < 2; s++) {
            int acol = s * 32 + acolh;
            uint32_t Ahf[2][4], Alf[2][4];
            ldsm_x4(Ahf[0], sa_hi + (uint32_t)(arow * ROWB + acol));
            ldsm_x4(Ahf[1], sa_hi + (uint32_t)((arow + 16) * ROWB + acol));
            ldsm_x4(Alf[0], sa_lo + (uint32_t)(arow * ROWB + acol));
            ldsm_x4(Alf[1], sa_lo + (uint32_t)((arow + 16) * ROWB + acol));
            int bcol = s * 32 + bcolh;
            #pragma unroll
            for (int np = 0; np < 4; np++) {
                uint32_t Bhf[4], Blf[4];
                uint32_t ba = (uint32_t)((brow + np * 16) * ROWB + bcol);
                ldsm_x4(Bhf, sb_hi + ba);
                ldsm_x4(Blf, sb_lo + ba);
                #pragma unroll
                for (int mt = 0; mt < 2; mt++) {
                    if (HALF) {
                        mma_f16(acc[mt][2 * np],     Ahf[mt], Bhf);
                        mma_f16(acc[mt][2 * np],     Ahf[mt], Blf);
                        mma_f16(acc[mt][2 * np],     Alf[mt], Bhf);
                        mma_f16(acc[mt][2 * np + 1], Ahf[mt], Bhf + 2);
                        mma_f16(acc[mt][2 * np + 1], Ahf[mt], Blf + 2);
                        mma_f16(acc[mt][2 * np + 1], Alf[mt], Bhf + 2);
                    } else {
                        mma_bf16(acc[mt][2 * np],     Ahf[mt], Bhf);
                        mma_bf16(acc[mt][2 * np],     Ahf[mt], Blf);
                        mma_bf16(acc[mt][2 * np],     Alf[mt], Bhf);
                        mma_bf16(acc[mt][2 * np + 1], Ahf[mt], Bhf + 2);
                        mma_bf16(acc[mt][2 * np + 1], Ahf[mt], Blf + 2);
                        mma_bf16(acc[mt][2 * np + 1], Alf[mt], Bhf + 2);
                    }
                }
            }
        }
        __syncthreads();
    }
}

// proj = cb @ w_out^T   (M=8192, N=1024, K=256, bf16 3-pass)
__global__ __launch_bounds__(256, 2)
void k_proj()
{
    extern __shared__ __align__(16) char smem_raw[];
    uint32_t sbase = smem_u32(smem_raw);

    int tid  = threadIdx.x;
    int wid  = tid >> 5;
    int lane = tid & 31;
    int wm   = wid >> 1;
    int wn   = wid & 1;
    int n0   = blockIdx.x * 128;
    int m0   = blockIdx.y * 128;

    float acc[2][8][4];
    #pragma unroll
    for (int mt = 0; mt < 2; mt++)
        #pragma unroll
        for (int nt = 0; nt < 8; nt++)
            #pragma unroll
            for (int j = 0; j < 4; j++) acc[mt][nt][j] = 0.f;

    hmma4_loop<DCB, false>(sbase, m0, n0, tid, g_cb_hi, g_cb_lo, g_wo_hi, g_wo_lo, acc);

    int q  = lane >> 2;
    int qq = lane & 3;
    #pragma unroll
    for (int mt = 0; mt < 2; mt++) {
        int RB = m0 + wm * 32 + mt * 16;
        #pragma unroll
        for (int h = 0; h < 2; h++) {
            int row = RB + h * 8 + q;
            float* pw = g_proj + (size_t)row * DIN + n0;
            #pragma unroll
            for (int nt = 0; nt < 8; nt++) {
                int c0 = wn * 64 + nt * 8 + qq * 2;
                *(float2*)(pw + c0) = make_float2(acc[mt][nt][h * 2 + 0],
                                                  acc[mt][nt][h * 2 + 1]);
            }
        }
    }
}

// z_e = w_in @ z + in_b  (M=256 ch, N=1024 tok/batch, K=1024, fp16 3-pass)
__global__ __launch_bounds__(256, 2)
void k_zein(const float* __restrict__ bias)
{
    extern __shared__ __align__(16) char smem_raw[];
    uint32_t sbase = smem_u32(smem_raw);

    int tid  = threadIdx.x;
    int wid  = tid >> 5;
    int lane = tid & 31;
    int wm   = wid >> 1;
    int wn   = wid & 1;
    int n0   = blockIdx.x * 128;     // token within batch
    int m0   = blockIdx.y * 128;     // channel
    int b    = blockIdx.z;

    const __half* zh = g_z_hi + (size_t)b * TT * DIN;
    const __half* zl = g_z_lo + (size_t)b * TT * DIN;

    float acc[2][8][4];
    #pragma unroll
    for (int mt = 0; mt < 2; mt++)
        #pragma unroll
        for (int nt = 0; nt < 8; nt++)
            #pragma unroll
            for (int j = 0; j < 4; j++) acc[mt][nt][j] = 0.f;

    hmma4_loop<DIN, true>(sbase, m0, n0, tid, g_wi_hi, g_wi_lo, zh, zl, acc);

    int q  = lane >> 2;
    int qq = lane & 3;
    float* C = g_ze + (size_t)b * DCB * TT;
    #pragma unroll
    for (int mt = 0; mt < 2; mt++) {
        int RB = m0 + wm * 32 + mt * 16;
        #pragma unroll
        for (int h = 0; h < 2; h++) {
            int row = RB + h * 8 + q;
            float bb = bias[row];
            float* cw = C + (size_t)row * TT + n0;
            #pragma unroll
            for (int nt = 0; nt < 8; nt++) {
                int c0 = wn * 64 + nt * 8 + qq * 2;
                *(float2*)(cw + c0) = make_float2(acc[mt][nt][h * 2 + 0] + bb,
                                                  acc[mt][nt][h * 2 + 1] + bb);
            }
        }
    }
}

// ---------------- argmin refinement (near-exact fp32) + fused loss ----------
__global__ void k_refine(float* __restrict__ dout)
{
    int warp = threadIdx.x >> 5;
    int lane = threadIdx.x & 31;
    int n = blockIdx.x * 8 + warp;

    const unsigned long long* tm = g_tilemin + (size_t)n * 128;
    unsigned long long best = tm[lane];
    {
        unsigned long long v;
        v = tm[lane + 32]; if (v < best) best = v;
        v = tm[lane + 64]; if (v < best) best = v;
        v = tm[lane + 96]; if (v < best) best = v;
        #pragma unroll
        for (int off = 16; off; off >>= 1) {
            unsigned long long o = __shfl_xor_sync(0xFFFFFFFFu, best, off);
            if (o < best) best = o;
        }
    }
    float dmin = funkey((unsigned)(best >> 32));
    float thresh = dmin + 8e-3f;        // widened: single-pass bf16 dist error

    float inv = g_inv[n];
    float rsq = g_rowsq[n];
    float ev[8];
    {
        const __nv_bfloat16* ah = g_a_hi + (size_t)n * DCB + lane * 8;
        const __nv_bfloat16* al = g_a_lo + (size_t)n * DCB + lane * 8;
        #pragma unroll
        for (int j = 0; j < 8; j++)
            ev[j] = __bfloat162float(ah[j]) + __bfloat162float(al[j]);
    }

    const float* distrow = dout + OFF_DIST + (size_t)n * KK;

    float bestd = 3.4e38f;
    int   bestk = KK;
    float bestpart = 0.f;

    for (int ti = 0; ti < 128; ti++) {
        float tmin = funkey((unsigned)(tm[ti] >> 32));
        if (tmin > thresh) continue;
        int k0 = ti * 64;
        float d0 = distrow[k0 + lane];
        float d1 = distrow[k0 + 32 + lane];
        #pragma unroll
        for (int half = 0; half < 2; half++) {
            float dv = (half == 0) ? d0 : d1;
            unsigned mask = __ballot_sync(0xFFFFFFFFu, dv <= thresh);
            while (mask) {
                int j = __ffs(mask) - 1;
                mask &= mask - 1;
                int k = k0 + half * 32 + j;
                const float* cr = g_cbn + (size_t)k * DCB + lane * 8;
                float part = 0.f;
                #pragma unroll
                for (int qv = 0; qv < 8; qv++)
                    part += ev[qv] * cr[qv];
                #pragma unroll
                for (int off = 16; off; off >>= 1)
                    part += __shfl_xor_sync(0xFFFFFFFFu, part, off);
                float de = rsq + g_colsq[k] - 2.f * part;
                if (de < bestd || (de == bestd && k < bestk)) {
                    bestd = de; bestk = k; bestpart = part;
                }
            }
        }
    }

    if (lane == 0) {
        g_idx[n] = bestk;
        dout[OFF_IDX + n] = (float)bestk;
        atomicAdd(&g_counts[bestk], 1);
        float dot_raw = bestpart / (inv * g_cbinv[bestk]);
        g_lossn[n] = g_rowsq_raw[n] + g_cbsq[bestk] - 2.f * dot_raw;
    }
}

// ---------------- z_q_out gather ----------------
__global__ void k_gather(const float* __restrict__ outb, float* __restrict__ dout)
{
    int t  = blockIdx.x * 256 + threadIdx.x;
    int o4 = blockIdx.y * 4;
    int b  = blockIdx.z;
    int idx = g_idx[b * TT + t];
    float4 v = *(const float4*)(g_proj + (size_t)idx * DIN + o4);
    size_t base = OFF_ZQ + (size_t)b * DIN * TT + (size_t)o4 * TT + t;
    dout[base]          = v.x + outb[o4];
    dout[base + TT]     = v.y + outb[o4 + 1];
    dout[base + 2 * TT] = v.z + outb[o4 + 2];
    dout[base + 3 * TT] = v.w + outb[o4 + 3];
}

// ---------------- scalars: losses, perplexity, active ----------------
__global__ void k_final(const float* __restrict__ cs, float* __restrict__ dout)
{
    int tid = threadIdx.x;
    __shared__ float lsum[256];
    {
        int bb = tid >> 4;
        int sl = tid & 15;
        float s = 0.f;
        #pragma unroll 4
        for (int i = 0; i < 64; i++)
            s += g_lossn[bb * TT + sl + i * 16];
        lsum[tid] = s;
    }
    __syncthreads();
    if (tid < BB) {
        float s = 0.f;
        #pragma unroll
        for (int i = 0; i < 16; i++) s += lsum[tid * 16 + i];
        float mean = s / (float)(DCB * TT);
        dout[OFF_COMMIT + tid] = mean * 0.15f;
        dout[OFF_CBL + tid]    = mean;
    }

    float ent = 0.f;
    int   act = 0;
    for (int k = tid; k < KK; k += 256) {
        float cnt = (float)g_counts[k];
        float p   = cnt / (float)NTOK;
        ent += p * logf(p + 1e-10f);
        float ncs = cs[k] * 0.99f + cnt * 0.01f;
        if (ncs > 2.0f) act++;
    }
    __shared__ float se[256];
    __shared__ int   sa[256];
    se[tid] = ent; sa[tid] = act; __syncthreads();
    #pragma unroll
    for (int off = 128; off; off >>= 1) {
        if (tid < off) { se[tid] += se[tid + off]; sa[tid] += sa[tid + off]; }
        __syncthreads();
    }
    if (tid == 0) {
        dout[OFF_PERP] = expf(-se[0]);
        dout[OFF_ACT]  = (float)sa[0];
    }
}

// ---------------- launch (fork-join) ----------------
extern "C" void kernel_launch(void* const* d_in, const int* in_sizes, int n_in,
                              void* d_out, int out_size)
{
    const float* z     = (const float*)d_in[0];
    const float* in_g  = (const float*)d_in[1];
    const float* in_v  = (const float*)d_in[2];
    const float* in_b  = (const float*)d_in[3];
    const float* out_g = (const float*)d_in[4];
    const float* out_v = (const float*)d_in[5];
    const float* out_b = (const float*)d_in[6];
    const float* cb    = (const float*)d_in[7];
    const float* cs    = (const float*)d_in[8];
    float* dout = (float*)d_out;

    static cudaStream_t s2 = nullptr;
    static cudaEvent_t  evF = nullptr, evJ = nullptr;
    if (!s2) {
        cudaStreamCreateWithFlags(&s2, cudaStreamNonBlocking);
        cudaEventCreateWithFlags(&evF, cudaEventDisableTiming);
        cudaEventCreateWithFlags(&evJ, cudaEventDisableTiming);
        cudaFuncSetAttribute(k_dist, cudaFuncAttributeMaxDynamicSharedMemorySize, SMEM_DIST);
        cudaFuncSetAttribute(k_proj, cudaFuncAttributeMaxDynamicSharedMemorySize, SMEM_P4);
        cudaFuncSetAttribute(k_zein, cudaFuncAttributeMaxDynamicSharedMemorySize, SMEM_P4);
    }

    // fork: stream2 does codebook/w_out prep + proj GEMM
    cudaEventRecord(evF, 0);
    cudaStreamWaitEvent(s2, evF, 0);
    k_prep_cbwo<<<1024 + KK, 256, 0, s2>>>(out_v, out_g, cb);
    {
        dim3 grid(DIN / 128, KK / 128, 1);
        k_proj<<<grid, 256, SMEM_P4, s2>>>();
    }
    cudaEventRecord(evJ, s2);

    // main chain
    k_prep_win<<<256, 256>>>(in_v, in_g);
    {
        dim3 grid(4, 32, BB);
        k_zsplit<<<grid, 256>>>(z);
    }
    {
        dim3 grid(TT / 128, DCB / 128, BB);
        k_zein<<<grid, 256, SMEM_P4>>>(in_b);
    }
    k_toknorm<<<NTOK / 32, 256>>>();

    // join
    cudaStreamWaitEvent(0, evJ, 0);

    {
        dim3 grid(KK / 128, NTOK / 128, 1);
        k_dist<<<grid, 256, SMEM_DIST>>>(dout);
    }
    k_refine<<<NTOK / 8, 256>>>(dout);
    {
        dim3 grid(4, 256, BB);
        k_gather<<<grid, 256>>>(out_b, dout);
    }
    k_final<<<1, 256>>>(cs, dout);
}